// round 1
// baseline (speedup 1.0000x reference)
#include <cuda_runtime.h>
#include <math.h>

// Problem constants
constexpr int Bc  = 8;
constexpr int Sc  = 512;
constexpr int Ec  = 1024;
constexpr int Hc  = 16;
constexpr int HDc = 64;
constexpr int FFc = 4096;
constexpr int NEc = 129;           // 2P+1
constexpr int Mc  = Bc * Sc;       // 4096 rows

// Scratch (device globals; no allocation allowed)
__device__ float g_Q[Mc * Ec];
__device__ float g_K[Mc * Ec];
__device__ float g_V[Mc * Ec];
__device__ float g_qp[Bc * Hc * Sc * NEc];
__device__ float g_awp[Bc * Hc * Sc * NEc];
__device__ float g_aw[Bc * Hc * Sc * Sc];     // 134 MB: scores -> attention weights
__device__ float g_attn[Mc * Ec];             // concat layout [b,i,h*64+d]
__device__ float g_t0[Mc * Ec];               // attn_out / ffn_out
__device__ float g_h[Mc * Ec];                // after ln1
__device__ float g_ff[Mc * FFc];              // 67 MB

// ---------------------------------------------------------------------------
// Generic tiled GEMM: C[M,N] = A[M,K] @ W[K,N] + bias, optional ReLU.
// 64x64 block tile, K-tile 16, 256 threads, 4x4 per-thread microtile.
// M,N multiples of 64; K multiple of 16.
// ---------------------------------------------------------------------------
template<int RELU>
__global__ void __launch_bounds__(256) gemm_bias(
    const float* __restrict__ A, const float* __restrict__ W,
    const float* __restrict__ bias, float* __restrict__ C,
    int Mg, int Kg, int Ng)
{
    __shared__ float As[16][64];
    __shared__ float Bs[16][64];
    const int tid = threadIdx.x;
    const int tx = tid & 15, ty = tid >> 4;
    const int bm = blockIdx.y * 64, bn = blockIdx.x * 64;

    const int am = tid >> 2, ak = (tid & 3) << 2;   // A tile: 64 rows x 16 k
    const int bk = tid >> 4, bn4 = (tid & 15) << 2; // B tile: 16 k x 64 n

    float acc[4][4] = {};

    for (int k0 = 0; k0 < Kg; k0 += 16) {
        float4 av = *reinterpret_cast<const float4*>(A + (size_t)(bm + am) * Kg + k0 + ak);
        As[ak + 0][am] = av.x; As[ak + 1][am] = av.y;
        As[ak + 2][am] = av.z; As[ak + 3][am] = av.w;
        float4 bv = *reinterpret_cast<const float4*>(W + (size_t)(k0 + bk) * Ng + bn + bn4);
        *reinterpret_cast<float4*>(&Bs[bk][bn4]) = bv;
        __syncthreads();
        #pragma unroll
        for (int kk = 0; kk < 16; kk++) {
            float4 a = *reinterpret_cast<const float4*>(&As[kk][ty << 2]);
            float4 b = *reinterpret_cast<const float4*>(&Bs[kk][tx << 2]);
            float ar[4] = {a.x, a.y, a.z, a.w};
            float br[4] = {b.x, b.y, b.z, b.w};
            #pragma unroll
            for (int r = 0; r < 4; r++)
                #pragma unroll
                for (int c = 0; c < 4; c++)
                    acc[r][c] += ar[r] * br[c];
        }
        __syncthreads();
    }

    #pragma unroll
    for (int r = 0; r < 4; r++) {
        int row = bm + (ty << 2) + r;
        float4 o;
        o.x = acc[r][0] + bias[bn + (tx << 2) + 0];
        o.y = acc[r][1] + bias[bn + (tx << 2) + 1];
        o.z = acc[r][2] + bias[bn + (tx << 2) + 2];
        o.w = acc[r][3] + bias[bn + (tx << 2) + 3];
        if (RELU) {
            o.x = fmaxf(o.x, 0.f); o.y = fmaxf(o.y, 0.f);
            o.z = fmaxf(o.z, 0.f); o.w = fmaxf(o.w, 0.f);
        }
        *reinterpret_cast<float4*>(C + (size_t)row * Ng + bn + (tx << 2)) = o;
    }
}

// ---------------------------------------------------------------------------
// qp[b,h,i,e] = sum_d Q[b,i,h*64+d] * pos_emb[e,d]
// one block per (b,i); q row + pos_emb staged in shared.
// ---------------------------------------------------------------------------
__global__ void __launch_bounds__(256) qp_kernel(const float* __restrict__ pos_emb)
{
    __shared__ float qsh[Ec];
    __shared__ float pe[NEc * 65];   // pad stride 65 to kill bank conflicts
    const int b = blockIdx.x >> 9, i = blockIdx.x & 511;
    const int tid = threadIdx.x;
    const float* qrow = g_Q + (size_t)(b * Sc + i) * Ec;
    for (int t = tid; t < Ec; t += 256) qsh[t] = qrow[t];
    for (int t = tid; t < NEc * HDc; t += 256) pe[(t >> 6) * 65 + (t & 63)] = pos_emb[t];
    __syncthreads();
    for (int o = tid; o < Hc * NEc; o += 256) {
        int h = o / NEc, e = o - h * NEc;
        const float* qh = qsh + h * HDc;
        const float* per = pe + e * 65;
        float s = 0.f;
        #pragma unroll
        for (int d = 0; d < HDc; d++) s += qh[d] * per[d];
        g_qp[((b * Hc + h) * Sc + i) * NEc + e] = s;
    }
}

// ---------------------------------------------------------------------------
// Raw QK^T scores per (b,h): g_aw[bh,i,j] = Q_h[i,:] . K_h[j,:]
// ---------------------------------------------------------------------------
__global__ void __launch_bounds__(256) qk_kernel()
{
    __shared__ float Qs[64 * 65];
    __shared__ float Ks[64 * 65];
    const int bh = blockIdx.z;
    const int b = bh >> 4, h = bh & 15;
    const int bi = blockIdx.y * 64, bj = blockIdx.x * 64;
    const int tid = threadIdx.x, tx = tid & 15, ty = tid >> 4;

    const float* Qb = g_Q + (size_t)b * Sc * Ec + h * HDc;
    const float* Kb = g_K + (size_t)b * Sc * Ec + h * HDc;

    #pragma unroll
    for (int t = 0; t < 16; t++) {
        int idx = tid + 256 * t;
        int m = idx >> 6, d = idx & 63;
        Qs[d * 65 + m] = Qb[(size_t)(bi + m) * Ec + d];
        Ks[d * 65 + m] = Kb[(size_t)(bj + m) * Ec + d];
    }
    __syncthreads();

    float acc[4][4] = {};
    #pragma unroll 4
    for (int d = 0; d < 64; d++) {
        float ar[4], br[4];
        #pragma unroll
        for (int r = 0; r < 4; r++) ar[r] = Qs[d * 65 + (ty << 2) + r];
        #pragma unroll
        for (int c = 0; c < 4; c++) br[c] = Ks[d * 65 + (tx << 2) + c];
        #pragma unroll
        for (int r = 0; r < 4; r++)
            #pragma unroll
            for (int c = 0; c < 4; c++)
                acc[r][c] += ar[r] * br[c];
    }

    #pragma unroll
    for (int r = 0; r < 4; r++) {
        int row = bh * Sc + bi + (ty << 2) + r;
        #pragma unroll
        for (int c = 0; c < 4; c++)
            g_aw[row * Sc + bj + (tx << 2) + c] = acc[r][c];
    }
}

// ---------------------------------------------------------------------------
// Fused: score = (qk + qp[gather by rel idx]) * scale + 0.6*dist; softmax;
// write aw back; bucket-accumulate aw into awp[129] by idx.
// One block per (b,h,i).
// ---------------------------------------------------------------------------
__global__ void __launch_bounds__(256) softmax_kernel(
    const float* __restrict__ dist, const int* __restrict__ dt)
{
    __shared__ float ssc[Sc];
    __shared__ int dts[Sc];
    __shared__ unsigned char es[Sc];
    __shared__ float bucket[NEc];
    __shared__ float red[8];

    const int i = blockIdx.x, h = blockIdx.y, b = blockIdx.z;
    const int tid = threadIdx.x;
    const int bh = b * Hc + h;
    const int rowbase = (bh * Sc + i) * Sc;
    const float* qprow = g_qp + (bh * Sc + i) * NEc;
    const float* drow = dist + ((size_t)b * Sc + i) * Sc;

    for (int t = tid; t < Sc; t += 256) dts[t] = dt[b * Sc + t];
    for (int t = tid; t < NEc; t += 256) bucket[t] = 0.f;
    __syncthreads();

    const int dti = dts[i];
    float lmax = -1e30f;
    for (int t = tid; t < Sc; t += 256) {
        int rel = dts[t] - dti;
        rel = rel < -64 ? -64 : (rel > 64 ? 64 : rel);
        int e = rel + 64;
        es[t] = (unsigned char)e;
        float s = (g_aw[rowbase + t] + qprow[e]) * 0.125f + 0.6f * drow[t];
        ssc[t] = s;
        lmax = fmaxf(lmax, s);
    }
    #pragma unroll
    for (int o = 16; o; o >>= 1) lmax = fmaxf(lmax, __shfl_xor_sync(0xffffffffu, lmax, o));
    if ((tid & 31) == 0) red[tid >> 5] = lmax;
    __syncthreads();
    float mx = red[0];
    #pragma unroll
    for (int w = 1; w < 8; w++) mx = fmaxf(mx, red[w]);
    __syncthreads();

    float lsum = 0.f;
    for (int t = tid; t < Sc; t += 256) {
        float p = __expf(ssc[t] - mx);
        ssc[t] = p;
        lsum += p;
    }
    #pragma unroll
    for (int o = 16; o; o >>= 1) lsum += __shfl_xor_sync(0xffffffffu, lsum, o);
    if ((tid & 31) == 0) red[tid >> 5] = lsum;
    __syncthreads();
    float tot = 0.f;
    #pragma unroll
    for (int w = 0; w < 8; w++) tot += red[w];
    const float inv = 1.f / tot;

    for (int t = tid; t < Sc; t += 256) {
        float a = ssc[t] * inv;
        g_aw[rowbase + t] = a;
        atomicAdd(&bucket[es[t]], a);
    }
    __syncthreads();
    for (int t = tid; t < NEc; t += 256)
        g_awp[(bh * Sc + i) * NEc + t] = bucket[t];
}

// ---------------------------------------------------------------------------
// attn[b,i,h*64+d] = sum_j aw[bh,i,j]*V[b,j,h*64+d] + sum_e awp[bh,i,e]*pe[e,d]
// Implemented as one GEMM with extended K = 512 + 144 (129 real + pad).
// ---------------------------------------------------------------------------
__global__ void __launch_bounds__(256) attn_kernel(const float* __restrict__ pos_emb)
{
    __shared__ float As[16][64];
    __shared__ float Bs[16][64];
    const int bh = blockIdx.z;
    const int b = bh >> 4, h = bh & 15;
    const int bi = blockIdx.y * 64;
    const int tid = threadIdx.x, tx = tid & 15, ty = tid >> 4;

    const int am = tid >> 2, ak = (tid & 3) << 2;
    const int bk = tid >> 4, bn = (tid & 15) << 2;

    float acc[4][4] = {};
    const int KT = 512 + 144;

    for (int k0 = 0; k0 < KT; k0 += 16) {
        // A tile (aw rows, then awp tail)
        if (k0 < 512) {
            float4 av = *reinterpret_cast<const float4*>(
                g_aw + (size_t)(bh * Sc + bi + am) * Sc + k0 + ak);
            As[ak + 0][am] = av.x; As[ak + 1][am] = av.y;
            As[ak + 2][am] = av.z; As[ak + 3][am] = av.w;
        } else {
            #pragma unroll
            for (int j = 0; j < 4; j++) {
                int e = k0 + ak + j - 512;
                As[ak + j][am] = (e < NEc) ? g_awp[(bh * Sc + bi + am) * NEc + e] : 0.f;
            }
        }
        // B tile (V rows, then pos_emb tail)
        {
            int kg = k0 + bk;
            if (kg < 512) {
                float4 bv = *reinterpret_cast<const float4*>(
                    g_V + (size_t)(b * Sc + kg) * Ec + h * HDc + bn);
                *reinterpret_cast<float4*>(&Bs[bk][bn]) = bv;
            } else {
                int e = kg - 512;
                if (e < NEc) {
                    float4 bv = *reinterpret_cast<const float4*>(pos_emb + e * HDc + bn);
                    *reinterpret_cast<float4*>(&Bs[bk][bn]) = bv;
                } else {
                    Bs[bk][bn + 0] = 0.f; Bs[bk][bn + 1] = 0.f;
                    Bs[bk][bn + 2] = 0.f; Bs[bk][bn + 3] = 0.f;
                }
            }
        }
        __syncthreads();
        #pragma unroll
        for (int kk = 0; kk < 16; kk++) {
            float4 a = *reinterpret_cast<const float4*>(&As[kk][ty << 2]);
            float4 b4 = *reinterpret_cast<const float4*>(&Bs[kk][tx << 2]);
            float ar[4] = {a.x, a.y, a.z, a.w};
            float br[4] = {b4.x, b4.y, b4.z, b4.w};
            #pragma unroll
            for (int r = 0; r < 4; r++)
                #pragma unroll
                for (int c = 0; c < 4; c++)
                    acc[r][c] += ar[r] * br[c];
        }
        __syncthreads();
    }

    #pragma unroll
    for (int r = 0; r < 4; r++) {
        float4 o = make_float4(acc[r][0], acc[r][1], acc[r][2], acc[r][3]);
        *reinterpret_cast<float4*>(
            g_attn + (size_t)(b * Sc + bi + (ty << 2) + r) * Ec + h * HDc + (tx << 2)) = o;
    }
}

// ---------------------------------------------------------------------------
// out = LayerNorm(X + R) * gamma + beta   (row length 1024)
// ---------------------------------------------------------------------------
__global__ void __launch_bounds__(256) add_ln_kernel(
    const float* __restrict__ X, const float* __restrict__ Rr,
    const float* __restrict__ gam, const float* __restrict__ bet,
    float* __restrict__ Out)
{
    __shared__ float sh[Ec];
    __shared__ float red[8];
    const int row = blockIdx.x;
    const int tid = threadIdx.x;
    const float* xr = X + (size_t)row * Ec;
    const float* rr = Rr + (size_t)row * Ec;

    float lsum = 0.f;
    for (int t = tid; t < Ec; t += 256) {
        float v = xr[t] + rr[t];
        sh[t] = v;
        lsum += v;
    }
    #pragma unroll
    for (int o = 16; o; o >>= 1) lsum += __shfl_xor_sync(0xffffffffu, lsum, o);
    if ((tid & 31) == 0) red[tid >> 5] = lsum;
    __syncthreads();
    float tot = 0.f;
    #pragma unroll
    for (int w = 0; w < 8; w++) tot += red[w];
    const float mu = tot * (1.f / Ec);
    __syncthreads();

    float lvar = 0.f;
    for (int t = tid; t < Ec; t += 256) {
        float d = sh[t] - mu;
        lvar += d * d;
    }
    #pragma unroll
    for (int o = 16; o; o >>= 1) lvar += __shfl_xor_sync(0xffffffffu, lvar, o);
    if ((tid & 31) == 0) red[tid >> 5] = lvar;
    __syncthreads();
    float vtot = 0.f;
    #pragma unroll
    for (int w = 0; w < 8; w++) vtot += red[w];
    const float inv = rsqrtf(vtot * (1.f / Ec) + 1e-5f);

    float* orow = Out + (size_t)row * Ec;
    for (int t = tid; t < Ec; t += 256)
        orow[t] = (sh[t] - mu) * inv * gam[t] + bet[t];
}

// ---------------------------------------------------------------------------
extern "C" void kernel_launch(void* const* d_in, const int* in_sizes, int n_in,
                              void* d_out, int out_size)
{
    (void)in_sizes; (void)n_in; (void)out_size;
    const float* x       = (const float*)d_in[0];
    const float* dist    = (const float*)d_in[1];
    const int*   dt      = (const int*)d_in[2];
    const float* pos_emb = (const float*)d_in[3];
    const float* wq_w = (const float*)d_in[4];
    const float* wq_b = (const float*)d_in[5];
    const float* wk_w = (const float*)d_in[6];
    const float* wk_b = (const float*)d_in[7];
    const float* wv_w = (const float*)d_in[8];
    const float* wv_b = (const float*)d_in[9];
    const float* wo_w = (const float*)d_in[10];
    const float* wo_b = (const float*)d_in[11];
    const float* ff1_w = (const float*)d_in[12];
    const float* ff1_b = (const float*)d_in[13];
    const float* ff2_w = (const float*)d_in[14];
    const float* ff2_b = (const float*)d_in[15];
    const float* ln1_g = (const float*)d_in[16];
    const float* ln1_b = (const float*)d_in[17];
    const float* ln2_g = (const float*)d_in[18];
    const float* ln2_b = (const float*)d_in[19];
    float* out = (float*)d_out;

    float *Q, *K, *V, *ATT, *T0, *Hs, *FFb;
    cudaGetSymbolAddress((void**)&Q, g_Q);
    cudaGetSymbolAddress((void**)&K, g_K);
    cudaGetSymbolAddress((void**)&V, g_V);
    cudaGetSymbolAddress((void**)&ATT, g_attn);
    cudaGetSymbolAddress((void**)&T0, g_t0);
    cudaGetSymbolAddress((void**)&Hs, g_h);
    cudaGetSymbolAddress((void**)&FFb, g_ff);

    dim3 blk(256);

    // QKV projections
    gemm_bias<0><<<dim3(Ec / 64, Mc / 64), blk>>>(x, wq_w, wq_b, Q, Mc, Ec, Ec);
    gemm_bias<0><<<dim3(Ec / 64, Mc / 64), blk>>>(x, wk_w, wk_b, K, Mc, Ec, Ec);
    gemm_bias<0><<<dim3(Ec / 64, Mc / 64), blk>>>(x, wv_w, wv_b, V, Mc, Ec, Ec);

    // relative-position projection of q
    qp_kernel<<<Mc, blk>>>(pos_emb);

    // raw QK^T
    qk_kernel<<<dim3(Sc / 64, Sc / 64, Bc * Hc), blk>>>();

    // fused score assembly + softmax + bucket scatter
    softmax_kernel<<<dim3(Sc, Hc, Bc), blk>>>(dist, dt);

    // attn = aw @ V  (+ awp @ pos_emb tail), written in concat layout
    attn_kernel<<<dim3(1, Sc / 64, Bc * Hc), blk>>>(pos_emb);

    // output projection
    gemm_bias<0><<<dim3(Ec / 64, Mc / 64), blk>>>(ATT, wo_w, wo_b, T0, Mc, Ec, Ec);

    // h = LN(x + attn_out)
    add_ln_kernel<<<Mc, blk>>>(x, T0, ln1_g, ln1_b, Hs);

    // FFN
    gemm_bias<1><<<dim3(FFc / 64, Mc / 64), blk>>>(Hs, ff1_w, ff1_b, FFb, Mc, Ec, FFc);
    gemm_bias<0><<<dim3(Ec / 64, Mc / 64), blk>>>(FFb, ff2_w, ff2_b, T0, Mc, FFc, Ec);

    // out = LN(h + ffn)
    add_ln_kernel<<<Mc, blk>>>(Hs, T0, ln2_g, ln2_b, out);
}

// round 3
// speedup vs baseline: 1.6971x; 1.6971x over previous
#include <cuda_runtime.h>
#include <cuda_bf16.h>
#include <cstdint>
#include <math.h>

// Problem constants
constexpr int Bc  = 8;
constexpr int Sc  = 512;
constexpr int Ec  = 1024;
constexpr int Hc  = 16;
constexpr int HDc = 64;
constexpr int FFc = 4096;
constexpr int NEc = 129;           // 2P+1
constexpr int Mc  = Bc * Sc;       // 4096 rows
constexpr int E3  = 3 * Ec;        // 3072

// ---------------------------------------------------------------------------
// Scratch (device globals; no allocation allowed)
// ---------------------------------------------------------------------------
__device__ __align__(256) __nv_bfloat16 g_xh[Mc * Ec];
__device__ __align__(256) __nv_bfloat16 g_xl[Mc * Ec];
__device__ __align__(256) __nv_bfloat16 g_W3h[E3 * Ec];   // [3072,1024] qkv^T
__device__ __align__(256) __nv_bfloat16 g_W3l[E3 * Ec];
__device__ __align__(256) __nv_bfloat16 g_Woh[Ec * Ec];
__device__ __align__(256) __nv_bfloat16 g_Wol[Ec * Ec];
__device__ __align__(256) __nv_bfloat16 g_W1h[FFc * Ec];  // [4096,1024] ff1^T
__device__ __align__(256) __nv_bfloat16 g_W1l[FFc * Ec];
__device__ __align__(256) __nv_bfloat16 g_W2h[Ec * FFc];  // [1024,4096] ff2^T
__device__ __align__(256) __nv_bfloat16 g_W2l[Ec * FFc];
__device__ float g_b3[E3];
__device__ float g_QKV[Mc * E3];                          // fp32 q|k|v
__device__ float g_qp[Bc * Hc * Sc * NEc];
__device__ float g_awp[Bc * Hc * Sc * NEc];
__device__ float g_aw[Bc * Hc * Sc * Sc];                 // 134 MB
__device__ __align__(256) __nv_bfloat16 g_ah[Mc * Ec];    // attn concat hi/lo
__device__ __align__(256) __nv_bfloat16 g_al[Mc * Ec];
__device__ float g_t0[Mc * Ec];
__device__ float g_h[Mc * Ec];
__device__ __align__(256) __nv_bfloat16 g_hh[Mc * Ec];
__device__ __align__(256) __nv_bfloat16 g_hl[Mc * Ec];
__device__ __align__(256) __nv_bfloat16 g_fh[Mc * FFc];
__device__ __align__(256) __nv_bfloat16 g_fl[Mc * FFc];

// ---------------------------------------------------------------------------
// PTX helpers (sm_80-era only: HMMA / ldmatrix / cp.async — no tcgen05)
// ---------------------------------------------------------------------------
__device__ __forceinline__ uint32_t smem_u32(const void* p) {
    uint32_t a;
    asm("{ .reg .u64 t; cvta.to.shared.u64 t, %1; cvt.u32.u64 %0, t; }" : "=r"(a) : "l"(p));
    return a;
}
__device__ __forceinline__ void cpasync16(uint32_t dst, const void* src) {
    asm volatile("cp.async.cg.shared.global [%0], [%1], 16;" :: "r"(dst), "l"(src));
}
#define CP_COMMIT()  asm volatile("cp.async.commit_group;" ::: "memory")
#define CP_WAIT(n)   asm volatile("cp.async.wait_group %0;" :: "n"(n) : "memory")

__device__ __forceinline__ void ldsm4(uint32_t* r, uint32_t addr) {
    asm volatile("ldmatrix.sync.aligned.m8n8.x4.shared.b16 {%0,%1,%2,%3}, [%4];"
                 : "=r"(r[0]), "=r"(r[1]), "=r"(r[2]), "=r"(r[3]) : "r"(addr));
}
__device__ __forceinline__ void mma_bf16(float* c, const uint32_t* a, const uint32_t* b) {
    asm volatile(
        "mma.sync.aligned.m16n8k16.row.col.f32.bf16.bf16.f32 "
        "{%0,%1,%2,%3}, {%4,%5,%6,%7}, {%8,%9}, {%0,%1,%2,%3};"
        : "+f"(c[0]), "+f"(c[1]), "+f"(c[2]), "+f"(c[3])
        : "r"(a[0]), "r"(a[1]), "r"(a[2]), "r"(a[3]), "r"(b[0]), "r"(b[1]));
}

// ---------------------------------------------------------------------------
// HMMA GEMM: C[M,N] = (Ah+Al)[M,K] @ (Bh+Bl)[N,K]^T + bias
// 3-pass split-bf16 (hi*hi + lo*hi + hi*lo), fp32 accumulate.
// 128x128 CTA tile, BK=32, 8 warps of 32x64, cp.async double buffer.
// ---------------------------------------------------------------------------
constexpr int BKc   = 32;
constexpr int LDSp  = 40;                  // padded row (elements)
constexpr int TILEB = 128 * LDSp * 2;      // 10240 B per 128x32 tile
constexpr int BUFB  = 4 * TILEB;           // Ah,Al,Bh,Bl = 40960 B
constexpr int MMA_SMEM = 2 * BUFB;         // 81920 B

template<int RELU, int SPLIT>
__global__ void __launch_bounds__(256)
mma_gemm(const __nv_bfloat16* __restrict__ Ah, const __nv_bfloat16* __restrict__ Al,
         const __nv_bfloat16* __restrict__ Bh, const __nv_bfloat16* __restrict__ Bl,
         const float* __restrict__ bias, float* __restrict__ C,
         __nv_bfloat16* __restrict__ Ch, __nv_bfloat16* __restrict__ Cl,
         int K, int N)
{
    extern __shared__ char sm[];
    const uint32_t sbase = smem_u32(sm);
    const int tid = threadIdx.x;
    const int wid = tid >> 5, lane = tid & 31;
    const int wm = wid & 3, wn = wid >> 2;       // warp tile: rows wm*32, cols wn*64
    const int bm = blockIdx.y * 128, bn = blockIdx.x * 128;

    // per-thread load coords (2 iterations of 512 (row,seg) pairs)
    const int r0l = tid >> 2, sg = (tid & 3) << 3;   // row, seg-elem

    auto load_chunk = [&](int kc) {
        const int buf = kc & 1;
        const uint32_t base = sbase + buf * BUFB;
        const int k0 = kc * BKc;
        #pragma unroll
        for (int it = 0; it < 2; it++) {
            const int r = r0l + it * 64;
            const uint32_t dst = base + r * 80 + sg * 2;
            const size_t ao = (size_t)(bm + r) * K + k0 + sg;
            const size_t bo = (size_t)(bn + r) * K + k0 + sg;
            cpasync16(dst,             Ah + ao);
            cpasync16(dst + TILEB,     Al + ao);
            cpasync16(dst + 2 * TILEB, Bh + bo);
            cpasync16(dst + 3 * TILEB, Bl + bo);
        }
        CP_COMMIT();
    };

    float acc[2][8][4];
    #pragma unroll
    for (int mt = 0; mt < 2; mt++)
        #pragma unroll
        for (int nt = 0; nt < 8; nt++)
            #pragma unroll
            for (int i = 0; i < 4; i++) acc[mt][nt][i] = 0.f;

    uint32_t aF[2][2][4];   // [mt][kstep][4]
    uint32_t bF[8][2][2];   // [nt][kstep][2]

    // ldmatrix address components (fixed per thread)
    const int a_row = wm * 32 + (lane & 15);
    const int a_kof = (lane >> 4) << 3;
    const int b_n   = wn * 64 + (lane & 7) + ((lane & 16) >> 1);
    const int b_kof = ((lane >> 3) & 1) << 3;

    auto loadA = [&](uint32_t tbase) {
        #pragma unroll
        for (int mt = 0; mt < 2; mt++)
            #pragma unroll
            for (int ks = 0; ks < 2; ks++)
                ldsm4(aF[mt][ks], tbase + (a_row + mt * 16) * 80 + (ks * 16 + a_kof) * 2);
    };
    auto loadB = [&](uint32_t tbase) {
        #pragma unroll
        for (int ntp = 0; ntp < 4; ntp++)
            #pragma unroll
            for (int ks = 0; ks < 2; ks++) {
                uint32_t t4[4];
                ldsm4(t4, tbase + (b_n + ntp * 16) * 80 + (ks * 16 + b_kof) * 2);
                bF[ntp * 2 + 0][ks][0] = t4[0]; bF[ntp * 2 + 0][ks][1] = t4[1];
                bF[ntp * 2 + 1][ks][0] = t4[2]; bF[ntp * 2 + 1][ks][1] = t4[3];
            }
    };
    auto mma_all = [&]() {
        #pragma unroll
        for (int ks = 0; ks < 2; ks++)
            #pragma unroll
            for (int mt = 0; mt < 2; mt++)
                #pragma unroll
                for (int nt = 0; nt < 8; nt++)
                    mma_bf16(acc[mt][nt], aF[mt][ks], bF[nt][ks]);
    };

    const int nk = K / BKc;
    load_chunk(0);
    for (int kc = 0; kc < nk; kc++) {
        if (kc + 1 < nk) { load_chunk(kc + 1); CP_WAIT(1); }
        else             { CP_WAIT(0); }
        __syncthreads();

        const uint32_t base = sbase + (kc & 1) * BUFB;
        loadA(base);                 // Ah
        loadB(base + 2 * TILEB);     // Bh
        mma_all();                   // hi*hi
        loadA(base + TILEB);         // Al
        mma_all();                   // lo*hi
        loadA(base);                 // Ah again
        loadB(base + 3 * TILEB);     // Bl
        mma_all();                   // hi*lo
        __syncthreads();
    }

    // epilogue
    #pragma unroll
    for (int mt = 0; mt < 2; mt++) {
        #pragma unroll
        for (int nt = 0; nt < 8; nt++) {
            const int row = bm + wm * 32 + mt * 16 + (lane >> 2);
            const int col = bn + wn * 64 + nt * 8 + ((lane & 3) << 1);
            const float bi0 = bias[col], bi1 = bias[col + 1];
            float o00 = acc[mt][nt][0] + bi0, o01 = acc[mt][nt][1] + bi1;
            float o10 = acc[mt][nt][2] + bi0, o11 = acc[mt][nt][3] + bi1;
            if (RELU) {
                o00 = fmaxf(o00, 0.f); o01 = fmaxf(o01, 0.f);
                o10 = fmaxf(o10, 0.f); o11 = fmaxf(o11, 0.f);
            }
            const size_t i0 = (size_t)row * N + col;
            const size_t i1 = (size_t)(row + 8) * N + col;
            if (SPLIT) {
                const __nv_bfloat16 h00 = __float2bfloat16(o00), h01 = __float2bfloat16(o01);
                const __nv_bfloat16 h10 = __float2bfloat16(o10), h11 = __float2bfloat16(o11);
                __nv_bfloat162 ph0 = __halves2bfloat162(h00, h01);
                __nv_bfloat162 ph1 = __halves2bfloat162(h10, h11);
                __nv_bfloat162 pl0 = __halves2bfloat162(
                    __float2bfloat16(o00 - __bfloat162float(h00)),
                    __float2bfloat16(o01 - __bfloat162float(h01)));
                __nv_bfloat162 pl1 = __halves2bfloat162(
                    __float2bfloat16(o10 - __bfloat162float(h10)),
                    __float2bfloat16(o11 - __bfloat162float(h11)));
                *(uint32_t*)(Ch + i0) = *(uint32_t*)&ph0;
                *(uint32_t*)(Ch + i1) = *(uint32_t*)&ph1;
                *(uint32_t*)(Cl + i0) = *(uint32_t*)&pl0;
                *(uint32_t*)(Cl + i1) = *(uint32_t*)&pl1;
            } else {
                *(float2*)(C + i0) = make_float2(o00, o01);
                *(float2*)(C + i1) = make_float2(o10, o11);
            }
        }
    }
}

// ---------------------------------------------------------------------------
// fp32 -> bf16 hi/lo split (elementwise)
// ---------------------------------------------------------------------------
__global__ void __launch_bounds__(256) split_act(
    const float* __restrict__ A, __nv_bfloat16* __restrict__ hi,
    __nv_bfloat16* __restrict__ lo, int n2)
{
    const int i = blockIdx.x * 256 + threadIdx.x;
    if (i >= n2) return;
    const float2 v = ((const float2*)A)[i];
    const __nv_bfloat16 h0 = __float2bfloat16(v.x), h1 = __float2bfloat16(v.y);
    ((__nv_bfloat162*)hi)[i] = __halves2bfloat162(h0, h1);
    ((__nv_bfloat162*)lo)[i] = __halves2bfloat162(
        __float2bfloat16(v.x - __bfloat162float(h0)),
        __float2bfloat16(v.y - __bfloat162float(h1)));
}

// ---------------------------------------------------------------------------
// W[K,N] fp32 -> Wt[N,K] bf16 hi/lo (tiled transpose + split)
// ---------------------------------------------------------------------------
__global__ void __launch_bounds__(256) transpose_split(
    const float* __restrict__ W, int K, int N,
    __nv_bfloat16* __restrict__ hi, __nv_bfloat16* __restrict__ lo,
    int rowOff, int ldo)
{
    __shared__ float t[32][33];
    const int k0 = blockIdx.y * 32, n0 = blockIdx.x * 32;
    const int tx = threadIdx.x, ty = threadIdx.y;
    #pragma unroll
    for (int j = 0; j < 32; j += 8)
        t[ty + j][tx] = W[(size_t)(k0 + ty + j) * N + n0 + tx];
    __syncthreads();
    #pragma unroll
    for (int j = 0; j < 32; j += 8) {
        const float v = t[tx][ty + j];
        const size_t o = (size_t)(rowOff + n0 + ty + j) * ldo + k0 + tx;
        const __nv_bfloat16 h = __float2bfloat16(v);
        hi[o] = h;
        lo[o] = __float2bfloat16(v - __bfloat162float(h));
    }
}

__global__ void concat_bias(const float* a, const float* b, const float* c) {
    const int i = blockIdx.x * 256 + threadIdx.x;
    if (i < Ec) g_b3[i] = a[i];
    else if (i < 2 * Ec) g_b3[i] = b[i - Ec];
    else if (i < 3 * Ec) g_b3[i] = c[i - 2 * Ec];
}

// ---------------------------------------------------------------------------
// qp[b,h,i,e] = sum_d Q[b,i,h*64+d] * pos_emb[e,d]   (Q in g_QKV, ld=3072)
// ---------------------------------------------------------------------------
__global__ void __launch_bounds__(256) qp_kernel(const float* __restrict__ pos_emb)
{
    __shared__ float qsh[Ec];
    __shared__ float pe[NEc * 65];
    const int b = blockIdx.x >> 9, i = blockIdx.x & 511;
    const int tid = threadIdx.x;
    const float* qrow = g_QKV + (size_t)(b * Sc + i) * E3;
    for (int t = tid; t < Ec; t += 256) qsh[t] = qrow[t];
    for (int t = tid; t < NEc * HDc; t += 256) pe[(t >> 6) * 65 + (t & 63)] = pos_emb[t];
    __syncthreads();
    for (int o = tid; o < Hc * NEc; o += 256) {
        const int h = o / NEc, e = o - h * NEc;
        const float* qh = qsh + h * HDc;
        const float* per = pe + e * 65;
        float s = 0.f;
        #pragma unroll
        for (int d = 0; d < HDc; d++) s += qh[d] * per[d];
        g_qp[((b * Hc + h) * Sc + i) * NEc + e] = s;
    }
}

// ---------------------------------------------------------------------------
// Raw QK^T per (b,h): g_aw[bh,i,j] = Q_h[i,:] . K_h[j,:]
// ---------------------------------------------------------------------------
__global__ void __launch_bounds__(256) qk_kernel()
{
    __shared__ float Qs[64 * 65];
    __shared__ float Ks[64 * 65];
    const int bh = blockIdx.z;
    const int b = bh >> 4, h = bh & 15;
    const int bi = blockIdx.y * 64, bj = blockIdx.x * 64;
    const int tid = threadIdx.x, tx = tid & 15, ty = tid >> 4;

    const float* Qb = g_QKV + (size_t)b * Sc * E3 + h * HDc;
    const float* Kb = g_QKV + (size_t)b * Sc * E3 + Ec + h * HDc;

    #pragma unroll
    for (int t = 0; t < 16; t++) {
        const int idx = tid + 256 * t;
        const int m = idx >> 6, d = idx & 63;
        Qs[d * 65 + m] = Qb[(size_t)(bi + m) * E3 + d];
        Ks[d * 65 + m] = Kb[(size_t)(bj + m) * E3 + d];
    }
    __syncthreads();

    float acc[4][4] = {};
    #pragma unroll 4
    for (int d = 0; d < 64; d++) {
        float ar[4], br[4];
        #pragma unroll
        for (int r = 0; r < 4; r++) ar[r] = Qs[d * 65 + (ty << 2) + r];
        #pragma unroll
        for (int c = 0; c < 4; c++) br[c] = Ks[d * 65 + (tx << 2) + c];
        #pragma unroll
        for (int r = 0; r < 4; r++)
            #pragma unroll
            for (int c = 0; c < 4; c++)
                acc[r][c] += ar[r] * br[c];
    }

    #pragma unroll
    for (int r = 0; r < 4; r++) {
        const int row = bh * Sc + bi + (ty << 2) + r;
        #pragma unroll
        for (int c = 0; c < 4; c++)
            g_aw[row * Sc + bj + (tx << 2) + c] = acc[r][c];
    }
}

// ---------------------------------------------------------------------------
// Fused score + softmax + 129-bucket scatter of aw.
// ---------------------------------------------------------------------------
__global__ void __launch_bounds__(256) softmax_kernel(
    const float* __restrict__ dist, const int* __restrict__ dt)
{
    __shared__ float ssc[Sc];
    __shared__ int dts[Sc];
    __shared__ unsigned char es[Sc];
    __shared__ float bucket[NEc];
    __shared__ float red[8];

    const int i = blockIdx.x, h = blockIdx.y, b = blockIdx.z;
    const int tid = threadIdx.x;
    const int bh = b * Hc + h;
    const int rowbase = (bh * Sc + i) * Sc;
    const float* qprow = g_qp + (bh * Sc + i) * NEc;
    const float* drow = dist + ((size_t)b * Sc + i) * Sc;

    for (int t = tid; t < Sc; t += 256) dts[t] = dt[b * Sc + t];
    for (int t = tid; t < NEc; t += 256) bucket[t] = 0.f;
    __syncthreads();

    const int dti = dts[i];
    float lmax = -1e30f;
    for (int t = tid; t < Sc; t += 256) {
        int rel = dts[t] - dti;
        rel = rel < -64 ? -64 : (rel > 64 ? 64 : rel);
        const int e = rel + 64;
        es[t] = (unsigned char)e;
        const float s = (g_aw[rowbase + t] + qprow[e]) * 0.125f + 0.6f * drow[t];
        ssc[t] = s;
        lmax = fmaxf(lmax, s);
    }
    #pragma unroll
    for (int o = 16; o; o >>= 1) lmax = fmaxf(lmax, __shfl_xor_sync(0xffffffffu, lmax, o));
    if ((tid & 31) == 0) red[tid >> 5] = lmax;
    __syncthreads();
    float mx = red[0];
    #pragma unroll
    for (int w = 1; w < 8; w++) mx = fmaxf(mx, red[w]);
    __syncthreads();

    float lsum = 0.f;
    for (int t = tid; t < Sc; t += 256) {
        const float p = __expf(ssc[t] - mx);
        ssc[t] = p;
        lsum += p;
    }
    #pragma unroll
    for (int o = 16; o; o >>= 1) lsum += __shfl_xor_sync(0xffffffffu, lsum, o);
    if ((tid & 31) == 0) red[tid >> 5] = lsum;
    __syncthreads();
    float tot = 0.f;
    #pragma unroll
    for (int w = 0; w < 8; w++) tot += red[w];
    const float inv = 1.f / tot;

    for (int t = tid; t < Sc; t += 256) {
        const float a = ssc[t] * inv;
        g_aw[rowbase + t] = a;
        atomicAdd(&bucket[es[t]], a);
    }
    __syncthreads();
    for (int t = tid; t < NEc; t += 256)
        g_awp[(bh * Sc + i) * NEc + t] = bucket[t];
}

// ---------------------------------------------------------------------------
// attn = aw @ V + awp @ pos_emb  -> concat layout, written as bf16 hi/lo
// ---------------------------------------------------------------------------
__global__ void __launch_bounds__(256) attn_kernel(const float* __restrict__ pos_emb)
{
    __shared__ float As[16][64];
    __shared__ float Bs[16][64];
    const int bh = blockIdx.z;
    const int b = bh >> 4, h = bh & 15;
    const int bi = blockIdx.y * 64;
    const int tid = threadIdx.x, tx = tid & 15, ty = tid >> 4;

    const int am = tid >> 2, ak = (tid & 3) << 2;
    const int bk = tid >> 4, bn = (tid & 15) << 2;

    float acc[4][4] = {};
    const int KT = 512 + 144;

    for (int k0 = 0; k0 < KT; k0 += 16) {
        if (k0 < 512) {
            const float4 av = *reinterpret_cast<const float4*>(
                g_aw + (size_t)(bh * Sc + bi + am) * Sc + k0 + ak);
            As[ak + 0][am] = av.x; As[ak + 1][am] = av.y;
            As[ak + 2][am] = av.z; As[ak + 3][am] = av.w;
        } else {
            #pragma unroll
            for (int j = 0; j < 4; j++) {
                const int e = k0 + ak + j - 512;
                As[ak + j][am] = (e < NEc) ? g_awp[(bh * Sc + bi + am) * NEc + e] : 0.f;
            }
        }
        {
            const int kg = k0 + bk;
            if (kg < 512) {
                const float4 bv = *reinterpret_cast<const float4*>(
                    g_QKV + (size_t)(b * Sc + kg) * E3 + 2 * Ec + h * HDc + bn);
                *reinterpret_cast<float4*>(&Bs[bk][bn]) = bv;
            } else {
                const int e = kg - 512;
                if (e < NEc) {
                    const float4 bv = *reinterpret_cast<const float4*>(pos_emb + e * HDc + bn);
                    *reinterpret_cast<float4*>(&Bs[bk][bn]) = bv;
                } else {
                    Bs[bk][bn + 0] = 0.f; Bs[bk][bn + 1] = 0.f;
                    Bs[bk][bn + 2] = 0.f; Bs[bk][bn + 3] = 0.f;
                }
            }
        }
        __syncthreads();
        #pragma unroll
        for (int kk = 0; kk < 16; kk++) {
            const float4 a = *reinterpret_cast<const float4*>(&As[kk][ty << 2]);
            const float4 b4 = *reinterpret_cast<const float4*>(&Bs[kk][tx << 2]);
            const float ar[4] = {a.x, a.y, a.z, a.w};
            const float br[4] = {b4.x, b4.y, b4.z, b4.w};
            #pragma unroll
            for (int r = 0; r < 4; r++)
                #pragma unroll
                for (int c = 0; c < 4; c++)
                    acc[r][c] += ar[r] * br[c];
        }
        __syncthreads();
    }

    #pragma unroll
    for (int r = 0; r < 4; r++) {
        const size_t idx = (size_t)(b * Sc + bi + (ty << 2) + r) * Ec + h * HDc + (tx << 2);
        const __nv_bfloat16 h0 = __float2bfloat16(acc[r][0]);
        const __nv_bfloat16 h1 = __float2bfloat16(acc[r][1]);
        const __nv_bfloat16 h2 = __float2bfloat16(acc[r][2]);
        const __nv_bfloat16 h3 = __float2bfloat16(acc[r][3]);
        __nv_bfloat162 ph0 = __halves2bfloat162(h0, h1);
        __nv_bfloat162 ph1 = __halves2bfloat162(h2, h3);
        __nv_bfloat162 pl0 = __halves2bfloat162(
            __float2bfloat16(acc[r][0] - __bfloat162float(h0)),
            __float2bfloat16(acc[r][1] - __bfloat162float(h1)));
        __nv_bfloat162 pl1 = __halves2bfloat162(
            __float2bfloat16(acc[r][2] - __bfloat162float(h2)),
            __float2bfloat16(acc[r][3] - __bfloat162float(h3)));
        uint2 uh, ul;
        uh.x = *(uint32_t*)&ph0; uh.y = *(uint32_t*)&ph1;
        ul.x = *(uint32_t*)&pl0; ul.y = *(uint32_t*)&pl1;
        *(uint2*)(g_ah + idx) = uh;
        *(uint2*)(g_al + idx) = ul;
    }
}

// ---------------------------------------------------------------------------
// out = LayerNorm(X + R); optional bf16 hi/lo emission for next GEMM.
// ---------------------------------------------------------------------------
template<int SPLIT>
__global__ void __launch_bounds__(256) add_ln_kernel(
    const float* __restrict__ X, const float* __restrict__ Rr,
    const float* __restrict__ gam, const float* __restrict__ bet,
    float* __restrict__ Out, __nv_bfloat16* __restrict__ Oh,
    __nv_bfloat16* __restrict__ Ol)
{
    __shared__ float sh[Ec];
    __shared__ float red[8];
    const int row = blockIdx.x;
    const int tid = threadIdx.x;
    const float* xr = X + (size_t)row * Ec;
    const float* rr = Rr + (size_t)row * Ec;

    float lsum = 0.f;
    for (int t = tid; t < Ec; t += 256) {
        const float v = xr[t] + rr[t];
        sh[t] = v;
        lsum += v;
    }
    #pragma unroll
    for (int o = 16; o; o >>= 1) lsum += __shfl_xor_sync(0xffffffffu, lsum, o);
    if ((tid & 31) == 0) red[tid >> 5] = lsum;
    __syncthreads();
    float tot = 0.f;
    #pragma unroll
    for (int w = 0; w < 8; w++) tot += red[w];
    const float mu = tot * (1.f / Ec);
    __syncthreads();

    float lvar = 0.f;
    for (int t = tid; t < Ec; t += 256) {
        const float d = sh[t] - mu;
        lvar += d * d;
    }
    #pragma unroll
    for (int o = 16; o; o >>= 1) lvar += __shfl_xor_sync(0xffffffffu, lvar, o);
    if ((tid & 31) == 0) red[tid >> 5] = lvar;
    __syncthreads();
    float vtot = 0.f;
    #pragma unroll
    for (int w = 0; w < 8; w++) vtot += red[w];
    const float inv = rsqrtf(vtot * (1.f / Ec) + 1e-5f);

    float* orow = Out + (size_t)row * Ec;
    for (int t = tid; t < Ec; t += 256) {
        const float v = (sh[t] - mu) * inv * gam[t] + bet[t];
        orow[t] = v;
        if (SPLIT) {
            const size_t idx = (size_t)row * Ec + t;
            const __nv_bfloat16 hv = __float2bfloat16(v);
            Oh[idx] = hv;
            Ol[idx] = __float2bfloat16(v - __bfloat162float(hv));
        }
    }
}

// ---------------------------------------------------------------------------
extern "C" void kernel_launch(void* const* d_in, const int* in_sizes, int n_in,
                              void* d_out, int out_size)
{
    (void)in_sizes; (void)n_in; (void)out_size;
    const float* x       = (const float*)d_in[0];
    const float* dist    = (const float*)d_in[1];
    const int*   dt      = (const int*)d_in[2];
    const float* pos_emb = (const float*)d_in[3];
    const float* wq_w = (const float*)d_in[4];
    const float* wq_b = (const float*)d_in[5];
    const float* wk_w = (const float*)d_in[6];
    const float* wk_b = (const float*)d_in[7];
    const float* wv_w = (const float*)d_in[8];
    const float* wv_b = (const float*)d_in[9];
    const float* wo_w = (const float*)d_in[10];
    const float* wo_b = (const float*)d_in[11];
    const float* ff1_w = (const float*)d_in[12];
    const float* ff1_b = (const float*)d_in[13];
    const float* ff2_w = (const float*)d_in[14];
    const float* ff2_b = (const float*)d_in[15];
    const float* ln1_g = (const float*)d_in[16];
    const float* ln1_b = (const float*)d_in[17];
    const float* ln2_g = (const float*)d_in[18];
    const float* ln2_b = (const float*)d_in[19];
    float* out = (float*)d_out;

    __nv_bfloat16 *xh, *xl, *W3h, *W3l, *Woh, *Wol, *W1h, *W1l, *W2h, *W2l;
    __nv_bfloat16 *ah, *al, *hh, *hl, *fh, *fl;
    float *b3, *QKV, *T0, *Hs;
    cudaGetSymbolAddress((void**)&xh, g_xh);   cudaGetSymbolAddress((void**)&xl, g_xl);
    cudaGetSymbolAddress((void**)&W3h, g_W3h); cudaGetSymbolAddress((void**)&W3l, g_W3l);
    cudaGetSymbolAddress((void**)&Woh, g_Woh); cudaGetSymbolAddress((void**)&Wol, g_Wol);
    cudaGetSymbolAddress((void**)&W1h, g_W1h); cudaGetSymbolAddress((void**)&W1l, g_W1l);
    cudaGetSymbolAddress((void**)&W2h, g_W2h); cudaGetSymbolAddress((void**)&W2l, g_W2l);
    cudaGetSymbolAddress((void**)&ah, g_ah);   cudaGetSymbolAddress((void**)&al, g_al);
    cudaGetSymbolAddress((void**)&hh, g_hh);   cudaGetSymbolAddress((void**)&hl, g_hl);
    cudaGetSymbolAddress((void**)&fh, g_fh);   cudaGetSymbolAddress((void**)&fl, g_fl);
    cudaGetSymbolAddress((void**)&b3, g_b3);
    cudaGetSymbolAddress((void**)&QKV, g_QKV);
    cudaGetSymbolAddress((void**)&T0, g_t0);
    cudaGetSymbolAddress((void**)&Hs, g_h);

    cudaFuncSetAttribute(mma_gemm<0, 0>, cudaFuncAttributeMaxDynamicSharedMemorySize, MMA_SMEM);
    cudaFuncSetAttribute(mma_gemm<1, 1>, cudaFuncAttributeMaxDynamicSharedMemorySize, MMA_SMEM);

    dim3 blk(256);
    dim3 tblk(32, 8);

    // operand prep
    split_act<<<(Mc * Ec / 2 + 255) / 256, blk>>>(x, xh, xl, Mc * Ec / 2);
    transpose_split<<<dim3(Ec / 32, Ec / 32), tblk>>>(wq_w, Ec, Ec, W3h, W3l, 0, Ec);
    transpose_split<<<dim3(Ec / 32, Ec / 32), tblk>>>(wk_w, Ec, Ec, W3h, W3l, Ec, Ec);
    transpose_split<<<dim3(Ec / 32, Ec / 32), tblk>>>(wv_w, Ec, Ec, W3h, W3l, 2 * Ec, Ec);
    transpose_split<<<dim3(Ec / 32, Ec / 32), tblk>>>(wo_w, Ec, Ec, Woh, Wol, 0, Ec);
    transpose_split<<<dim3(FFc / 32, Ec / 32), tblk>>>(ff1_w, Ec, FFc, W1h, W1l, 0, Ec);
    transpose_split<<<dim3(Ec / 32, FFc / 32), tblk>>>(ff2_w, FFc, Ec, W2h, W2l, 0, FFc);
    concat_bias<<<12, blk>>>(wq_b, wk_b, wv_b);

    // fused QKV projection: [4096,1024] @ [1024,3072] -> g_QKV
    mma_gemm<0, 0><<<dim3(E3 / 128, Mc / 128), blk, MMA_SMEM>>>(
        xh, xl, W3h, W3l, b3, QKV, nullptr, nullptr, Ec, E3);

    qp_kernel<<<Mc, blk>>>(pos_emb);
    qk_kernel<<<dim3(Sc / 64, Sc / 64, Bc * Hc), blk>>>();
    softmax_kernel<<<dim3(Sc, Hc, Bc), blk>>>(dist, dt);
    attn_kernel<<<dim3(1, Sc / 64, Bc * Hc), blk>>>(pos_emb);

    // output projection
    mma_gemm<0, 0><<<dim3(Ec / 128, Mc / 128), blk, MMA_SMEM>>>(
        ah, al, Woh, Wol, wo_b, T0, nullptr, nullptr, Ec, Ec);

    // h = LN(x + attn_out), emit hi/lo for FF1
    add_ln_kernel<1><<<Mc, blk>>>(x, T0, ln1_g, ln1_b, Hs, hh, hl);

    // FF1 (ReLU, split output) and FF2
    mma_gemm<1, 1><<<dim3(FFc / 128, Mc / 128), blk, MMA_SMEM>>>(
        hh, hl, W1h, W1l, ff1_b, nullptr, fh, fl, Ec, FFc);
    mma_gemm<0, 0><<<dim3(Ec / 128, Mc / 128), blk, MMA_SMEM>>>(
        fh, fl, W2h, W2l, ff2_b, T0, nullptr, nullptr, FFc, Ec);

    // out = LN(h + ffn)
    add_ln_kernel<0><<<Mc, blk>>>(Hs, T0, ln2_g, ln2_b, out, nullptr, nullptr);
}

// round 4
// speedup vs baseline: 1.9280x; 1.1361x over previous
#include <cuda_runtime.h>
#include <cuda_bf16.h>
#include <cstdint>
#include <math.h>

// Problem constants
constexpr int Bc  = 8;
constexpr int Sc  = 512;
constexpr int Ec  = 1024;
constexpr int Hc  = 16;
constexpr int HDc = 64;
constexpr int FFc = 4096;
constexpr int NEc = 129;           // 2P+1
constexpr int Mc  = Bc * Sc;       // 4096 rows
constexpr int E3  = 3 * Ec;        // 3072
constexpr int SE  = 672;           // extended score width: 512 + 129 + pad (mult of 32)

// ---------------------------------------------------------------------------
// Scratch (device globals; no allocation allowed)
// ---------------------------------------------------------------------------
__device__ __align__(256) __nv_bfloat16 g_xh[Mc * Ec];
__device__ __align__(256) __nv_bfloat16 g_xl[Mc * Ec];
__device__ __align__(256) __nv_bfloat16 g_W3h[E3 * Ec];
__device__ __align__(256) __nv_bfloat16 g_W3l[E3 * Ec];
__device__ __align__(256) __nv_bfloat16 g_Woh[Ec * Ec];
__device__ __align__(256) __nv_bfloat16 g_Wol[Ec * Ec];
__device__ __align__(256) __nv_bfloat16 g_W1h[FFc * Ec];
__device__ __align__(256) __nv_bfloat16 g_W1l[FFc * Ec];
__device__ __align__(256) __nv_bfloat16 g_W2h[Ec * FFc];
__device__ __align__(256) __nv_bfloat16 g_W2l[Ec * FFc];
__device__ float g_b3[E3];
__device__ __align__(256) __nv_bfloat16 g_qkvh[Mc * E3];   // bf16 hi of q|k|v
__device__ __align__(256) __nv_bfloat16 g_qkvl[Mc * E3];
__device__ __align__(256) __nv_bfloat16 g_peh[256 * HDc];  // padded pos_emb split
__device__ __align__(256) __nv_bfloat16 g_pel[256 * HDc];
__device__ float g_aw[128 * Sc * SE];                      // fp32 scores (176 MB)
__device__ __align__(256) __nv_bfloat16 g_awh[128 * Sc * SE];
__device__ __align__(256) __nv_bfloat16 g_awl[128 * Sc * SE];
__device__ __align__(256) __nv_bfloat16 g_vth[128 * HDc * SE];  // per-head V^T (+pe^T)
__device__ __align__(256) __nv_bfloat16 g_vtl[128 * HDc * SE];
__device__ __align__(256) __nv_bfloat16 g_ah[Mc * Ec];
__device__ __align__(256) __nv_bfloat16 g_al[Mc * Ec];
__device__ float g_t0[Mc * Ec];
__device__ float g_h[Mc * Ec];
__device__ __align__(256) __nv_bfloat16 g_hh[Mc * Ec];
__device__ __align__(256) __nv_bfloat16 g_hl[Mc * Ec];
__device__ __align__(256) __nv_bfloat16 g_fh[Mc * FFc];
__device__ __align__(256) __nv_bfloat16 g_fl[Mc * FFc];

// ---------------------------------------------------------------------------
// PTX helpers (sm_80-era: HMMA / ldmatrix / cp.async — no tcgen05)
// ---------------------------------------------------------------------------
__device__ __forceinline__ uint32_t smem_u32(const void* p) {
    uint32_t a;
    asm("{ .reg .u64 t; cvta.to.shared.u64 t, %1; cvt.u32.u64 %0, t; }" : "=r"(a) : "l"(p));
    return a;
}
__device__ __forceinline__ void cpasync16(uint32_t dst, const void* src) {
    asm volatile("cp.async.cg.shared.global [%0], [%1], 16;" :: "r"(dst), "l"(src));
}
#define CP_COMMIT()  asm volatile("cp.async.commit_group;" ::: "memory")
#define CP_WAIT(n)   asm volatile("cp.async.wait_group %0;" :: "n"(n) : "memory")

__device__ __forceinline__ void ldsm4(uint32_t* r, uint32_t addr) {
    asm volatile("ldmatrix.sync.aligned.m8n8.x4.shared.b16 {%0,%1,%2,%3}, [%4];"
                 : "=r"(r[0]), "=r"(r[1]), "=r"(r[2]), "=r"(r[3]) : "r"(addr));
}
__device__ __forceinline__ void mma_bf16(float* c, const uint32_t* a, const uint32_t* b) {
    asm volatile(
        "mma.sync.aligned.m16n8k16.row.col.f32.bf16.bf16.f32 "
        "{%0,%1,%2,%3}, {%4,%5,%6,%7}, {%8,%9}, {%0,%1,%2,%3};"
        : "+f"(c[0]), "+f"(c[1]), "+f"(c[2]), "+f"(c[3])
        : "r"(a[0]), "r"(a[1]), "r"(a[2]), "r"(a[3]), "r"(b[0]), "r"(b[1]));
}
__device__ __forceinline__ void split2(float v0, float v1, uint32_t& uh, uint32_t& ul) {
    const __nv_bfloat16 h0 = __float2bfloat16(v0), h1 = __float2bfloat16(v1);
    __nv_bfloat162 ph = __halves2bfloat162(h0, h1);
    __nv_bfloat162 pl = __halves2bfloat162(
        __float2bfloat16(v0 - __bfloat162float(h0)),
        __float2bfloat16(v1 - __bfloat162float(h1)));
    uh = *(uint32_t*)&ph; ul = *(uint32_t*)&pl;
}

// ---------------------------------------------------------------------------
// HMMA GEMM: C[M,N] = (Ah+Al)[M,K] @ (Bh+Bl)[N,K]^T + bias  (3-pass split)
// 128x128 CTA tile, BK=32, 8 warps of 32x64, cp.async double buffer.
// ---------------------------------------------------------------------------
constexpr int LDSp  = 40;
constexpr int TILEB = 128 * LDSp * 2;
constexpr int BUFB  = 4 * TILEB;
constexpr int MMA_SMEM = 2 * BUFB;         // 81920 B

template<int RELU, int SPLIT>
__global__ void __launch_bounds__(256)
mma_gemm(const __nv_bfloat16* __restrict__ Ah, const __nv_bfloat16* __restrict__ Al,
         const __nv_bfloat16* __restrict__ Bh, const __nv_bfloat16* __restrict__ Bl,
         const float* __restrict__ bias, float* __restrict__ C,
         __nv_bfloat16* __restrict__ Ch, __nv_bfloat16* __restrict__ Cl,
         int K, int N)
{
    extern __shared__ char sm[];
    const uint32_t sbase = smem_u32(sm);
    const int tid = threadIdx.x;
    const int wid = tid >> 5, lane = tid & 31;
    const int wm = wid & 3, wn = wid >> 2;
    const int bm = blockIdx.y * 128, bn = blockIdx.x * 128;

    const int r0l = tid >> 2, sg = (tid & 3) << 3;

    auto load_chunk = [&](int kc) {
        const int buf = kc & 1;
        const uint32_t base = sbase + buf * BUFB;
        const int k0 = kc * 32;
        #pragma unroll
        for (int it = 0; it < 2; it++) {
            const int r = r0l + it * 64;
            const uint32_t dst = base + r * 80 + sg * 2;
            const size_t ao = (size_t)(bm + r) * K + k0 + sg;
            const size_t bo = (size_t)(bn + r) * K + k0 + sg;
            cpasync16(dst,             Ah + ao);
            cpasync16(dst + TILEB,     Al + ao);
            cpasync16(dst + 2 * TILEB, Bh + bo);
            cpasync16(dst + 3 * TILEB, Bl + bo);
        }
        CP_COMMIT();
    };

    float acc[2][8][4];
    #pragma unroll
    for (int mt = 0; mt < 2; mt++)
        #pragma unroll
        for (int nt = 0; nt < 8; nt++)
            #pragma unroll
            for (int i = 0; i < 4; i++) acc[mt][nt][i] = 0.f;

    uint32_t aF[2][2][4];
    uint32_t bF[8][2][2];

    const int a_row = wm * 32 + (lane & 15);
    const int a_kof = (lane >> 4) << 3;
    const int b_n   = wn * 64 + (lane & 7) + ((lane & 16) >> 1);
    const int b_kof = ((lane >> 3) & 1) << 3;

    auto loadA = [&](uint32_t tbase) {
        #pragma unroll
        for (int mt = 0; mt < 2; mt++)
            #pragma unroll
            for (int ks = 0; ks < 2; ks++)
                ldsm4(aF[mt][ks], tbase + (a_row + mt * 16) * 80 + (ks * 16 + a_kof) * 2);
    };
    auto loadB = [&](uint32_t tbase) {
        #pragma unroll
        for (int ntp = 0; ntp < 4; ntp++)
            #pragma unroll
            for (int ks = 0; ks < 2; ks++) {
                uint32_t t4[4];
                ldsm4(t4, tbase + (b_n + ntp * 16) * 80 + (ks * 16 + b_kof) * 2);
                bF[ntp * 2 + 0][ks][0] = t4[0]; bF[ntp * 2 + 0][ks][1] = t4[1];
                bF[ntp * 2 + 1][ks][0] = t4[2]; bF[ntp * 2 + 1][ks][1] = t4[3];
            }
    };
    auto mma_all = [&]() {
        #pragma unroll
        for (int ks = 0; ks < 2; ks++)
            #pragma unroll
            for (int mt = 0; mt < 2; mt++)
                #pragma unroll
                for (int nt = 0; nt < 8; nt++)
                    mma_bf16(acc[mt][nt], aF[mt][ks], bF[nt][ks]);
    };

    const int nk = K / 32;
    load_chunk(0);
    for (int kc = 0; kc < nk; kc++) {
        if (kc + 1 < nk) { load_chunk(kc + 1); CP_WAIT(1); }
        else             { CP_WAIT(0); }
        __syncthreads();

        const uint32_t base = sbase + (kc & 1) * BUFB;
        loadA(base);
        loadB(base + 2 * TILEB);
        mma_all();
        loadA(base + TILEB);
        mma_all();
        loadA(base);
        loadB(base + 3 * TILEB);
        mma_all();
        __syncthreads();
    }

    #pragma unroll
    for (int mt = 0; mt < 2; mt++) {
        #pragma unroll
        for (int nt = 0; nt < 8; nt++) {
            const int row = bm + wm * 32 + mt * 16 + (lane >> 2);
            const int col = bn + wn * 64 + nt * 8 + ((lane & 3) << 1);
            const float bi0 = bias[col], bi1 = bias[col + 1];
            float o00 = acc[mt][nt][0] + bi0, o01 = acc[mt][nt][1] + bi1;
            float o10 = acc[mt][nt][2] + bi0, o11 = acc[mt][nt][3] + bi1;
            if (RELU) {
                o00 = fmaxf(o00, 0.f); o01 = fmaxf(o01, 0.f);
                o10 = fmaxf(o10, 0.f); o11 = fmaxf(o11, 0.f);
            }
            const size_t i0 = (size_t)row * N + col;
            const size_t i1 = (size_t)(row + 8) * N + col;
            if (SPLIT) {
                uint32_t uh0, ul0, uh1, ul1;
                split2(o00, o01, uh0, ul0);
                split2(o10, o11, uh1, ul1);
                *(uint32_t*)(Ch + i0) = uh0;
                *(uint32_t*)(Ch + i1) = uh1;
                *(uint32_t*)(Cl + i0) = ul0;
                *(uint32_t*)(Cl + i1) = ul1;
            } else {
                *(float2*)(C + i0) = make_float2(o00, o01);
                *(float2*)(C + i1) = make_float2(o10, o11);
            }
        }
    }
}

// ---------------------------------------------------------------------------
// Fused scores GEMM (HMMA): per (b,h):
//   AW[i, j]      = Q_h[i,:] . K_h[j,:]          (j < 512)
//   AW[i, 512+e]  = Q_h[i,:] . pos_emb[e,:]      (e < 129; pad rows are zero)
// A = Q (bf16 hi/lo, ld=3072), B rows: K_h (ld=3072) or padded pe table (ld=64).
// CTA: 128x128 tile, K=64, single-buffer smem. grid (6, 4, 128).
// ---------------------------------------------------------------------------
constexpr int QK_LDS = 72;                         // padded row elems
constexpr int QK_T   = 128 * QK_LDS * 2;           // 18432 B per tile
constexpr int QK_SMEM = 4 * QK_T;                  // 73728 B

__global__ void __launch_bounds__(256)
qk_scores(float* __restrict__ AW)
{
    extern __shared__ char sm[];
    const uint32_t sA = smem_u32(sm);
    const uint32_t sB = sA + 2 * QK_T;
    const int tid = threadIdx.x;
    const int wid = tid >> 5, lane = tid & 31;
    const int wm = wid & 3, wn = wid >> 2;
    const int bn = blockIdx.x * 128, bm = blockIdx.y * 128;
    const int bh = blockIdx.z, b = bh >> 4, h = bh & 15;

    // load A (Q tile) and B (K rows / pe rows), hi+lo
    {
        const int r0 = tid >> 3, sg = (tid & 7) << 3;
        #pragma unroll
        for (int it = 0; it < 4; it++) {
            const int r = r0 + it * 32;
            const uint32_t off = (r * QK_LDS + sg) * 2;
            const size_t ao = (size_t)(b * Sc + bm + r) * E3 + h * HDc + sg;
            cpasync16(sA + off,        g_qkvh + ao);
            cpasync16(sA + QK_T + off, g_qkvl + ao);
            const int gr = bn + r;
            const __nv_bfloat16 *bph, *bpl;
            if (gr < Sc) {
                const size_t bo = (size_t)(b * Sc + gr) * E3 + Ec + h * HDc + sg;
                bph = g_qkvh + bo; bpl = g_qkvl + bo;
            } else {
                const size_t bo = (size_t)(gr - Sc) * HDc + sg;
                bph = g_peh + bo;  bpl = g_pel + bo;
            }
            cpasync16(sB + off,        bph);
            cpasync16(sB + QK_T + off, bpl);
        }
        CP_COMMIT(); CP_WAIT(0);
        __syncthreads();
    }

    float acc[2][8][4];
    #pragma unroll
    for (int mt = 0; mt < 2; mt++)
        #pragma unroll
        for (int nt = 0; nt < 8; nt++)
            #pragma unroll
            for (int i = 0; i < 4; i++) acc[mt][nt][i] = 0.f;

    uint32_t aF[2][2][4], bF[8][2][2];
    const int a_row = wm * 32 + (lane & 15);
    const int a_kof = (lane >> 4) << 3;
    const int b_n   = wn * 64 + (lane & 7) + ((lane & 16) >> 1);
    const int b_kof = ((lane >> 3) & 1) << 3;

    auto loadA = [&](uint32_t tb, int k0) {
        #pragma unroll
        for (int mt = 0; mt < 2; mt++)
            #pragma unroll
            for (int ks = 0; ks < 2; ks++)
                ldsm4(aF[mt][ks], tb + ((a_row + mt * 16) * QK_LDS + k0 + ks * 16 + a_kof) * 2);
    };
    auto loadB = [&](uint32_t tb, int k0) {
        #pragma unroll
        for (int ntp = 0; ntp < 4; ntp++)
            #pragma unroll
            for (int ks = 0; ks < 2; ks++) {
                uint32_t t4[4];
                ldsm4(t4, tb + ((b_n + ntp * 16) * QK_LDS + k0 + ks * 16 + b_kof) * 2);
                bF[ntp * 2 + 0][ks][0] = t4[0]; bF[ntp * 2 + 0][ks][1] = t4[1];
                bF[ntp * 2 + 1][ks][0] = t4[2]; bF[ntp * 2 + 1][ks][1] = t4[3];
            }
    };
    auto mma_all = [&]() {
        #pragma unroll
        for (int ks = 0; ks < 2; ks++)
            #pragma unroll
            for (int mt = 0; mt < 2; mt++)
                #pragma unroll
                for (int nt = 0; nt < 8; nt++)
                    mma_bf16(acc[mt][nt], aF[mt][ks], bF[nt][ks]);
    };

    #pragma unroll
    for (int kg = 0; kg < 2; kg++) {
        const int k0 = kg * 32;
        loadA(sA, k0);
        loadB(sB, k0);
        mma_all();                    // hi*hi
        loadA(sA + QK_T, k0);
        mma_all();                    // lo*hi
        loadA(sA, k0);
        loadB(sB + QK_T, k0);
        mma_all();                    // hi*lo
    }

    #pragma unroll
    for (int mt = 0; mt < 2; mt++) {
        #pragma unroll
        for (int nt = 0; nt < 8; nt++) {
            const int row = bm + wm * 32 + mt * 16 + (lane >> 2);
            const int col = bn + wn * 64 + nt * 8 + ((lane & 3) << 1);
            if (col < SE) {
                const size_t base = (size_t)(bh * Sc + row) * SE + col;
                *(float2*)(AW + base)            = make_float2(acc[mt][nt][0], acc[mt][nt][1]);
                *(float2*)(AW + base + 8ull * SE) = make_float2(acc[mt][nt][2], acc[mt][nt][3]);
            }
        }
    }
}

// ---------------------------------------------------------------------------
// Per-head V^T build: vt[bh][d][j] = V_h[j][d] (j<512), pe[j-512][d] (<641), 0
// ---------------------------------------------------------------------------
__global__ void vt_build()
{
    __shared__ __nv_bfloat16 th[32][33], tl[32][33];
    const int jt = blockIdx.x, dt = blockIdx.y, bh = blockIdx.z;
    const int b = bh >> 4, h = bh & 15;
    const int j0 = jt * 32, d0 = dt * 32;
    const int tx = threadIdx.x, ty = threadIdx.y;

    #pragma unroll
    for (int k = 0; k < 4; k++) {
        const int j = j0 + ty + k * 8;
        const int d = d0 + tx;
        __nv_bfloat16 vh, vl;
        if (j < Sc) {
            const size_t o = (size_t)(b * Sc + j) * E3 + 2 * Ec + h * HDc + d;
            vh = g_qkvh[o]; vl = g_qkvl[o];
        } else if (j < Sc + NEc) {
            const size_t o = (size_t)(j - Sc) * HDc + d;
            vh = g_peh[o]; vl = g_pel[o];
        } else {
            vh = __float2bfloat16(0.f); vl = __float2bfloat16(0.f);
        }
        th[ty + k * 8][tx] = vh;
        tl[ty + k * 8][tx] = vl;
    }
    __syncthreads();
    #pragma unroll
    for (int k = 0; k < 4; k++) {
        const int d = d0 + ty + k * 8;
        const int j = j0 + tx;
        const size_t o = (size_t)bh * HDc * SE + (size_t)d * SE + j;
        g_vth[o] = th[tx][ty + k * 8];
        g_vtl[o] = tl[tx][ty + k * 8];
    }
}

// ---------------------------------------------------------------------------
// AV GEMM (HMMA): attn[b,i,h*64+d] = sum_k awx[bh,i,k] * vt[bh,d,k], k<672
// CTA: 128 rows x 64 cols, 8 warps of 16x64, double-buffered. grid (4, 128).
// ---------------------------------------------------------------------------
constexpr int AV_AT = 128 * LDSp * 2;       // 10240
constexpr int AV_BT = 64 * LDSp * 2;        // 5120
constexpr int AV_BUF = 2 * AV_AT + 2 * AV_BT;  // 30720
constexpr int AV_SMEM = 2 * AV_BUF;            // 61440

__global__ void __launch_bounds__(256)
av_mma()
{
    extern __shared__ char sm[];
    const uint32_t sbase = smem_u32(sm);
    const int tid = threadIdx.x;
    const int wid = tid >> 5, lane = tid & 31;
    const int bm = blockIdx.x * 128;
    const int bh = blockIdx.y, b = bh >> 4, h = bh & 15;

    auto load_chunk = [&](int kc) {
        const int buf = kc & 1;
        const uint32_t base = sbase + buf * AV_BUF;
        const int k0 = kc * 32;
        const int sg = (tid & 3) << 3;
        #pragma unroll
        for (int it = 0; it < 2; it++) {
            const int r = (tid >> 2) + it * 64;
            const uint32_t dst = base + r * 80 + sg * 2;
            const size_t ao = (size_t)(bh * Sc + bm + r) * SE + k0 + sg;
            cpasync16(dst,         g_awh + ao);
            cpasync16(dst + AV_AT, g_awl + ao);
        }
        {
            const int r = tid >> 2;
            if (r < 64) {
                const uint32_t dst = base + 2 * AV_AT + r * 80 + sg * 2;
                const size_t bo = (size_t)bh * HDc * SE + (size_t)r * SE + k0 + sg;
                cpasync16(dst,         g_vth + bo);
                cpasync16(dst + AV_BT, g_vtl + bo);
            }
        }
        CP_COMMIT();
    };

    float acc[8][4];
    #pragma unroll
    for (int nt = 0; nt < 8; nt++)
        #pragma unroll
        for (int i = 0; i < 4; i++) acc[nt][i] = 0.f;

    uint32_t aF[2][4], bF[8][2][2];
    const int a_row = wid * 16 + (lane & 15);
    const int a_kof = (lane >> 4) << 3;
    const int b_n   = (lane & 7) + ((lane & 16) >> 1);
    const int b_kof = ((lane >> 3) & 1) << 3;

    auto loadA = [&](uint32_t tb) {
        #pragma unroll
        for (int ks = 0; ks < 2; ks++)
            ldsm4(aF[ks], tb + (a_row * 80) + (ks * 16 + a_kof) * 2);
    };
    auto loadB = [&](uint32_t tb) {
        #pragma unroll
        for (int ntp = 0; ntp < 4; ntp++)
            #pragma unroll
            for (int ks = 0; ks < 2; ks++) {
                uint32_t t4[4];
                ldsm4(t4, tb + (b_n + ntp * 16) * 80 + (ks * 16 + b_kof) * 2);
                bF[ntp * 2 + 0][ks][0] = t4[0]; bF[ntp * 2 + 0][ks][1] = t4[1];
                bF[ntp * 2 + 1][ks][0] = t4[2]; bF[ntp * 2 + 1][ks][1] = t4[3];
            }
    };
    auto mma_all = [&]() {
        #pragma unroll
        for (int ks = 0; ks < 2; ks++)
            #pragma unroll
            for (int nt = 0; nt < 8; nt++)
                mma_bf16(acc[nt], aF[ks], bF[nt][ks]);
    };

    const int nk = SE / 32;   // 21
    load_chunk(0);
    for (int kc = 0; kc < nk; kc++) {
        if (kc + 1 < nk) { load_chunk(kc + 1); CP_WAIT(1); }
        else             { CP_WAIT(0); }
        __syncthreads();
        const uint32_t base = sbase + (kc & 1) * AV_BUF;
        loadA(base);
        loadB(base + 2 * AV_AT);
        mma_all();
        loadA(base + AV_AT);
        mma_all();
        loadA(base);
        loadB(base + 2 * AV_AT + AV_BT);
        mma_all();
        __syncthreads();
    }

    #pragma unroll
    for (int nt = 0; nt < 8; nt++) {
        const int row = bm + wid * 16 + (lane >> 2);
        const int col = nt * 8 + ((lane & 3) << 1);
        const size_t i0 = (size_t)(b * Sc + row) * Ec + h * HDc + col;
        const size_t i1 = (size_t)(b * Sc + row + 8) * Ec + h * HDc + col;
        uint32_t uh0, ul0, uh1, ul1;
        split2(acc[nt][0], acc[nt][1], uh0, ul0);
        split2(acc[nt][2], acc[nt][3], uh1, ul1);
        *(uint32_t*)(g_ah + i0) = uh0;
        *(uint32_t*)(g_ah + i1) = uh1;
        *(uint32_t*)(g_al + i0) = ul0;
        *(uint32_t*)(g_al + i1) = ul1;
    }
}

// ---------------------------------------------------------------------------
// Elementwise prep kernels
// ---------------------------------------------------------------------------
__global__ void __launch_bounds__(256) split_act(
    const float* __restrict__ A, __nv_bfloat16* __restrict__ hi,
    __nv_bfloat16* __restrict__ lo, int n2)
{
    const int i = blockIdx.x * 256 + threadIdx.x;
    if (i >= n2) return;
    const float2 v = ((const float2*)A)[i];
    uint32_t uh, ul;
    split2(v.x, v.y, uh, ul);
    ((uint32_t*)hi)[i] = uh;
    ((uint32_t*)lo)[i] = ul;
}

__global__ void __launch_bounds__(256) transpose_split(
    const float* __restrict__ W, int K, int N,
    __nv_bfloat16* __restrict__ hi, __nv_bfloat16* __restrict__ lo,
    int rowOff, int ldo)
{
    __shared__ float t[32][33];
    const int k0 = blockIdx.y * 32, n0 = blockIdx.x * 32;
    const int tx = threadIdx.x, ty = threadIdx.y;
    #pragma unroll
    for (int j = 0; j < 32; j += 8)
        t[ty + j][tx] = W[(size_t)(k0 + ty + j) * N + n0 + tx];
    __syncthreads();
    #pragma unroll
    for (int j = 0; j < 32; j += 8) {
        const float v = t[tx][ty + j];
        const size_t o = (size_t)(rowOff + n0 + ty + j) * ldo + k0 + tx;
        const __nv_bfloat16 h = __float2bfloat16(v);
        hi[o] = h;
        lo[o] = __float2bfloat16(v - __bfloat162float(h));
    }
}

__global__ void concat_bias(const float* a, const float* b, const float* c) {
    const int i = blockIdx.x * 256 + threadIdx.x;
    if (i < Ec) g_b3[i] = a[i];
    else if (i < 2 * Ec) g_b3[i] = b[i - Ec];
    else if (i < 3 * Ec) g_b3[i] = c[i - 2 * Ec];
}

__global__ void pe_split(const float* __restrict__ pos_emb) {
    const int i = blockIdx.x * 256 + threadIdx.x;
    if (i >= 256 * HDc) return;
    const int e = i >> 6;
    const float v = (e < NEc) ? pos_emb[i] : 0.f;
    const __nv_bfloat16 h = __float2bfloat16(v);
    g_peh[i] = h;
    g_pel[i] = __float2bfloat16(v - __bfloat162float(h));
}

// ---------------------------------------------------------------------------
// Fused score assembly + softmax + bucket scatter; emits bf16 hi/lo aw_ext.
// ---------------------------------------------------------------------------
__global__ void __launch_bounds__(256) softmax_kernel(
    const float* __restrict__ dist, const int* __restrict__ dt)
{
    __shared__ float ssc[Sc];
    __shared__ int dts[Sc];
    __shared__ unsigned char es[Sc];
    __shared__ float bucket[NEc];
    __shared__ float red[8];

    const int i = blockIdx.x, h = blockIdx.y, b = blockIdx.z;
    const int tid = threadIdx.x;
    const int bh = b * Hc + h;
    const size_t rowbase = (size_t)(bh * Sc + i) * SE;
    const float* drow = dist + ((size_t)b * Sc + i) * Sc;

    for (int t = tid; t < Sc; t += 256) dts[t] = dt[b * Sc + t];
    for (int t = tid; t < NEc; t += 256) bucket[t] = 0.f;
    __syncthreads();

    const int dti = dts[i];
    float lmax = -1e30f;
    for (int t = tid; t < Sc; t += 256) {
        int rel = dts[t] - dti;
        rel = rel < -64 ? -64 : (rel > 64 ? 64 : rel);
        const int e = rel + 64;
        es[t] = (unsigned char)e;
        const float s = (g_aw[rowbase + t] + g_aw[rowbase + Sc + e]) * 0.125f + 0.6f * drow[t];
        ssc[t] = s;
        lmax = fmaxf(lmax, s);
    }
    #pragma unroll
    for (int o = 16; o; o >>= 1) lmax = fmaxf(lmax, __shfl_xor_sync(0xffffffffu, lmax, o));
    if ((tid & 31) == 0) red[tid >> 5] = lmax;
    __syncthreads();
    float mx = red[0];
    #pragma unroll
    for (int w = 1; w < 8; w++) mx = fmaxf(mx, red[w]);
    __syncthreads();

    float lsum = 0.f;
    for (int t = tid; t < Sc; t += 256) {
        const float p = __expf(ssc[t] - mx);
        ssc[t] = p;
        lsum += p;
    }
    #pragma unroll
    for (int o = 16; o; o >>= 1) lsum += __shfl_xor_sync(0xffffffffu, lsum, o);
    if ((tid & 31) == 0) red[tid >> 5] = lsum;
    __syncthreads();
    float tot = 0.f;
    #pragma unroll
    for (int w = 0; w < 8; w++) tot += red[w];
    const float inv = 1.f / tot;

    for (int t = tid; t < Sc; t += 256) {
        const float a = ssc[t] * inv;
        const __nv_bfloat16 hv = __float2bfloat16(a);
        g_awh[rowbase + t] = hv;
        g_awl[rowbase + t] = __float2bfloat16(a - __bfloat162float(hv));
        atomicAdd(&bucket[es[t]], a);
    }
    __syncthreads();
    for (int t = tid; t < SE - Sc; t += 256) {
        const float v = (t < NEc) ? bucket[t] : 0.f;
        const __nv_bfloat16 hv = __float2bfloat16(v);
        g_awh[rowbase + Sc + t] = hv;
        g_awl[rowbase + Sc + t] = __float2bfloat16(v - __bfloat162float(hv));
    }
}

// ---------------------------------------------------------------------------
// out = LayerNorm(X + R); optional bf16 hi/lo emission.
// ---------------------------------------------------------------------------
template<int SPLIT>
__global__ void __launch_bounds__(256) add_ln_kernel(
    const float* __restrict__ X, const float* __restrict__ Rr,
    const float* __restrict__ gam, const float* __restrict__ bet,
    float* __restrict__ Out, __nv_bfloat16* __restrict__ Oh,
    __nv_bfloat16* __restrict__ Ol)
{
    __shared__ float sh[Ec];
    __shared__ float red[8];
    const int row = blockIdx.x;
    const int tid = threadIdx.x;
    const float* xr = X + (size_t)row * Ec;
    const float* rr = Rr + (size_t)row * Ec;

    float lsum = 0.f;
    for (int t = tid; t < Ec; t += 256) {
        const float v = xr[t] + rr[t];
        sh[t] = v;
        lsum += v;
    }
    #pragma unroll
    for (int o = 16; o; o >>= 1) lsum += __shfl_xor_sync(0xffffffffu, lsum, o);
    if ((tid & 31) == 0) red[tid >> 5] = lsum;
    __syncthreads();
    float tot = 0.f;
    #pragma unroll
    for (int w = 0; w < 8; w++) tot += red[w];
    const float mu = tot * (1.f / Ec);
    __syncthreads();

    float lvar = 0.f;
    for (int t = tid; t < Ec; t += 256) {
        const float d = sh[t] - mu;
        lvar += d * d;
    }
    #pragma unroll
    for (int o = 16; o; o >>= 1) lvar += __shfl_xor_sync(0xffffffffu, lvar, o);
    if ((tid & 31) == 0) red[tid >> 5] = lvar;
    __syncthreads();
    float vtot = 0.f;
    #pragma unroll
    for (int w = 0; w < 8; w++) vtot += red[w];
    const float inv = rsqrtf(vtot * (1.f / Ec) + 1e-5f);

    float* orow = Out + (size_t)row * Ec;
    for (int t = tid; t < Ec; t += 256) {
        const float v = (sh[t] - mu) * inv * gam[t] + bet[t];
        orow[t] = v;
        if (SPLIT) {
            const size_t idx = (size_t)row * Ec + t;
            const __nv_bfloat16 hv = __float2bfloat16(v);
            Oh[idx] = hv;
            Ol[idx] = __float2bfloat16(v - __bfloat162float(hv));
        }
    }
}

// ---------------------------------------------------------------------------
extern "C" void kernel_launch(void* const* d_in, const int* in_sizes, int n_in,
                              void* d_out, int out_size)
{
    (void)in_sizes; (void)n_in; (void)out_size;
    const float* x       = (const float*)d_in[0];
    const float* dist    = (const float*)d_in[1];
    const int*   dt      = (const int*)d_in[2];
    const float* pos_emb = (const float*)d_in[3];
    const float* wq_w = (const float*)d_in[4];
    const float* wq_b = (const float*)d_in[5];
    const float* wk_w = (const float*)d_in[6];
    const float* wk_b = (const float*)d_in[7];
    const float* wv_w = (const float*)d_in[8];
    const float* wv_b = (const float*)d_in[9];
    const float* wo_w = (const float*)d_in[10];
    const float* wo_b = (const float*)d_in[11];
    const float* ff1_w = (const float*)d_in[12];
    const float* ff1_b = (const float*)d_in[13];
    const float* ff2_w = (const float*)d_in[14];
    const float* ff2_b = (const float*)d_in[15];
    const float* ln1_g = (const float*)d_in[16];
    const float* ln1_b = (const float*)d_in[17];
    const float* ln2_g = (const float*)d_in[18];
    const float* ln2_b = (const float*)d_in[19];
    float* out = (float*)d_out;

    __nv_bfloat16 *xh, *xl, *W3h, *W3l, *Woh, *Wol, *W1h, *W1l, *W2h, *W2l;
    __nv_bfloat16 *qkvh, *qkvl, *ah, *al, *hh, *hl, *fh, *fl;
    float *b3, *AW, *T0, *Hs;
    cudaGetSymbolAddress((void**)&xh, g_xh);   cudaGetSymbolAddress((void**)&xl, g_xl);
    cudaGetSymbolAddress((void**)&W3h, g_W3h); cudaGetSymbolAddress((void**)&W3l, g_W3l);
    cudaGetSymbolAddress((void**)&Woh, g_Woh); cudaGetSymbolAddress((void**)&Wol, g_Wol);
    cudaGetSymbolAddress((void**)&W1h, g_W1h); cudaGetSymbolAddress((void**)&W1l, g_W1l);
    cudaGetSymbolAddress((void**)&W2h, g_W2h); cudaGetSymbolAddress((void**)&W2l, g_W2l);
    cudaGetSymbolAddress((void**)&qkvh, g_qkvh); cudaGetSymbolAddress((void**)&qkvl, g_qkvl);
    cudaGetSymbolAddress((void**)&ah, g_ah);   cudaGetSymbolAddress((void**)&al, g_al);
    cudaGetSymbolAddress((void**)&hh, g_hh);   cudaGetSymbolAddress((void**)&hl, g_hl);
    cudaGetSymbolAddress((void**)&fh, g_fh);   cudaGetSymbolAddress((void**)&fl, g_fl);
    cudaGetSymbolAddress((void**)&b3, g_b3);
    cudaGetSymbolAddress((void**)&AW, g_aw);
    cudaGetSymbolAddress((void**)&T0, g_t0);
    cudaGetSymbolAddress((void**)&Hs, g_h);

    cudaFuncSetAttribute(mma_gemm<0, 0>, cudaFuncAttributeMaxDynamicSharedMemorySize, MMA_SMEM);
    cudaFuncSetAttribute(mma_gemm<0, 1>, cudaFuncAttributeMaxDynamicSharedMemorySize, MMA_SMEM);
    cudaFuncSetAttribute(mma_gemm<1, 1>, cudaFuncAttributeMaxDynamicSharedMemorySize, MMA_SMEM);
    cudaFuncSetAttribute(qk_scores, cudaFuncAttributeMaxDynamicSharedMemorySize, QK_SMEM);
    cudaFuncSetAttribute(av_mma, cudaFuncAttributeMaxDynamicSharedMemorySize, AV_SMEM);

    dim3 blk(256);
    dim3 tblk(32, 8);

    // operand prep
    split_act<<<(Mc * Ec / 2 + 255) / 256, blk>>>(x, xh, xl, Mc * Ec / 2);
    transpose_split<<<dim3(Ec / 32, Ec / 32), tblk>>>(wq_w, Ec, Ec, W3h, W3l, 0, Ec);
    transpose_split<<<dim3(Ec / 32, Ec / 32), tblk>>>(wk_w, Ec, Ec, W3h, W3l, Ec, Ec);
    transpose_split<<<dim3(Ec / 32, Ec / 32), tblk>>>(wv_w, Ec, Ec, W3h, W3l, 2 * Ec, Ec);
    transpose_split<<<dim3(Ec / 32, Ec / 32), tblk>>>(wo_w, Ec, Ec, Woh, Wol, 0, Ec);
    transpose_split<<<dim3(FFc / 32, Ec / 32), tblk>>>(ff1_w, Ec, FFc, W1h, W1l, 0, Ec);
    transpose_split<<<dim3(Ec / 32, FFc / 32), tblk>>>(ff2_w, FFc, Ec, W2h, W2l, 0, FFc);
    concat_bias<<<12, blk>>>(wq_b, wk_b, wv_b);
    pe_split<<<(256 * HDc + 255) / 256, blk>>>(pos_emb);

    // fused QKV projection -> bf16 hi/lo
    mma_gemm<0, 1><<<dim3(E3 / 128, Mc / 128), blk, MMA_SMEM>>>(
        xh, xl, W3h, W3l, b3, nullptr, qkvh, qkvl, Ec, E3);

    // per-head V^T (+pe^T) staging
    vt_build<<<dim3(SE / 32, 2, 128), tblk>>>();

    // fused scores: QK^T and q.pe in one HMMA GEMM
    qk_scores<<<dim3(6, 4, 128), blk, QK_SMEM>>>(AW);

    // softmax (+gather +bucket scatter), emits bf16 hi/lo aw_ext
    softmax_kernel<<<dim3(Sc, Hc, Bc), blk>>>(dist, dt);

    // attn = aw_ext @ vt^T  (HMMA)
    av_mma<<<dim3(4, 128), blk, AV_SMEM>>>();

    // output projection
    mma_gemm<0, 0><<<dim3(Ec / 128, Mc / 128), blk, MMA_SMEM>>>(
        ah, al, Woh, Wol, wo_b, T0, nullptr, nullptr, Ec, Ec);

    // h = LN(x + attn_out), emit hi/lo for FF1
    add_ln_kernel<1><<<Mc, blk>>>(x, T0, ln1_g, ln1_b, Hs, hh, hl);

    // FFN
    mma_gemm<1, 1><<<dim3(FFc / 128, Mc / 128), blk, MMA_SMEM>>>(
        hh, hl, W1h, W1l, ff1_b, nullptr, fh, fl, Ec, FFc);
    mma_gemm<0, 0><<<dim3(Ec / 128, Mc / 128), blk, MMA_SMEM>>>(
        fh, fl, W2h, W2l, ff2_b, T0, nullptr, nullptr, FFc, Ec);

    // out = LN(h + ffn)
    add_ln_kernel<0><<<Mc, blk>>>(Hs, T0, ln2_g, ln2_b, out, nullptr, nullptr);
}

// round 5
// speedup vs baseline: 2.0722x; 1.0748x over previous
#include <cuda_runtime.h>
#include <cuda_fp16.h>
#include <cstdint>
#include <math.h>

// Problem constants
constexpr int Bc  = 8;
constexpr int Sc  = 512;
constexpr int Ec  = 1024;
constexpr int Hc  = 16;
constexpr int HDc = 64;
constexpr int FFc = 4096;
constexpr int NEc = 129;           // 2P+1
constexpr int Mc  = Bc * Sc;       // 4096 rows
constexpr int E3  = 3 * Ec;        // 3072
constexpr int SE  = 672;           // extended score width: 512 + 129 + pad

// ---------------------------------------------------------------------------
// Scratch (device globals; no allocation allowed)
// ---------------------------------------------------------------------------
__device__ __align__(256) __half g_xh[Mc * Ec];
__device__ __align__(256) __half g_xl[Mc * Ec];
__device__ __align__(256) __half g_W3h[E3 * Ec];
__device__ __align__(256) __half g_W3l[E3 * Ec];
__device__ __align__(256) __half g_Woh[Ec * Ec];
__device__ __align__(256) __half g_Wol[Ec * Ec];
__device__ __align__(256) __half g_W1h[FFc * Ec];
__device__ __align__(256) __half g_W2h[Ec * FFc];
__device__ float g_b3[E3];
__device__ __align__(256) __half g_qkvh[Mc * E3];
__device__ __align__(256) __half g_qkvl[Mc * E3];
__device__ __align__(256) __half g_peh[256 * HDc];
__device__ __align__(256) __half g_pel[256 * HDc];
__device__ float g_aw[128 * Sc * SE];                  // fp32 scores
__device__ __align__(256) __half g_awh[128 * Sc * SE];
__device__ __align__(256) __half g_awl[128 * Sc * SE];
__device__ __align__(256) __half g_vth[128 * HDc * SE];
__device__ __align__(256) __half g_vtl[128 * HDc * SE];
__device__ __align__(256) __half g_ah[Mc * Ec];
__device__ __align__(256) __half g_al[Mc * Ec];
__device__ float g_t0[Mc * Ec];
__device__ float g_h[Mc * Ec];
__device__ __align__(256) __half g_hh[Mc * Ec];
__device__ __align__(256) __half g_hl[Mc * Ec];
__device__ __align__(256) __half g_fh[Mc * FFc];
__device__ __align__(256) __half g_fl[Mc * FFc];

// ---------------------------------------------------------------------------
// PTX helpers (sm_80-era: HMMA / ldmatrix / cp.async)
// ---------------------------------------------------------------------------
__device__ __forceinline__ uint32_t smem_u32(const void* p) {
    uint32_t a;
    asm("{ .reg .u64 t; cvta.to.shared.u64 t, %1; cvt.u32.u64 %0, t; }" : "=r"(a) : "l"(p));
    return a;
}
__device__ __forceinline__ void cpasync16(uint32_t dst, const void* src) {
    asm volatile("cp.async.cg.shared.global [%0], [%1], 16;" :: "r"(dst), "l"(src));
}
#define CP_COMMIT()  asm volatile("cp.async.commit_group;" ::: "memory")
#define CP_WAIT(n)   asm volatile("cp.async.wait_group %0;" :: "n"(n) : "memory")

__device__ __forceinline__ void ldsm4(uint32_t* r, uint32_t addr) {
    asm volatile("ldmatrix.sync.aligned.m8n8.x4.shared.b16 {%0,%1,%2,%3}, [%4];"
                 : "=r"(r[0]), "=r"(r[1]), "=r"(r[2]), "=r"(r[3]) : "r"(addr));
}
__device__ __forceinline__ void mma_f16(float* c, const uint32_t* a, const uint32_t* b) {
    asm volatile(
        "mma.sync.aligned.m16n8k16.row.col.f32.f16.f16.f32 "
        "{%0,%1,%2,%3}, {%4,%5,%6,%7}, {%8,%9}, {%0,%1,%2,%3};"
        : "+f"(c[0]), "+f"(c[1]), "+f"(c[2]), "+f"(c[3])
        : "r"(a[0]), "r"(a[1]), "r"(a[2]), "r"(a[3]), "r"(b[0]), "r"(b[1]));
}
__device__ __forceinline__ void split2(float v0, float v1, uint32_t& uh, uint32_t& ul) {
    const __half h0 = __float2half_rn(v0), h1 = __float2half_rn(v1);
    __half2 ph = __halves2half2(h0, h1);
    __half2 pl = __halves2half2(
        __float2half_rn(v0 - __half2float(h0)),
        __float2half_rn(v1 - __half2float(h1)));
    uh = *(uint32_t*)&ph; ul = *(uint32_t*)&pl;
}

// ---------------------------------------------------------------------------
// HMMA GEMM: C[M,N] = (Ah+Al)[M,K] @ (Bh[+Bl])[N,K]^T + bias
// PASSES==3: hi*hi + lo*hi + hi*lo.  PASSES==2: hi*hi + lo*hi (B hi only).
// 128x128 CTA tile, BK=32, 8 warps of 32x64, cp.async double buffer.
// ---------------------------------------------------------------------------
constexpr int LDSp  = 40;
constexpr int TILEB = 128 * LDSp * 2;
constexpr int BUFB  = 4 * TILEB;
constexpr int MMA_SMEM = 2 * BUFB;         // 81920 B

template<int RELU, int SPLIT, int PASSES>
__global__ void __launch_bounds__(256)
mma_gemm(const __half* __restrict__ Ah, const __half* __restrict__ Al,
         const __half* __restrict__ Bh, const __half* __restrict__ Bl,
         const float* __restrict__ bias, float* __restrict__ C,
         __half* __restrict__ Ch, __half* __restrict__ Cl,
         int K, int N)
{
    extern __shared__ char sm[];
    const uint32_t sbase = smem_u32(sm);
    const int tid = threadIdx.x;
    const int wid = tid >> 5, lane = tid & 31;
    const int wm = wid & 3, wn = wid >> 2;
    const int bm = blockIdx.y * 128, bn = blockIdx.x * 128;

    const int r0l = tid >> 2, sg = (tid & 3) << 3;

    auto load_chunk = [&](int kc) {
        const int buf = kc & 1;
        const uint32_t base = sbase + buf * BUFB;
        const int k0 = kc * 32;
        #pragma unroll
        for (int it = 0; it < 2; it++) {
            const int r = r0l + it * 64;
            const uint32_t dst = base + r * 80 + sg * 2;
            const size_t ao = (size_t)(bm + r) * K + k0 + sg;
            const size_t bo = (size_t)(bn + r) * K + k0 + sg;
            cpasync16(dst,             Ah + ao);
            cpasync16(dst + TILEB,     Al + ao);
            cpasync16(dst + 2 * TILEB, Bh + bo);
            if (PASSES == 3) cpasync16(dst + 3 * TILEB, Bl + bo);
        }
        CP_COMMIT();
    };

    float acc[2][8][4];
    #pragma unroll
    for (int mt = 0; mt < 2; mt++)
        #pragma unroll
        for (int nt = 0; nt < 8; nt++)
            #pragma unroll
            for (int i = 0; i < 4; i++) acc[mt][nt][i] = 0.f;

    uint32_t aF[2][2][4];
    uint32_t bF[8][2][2];

    const int a_row = wm * 32 + (lane & 15);
    const int a_kof = (lane >> 4) << 3;
    const int b_n   = wn * 64 + (lane & 7) + ((lane & 16) >> 1);
    const int b_kof = ((lane >> 3) & 1) << 3;

    auto loadA = [&](uint32_t tbase) {
        #pragma unroll
        for (int mt = 0; mt < 2; mt++)
            #pragma unroll
            for (int ks = 0; ks < 2; ks++)
                ldsm4(aF[mt][ks], tbase + (a_row + mt * 16) * 80 + (ks * 16 + a_kof) * 2);
    };
    auto loadB = [&](uint32_t tbase) {
        #pragma unroll
        for (int ntp = 0; ntp < 4; ntp++)
            #pragma unroll
            for (int ks = 0; ks < 2; ks++) {
                uint32_t t4[4];
                ldsm4(t4, tbase + (b_n + ntp * 16) * 80 + (ks * 16 + b_kof) * 2);
                bF[ntp * 2 + 0][ks][0] = t4[0]; bF[ntp * 2 + 0][ks][1] = t4[1];
                bF[ntp * 2 + 1][ks][0] = t4[2]; bF[ntp * 2 + 1][ks][1] = t4[3];
            }
    };
    auto mma_all = [&]() {
        #pragma unroll
        for (int ks = 0; ks < 2; ks++)
            #pragma unroll
            for (int mt = 0; mt < 2; mt++)
                #pragma unroll
                for (int nt = 0; nt < 8; nt++)
                    mma_f16(acc[mt][nt], aF[mt][ks], bF[nt][ks]);
    };

    const int nk = K / 32;
    load_chunk(0);
    for (int kc = 0; kc < nk; kc++) {
        if (kc + 1 < nk) { load_chunk(kc + 1); CP_WAIT(1); }
        else             { CP_WAIT(0); }
        __syncthreads();

        const uint32_t base = sbase + (kc & 1) * BUFB;
        loadA(base);
        loadB(base + 2 * TILEB);
        mma_all();                   // hi*hi
        loadA(base + TILEB);
        mma_all();                   // lo*hi
        if (PASSES == 3) {
            loadA(base);
            loadB(base + 3 * TILEB);
            mma_all();               // hi*lo
        }
        __syncthreads();
    }

    #pragma unroll
    for (int mt = 0; mt < 2; mt++) {
        #pragma unroll
        for (int nt = 0; nt < 8; nt++) {
            const int row = bm + wm * 32 + mt * 16 + (lane >> 2);
            const int col = bn + wn * 64 + nt * 8 + ((lane & 3) << 1);
            const float bi0 = bias[col], bi1 = bias[col + 1];
            float o00 = acc[mt][nt][0] + bi0, o01 = acc[mt][nt][1] + bi1;
            float o10 = acc[mt][nt][2] + bi0, o11 = acc[mt][nt][3] + bi1;
            if (RELU) {
                o00 = fmaxf(o00, 0.f); o01 = fmaxf(o01, 0.f);
                o10 = fmaxf(o10, 0.f); o11 = fmaxf(o11, 0.f);
            }
            const size_t i0 = (size_t)row * N + col;
            const size_t i1 = (size_t)(row + 8) * N + col;
            if (SPLIT) {
                uint32_t uh0, ul0, uh1, ul1;
                split2(o00, o01, uh0, ul0);
                split2(o10, o11, uh1, ul1);
                *(uint32_t*)(Ch + i0) = uh0;
                *(uint32_t*)(Ch + i1) = uh1;
                *(uint32_t*)(Cl + i0) = ul0;
                *(uint32_t*)(Cl + i1) = ul1;
            } else {
                *(float2*)(C + i0) = make_float2(o00, o01);
                *(float2*)(C + i1) = make_float2(o10, o11);
            }
        }
    }
}

// ---------------------------------------------------------------------------
// Fused scores GEMM (HMMA, 3-pass fp16): per (b,h):
//   AW[i, j]     = Q_h[i,:] . K_h[j,:]       (j < 512)
//   AW[i, 512+e] = Q_h[i,:] . pos_emb[e,:]   (e < 129; pad rows zero)
// ---------------------------------------------------------------------------
constexpr int QK_LDS = 72;
constexpr int QK_T   = 128 * QK_LDS * 2;
constexpr int QK_SMEM = 4 * QK_T;                  // 73728 B

__global__ void __launch_bounds__(256)
qk_scores(float* __restrict__ AW)
{
    extern __shared__ char sm[];
    const uint32_t sA = smem_u32(sm);
    const uint32_t sB = sA + 2 * QK_T;
    const int tid = threadIdx.x;
    const int wid = tid >> 5, lane = tid & 31;
    const int wm = wid & 3, wn = wid >> 2;
    const int bn = blockIdx.x * 128, bm = blockIdx.y * 128;
    const int bh = blockIdx.z, b = bh >> 4, h = bh & 15;

    {
        const int r0 = tid >> 3, sg = (tid & 7) << 3;
        #pragma unroll
        for (int it = 0; it < 4; it++) {
            const int r = r0 + it * 32;
            const uint32_t off = (r * QK_LDS + sg) * 2;
            const size_t ao = (size_t)(b * Sc + bm + r) * E3 + h * HDc + sg;
            cpasync16(sA + off,        g_qkvh + ao);
            cpasync16(sA + QK_T + off, g_qkvl + ao);
            const int gr = bn + r;
            const __half *bph, *bpl;
            if (gr < Sc) {
                const size_t bo = (size_t)(b * Sc + gr) * E3 + Ec + h * HDc + sg;
                bph = g_qkvh + bo; bpl = g_qkvl + bo;
            } else {
                const size_t bo = (size_t)(gr - Sc) * HDc + sg;
                bph = g_peh + bo;  bpl = g_pel + bo;
            }
            cpasync16(sB + off,        bph);
            cpasync16(sB + QK_T + off, bpl);
        }
        CP_COMMIT(); CP_WAIT(0);
        __syncthreads();
    }

    float acc[2][8][4];
    #pragma unroll
    for (int mt = 0; mt < 2; mt++)
        #pragma unroll
        for (int nt = 0; nt < 8; nt++)
            #pragma unroll
            for (int i = 0; i < 4; i++) acc[mt][nt][i] = 0.f;

    uint32_t aF[2][2][4], bF[8][2][2];
    const int a_row = wm * 32 + (lane & 15);
    const int a_kof = (lane >> 4) << 3;
    const int b_n   = wn * 64 + (lane & 7) + ((lane & 16) >> 1);
    const int b_kof = ((lane >> 3) & 1) << 3;

    auto loadA = [&](uint32_t tb, int k0) {
        #pragma unroll
        for (int mt = 0; mt < 2; mt++)
            #pragma unroll
            for (int ks = 0; ks < 2; ks++)
                ldsm4(aF[mt][ks], tb + ((a_row + mt * 16) * QK_LDS + k0 + ks * 16 + a_kof) * 2);
    };
    auto loadB = [&](uint32_t tb, int k0) {
        #pragma unroll
        for (int ntp = 0; ntp < 4; ntp++)
            #pragma unroll
            for (int ks = 0; ks < 2; ks++) {
                uint32_t t4[4];
                ldsm4(t4, tb + ((b_n + ntp * 16) * QK_LDS + k0 + ks * 16 + b_kof) * 2);
                bF[ntp * 2 + 0][ks][0] = t4[0]; bF[ntp * 2 + 0][ks][1] = t4[1];
                bF[ntp * 2 + 1][ks][0] = t4[2]; bF[ntp * 2 + 1][ks][1] = t4[3];
            }
    };
    auto mma_all = [&]() {
        #pragma unroll
        for (int ks = 0; ks < 2; ks++)
            #pragma unroll
            for (int mt = 0; mt < 2; mt++)
                #pragma unroll
                for (int nt = 0; nt < 8; nt++)
                    mma_f16(acc[mt][nt], aF[mt][ks], bF[nt][ks]);
    };

    #pragma unroll
    for (int kg = 0; kg < 2; kg++) {
        const int k0 = kg * 32;
        loadA(sA, k0);
        loadB(sB, k0);
        mma_all();
        loadA(sA + QK_T, k0);
        mma_all();
        loadA(sA, k0);
        loadB(sB + QK_T, k0);
        mma_all();
    }

    #pragma unroll
    for (int mt = 0; mt < 2; mt++) {
        #pragma unroll
        for (int nt = 0; nt < 8; nt++) {
            const int row = bm + wm * 32 + mt * 16 + (lane >> 2);
            const int col = bn + wn * 64 + nt * 8 + ((lane & 3) << 1);
            if (col < SE) {
                const size_t base = (size_t)(bh * Sc + row) * SE + col;
                *(float2*)(AW + base)             = make_float2(acc[mt][nt][0], acc[mt][nt][1]);
                *(float2*)(AW + base + 8ull * SE) = make_float2(acc[mt][nt][2], acc[mt][nt][3]);
            }
        }
    }
}

// ---------------------------------------------------------------------------
// Per-head V^T build
// ---------------------------------------------------------------------------
__global__ void vt_build()
{
    __shared__ __half th[32][33], tl[32][33];
    const int jt = blockIdx.x, dt = blockIdx.y, bh = blockIdx.z;
    const int b = bh >> 4, h = bh & 15;
    const int j0 = jt * 32, d0 = dt * 32;
    const int tx = threadIdx.x, ty = threadIdx.y;

    #pragma unroll
    for (int k = 0; k < 4; k++) {
        const int j = j0 + ty + k * 8;
        const int d = d0 + tx;
        __half vh, vl;
        if (j < Sc) {
            const size_t o = (size_t)(b * Sc + j) * E3 + 2 * Ec + h * HDc + d;
            vh = g_qkvh[o]; vl = g_qkvl[o];
        } else if (j < Sc + NEc) {
            const size_t o = (size_t)(j - Sc) * HDc + d;
            vh = g_peh[o]; vl = g_pel[o];
        } else {
            vh = __float2half_rn(0.f); vl = __float2half_rn(0.f);
        }
        th[ty + k * 8][tx] = vh;
        tl[ty + k * 8][tx] = vl;
    }
    __syncthreads();
    #pragma unroll
    for (int k = 0; k < 4; k++) {
        const int d = d0 + ty + k * 8;
        const int j = j0 + tx;
        const size_t o = (size_t)bh * HDc * SE + (size_t)d * SE + j;
        g_vth[o] = th[tx][ty + k * 8];
        g_vtl[o] = tl[tx][ty + k * 8];
    }
}

// ---------------------------------------------------------------------------
// AV GEMM (HMMA, 3-pass fp16)
// ---------------------------------------------------------------------------
constexpr int AV_AT = 128 * LDSp * 2;
constexpr int AV_BT = 64 * LDSp * 2;
constexpr int AV_BUF = 2 * AV_AT + 2 * AV_BT;
constexpr int AV_SMEM = 2 * AV_BUF;            // 61440

__global__ void __launch_bounds__(256)
av_mma()
{
    extern __shared__ char sm[];
    const uint32_t sbase = smem_u32(sm);
    const int tid = threadIdx.x;
    const int wid = tid >> 5, lane = tid & 31;
    const int bm = blockIdx.x * 128;
    const int bh = blockIdx.y, b = bh >> 4, h = bh & 15;

    auto load_chunk = [&](int kc) {
        const int buf = kc & 1;
        const uint32_t base = sbase + buf * AV_BUF;
        const int k0 = kc * 32;
        const int sg = (tid & 3) << 3;
        #pragma unroll
        for (int it = 0; it < 2; it++) {
            const int r = (tid >> 2) + it * 64;
            const uint32_t dst = base + r * 80 + sg * 2;
            const size_t ao = (size_t)(bh * Sc + bm + r) * SE + k0 + sg;
            cpasync16(dst,         g_awh + ao);
            cpasync16(dst + AV_AT, g_awl + ao);
        }
        {
            const int r = tid >> 2;
            if (r < 64) {
                const uint32_t dst = base + 2 * AV_AT + r * 80 + sg * 2;
                const size_t bo = (size_t)bh * HDc * SE + (size_t)r * SE + k0 + sg;
                cpasync16(dst,         g_vth + bo);
                cpasync16(dst + AV_BT, g_vtl + bo);
            }
        }
        CP_COMMIT();
    };

    float acc[8][4];
    #pragma unroll
    for (int nt = 0; nt < 8; nt++)
        #pragma unroll
        for (int i = 0; i < 4; i++) acc[nt][i] = 0.f;

    uint32_t aF[2][4], bF[8][2][2];
    const int a_row = wid * 16 + (lane & 15);
    const int a_kof = (lane >> 4) << 3;
    const int b_n   = (lane & 7) + ((lane & 16) >> 1);
    const int b_kof = ((lane >> 3) & 1) << 3;

    auto loadA = [&](uint32_t tb) {
        #pragma unroll
        for (int ks = 0; ks < 2; ks++)
            ldsm4(aF[ks], tb + (a_row * 80) + (ks * 16 + a_kof) * 2);
    };
    auto loadB = [&](uint32_t tb) {
        #pragma unroll
        for (int ntp = 0; ntp < 4; ntp++)
            #pragma unroll
            for (int ks = 0; ks < 2; ks++) {
                uint32_t t4[4];
                ldsm4(t4, tb + (b_n + ntp * 16) * 80 + (ks * 16 + b_kof) * 2);
                bF[ntp * 2 + 0][ks][0] = t4[0]; bF[ntp * 2 + 0][ks][1] = t4[1];
                bF[ntp * 2 + 1][ks][0] = t4[2]; bF[ntp * 2 + 1][ks][1] = t4[3];
            }
    };
    auto mma_all = [&]() {
        #pragma unroll
        for (int ks = 0; ks < 2; ks++)
            #pragma unroll
            for (int nt = 0; nt < 8; nt++)
                mma_f16(acc[nt], aF[ks], bF[nt][ks]);
    };

    const int nk = SE / 32;   // 21
    load_chunk(0);
    for (int kc = 0; kc < nk; kc++) {
        if (kc + 1 < nk) { load_chunk(kc + 1); CP_WAIT(1); }
        else             { CP_WAIT(0); }
        __syncthreads();
        const uint32_t base = sbase + (kc & 1) * AV_BUF;
        loadA(base);
        loadB(base + 2 * AV_AT);
        mma_all();
        loadA(base + AV_AT);
        mma_all();
        loadA(base);
        loadB(base + 2 * AV_AT + AV_BT);
        mma_all();
        __syncthreads();
    }

    #pragma unroll
    for (int nt = 0; nt < 8; nt++) {
        const int row = bm + wid * 16 + (lane >> 2);
        const int col = nt * 8 + ((lane & 3) << 1);
        const size_t i0 = (size_t)(b * Sc + row) * Ec + h * HDc + col;
        const size_t i1 = (size_t)(b * Sc + row + 8) * Ec + h * HDc + col;
        uint32_t uh0, ul0, uh1, ul1;
        split2(acc[nt][0], acc[nt][1], uh0, ul0);
        split2(acc[nt][2], acc[nt][3], uh1, ul1);
        *(uint32_t*)(g_ah + i0) = uh0;
        *(uint32_t*)(g_ah + i1) = uh1;
        *(uint32_t*)(g_al + i0) = ul0;
        *(uint32_t*)(g_al + i1) = ul1;
    }
}

// ---------------------------------------------------------------------------
// Elementwise prep kernels
// ---------------------------------------------------------------------------
__global__ void __launch_bounds__(256) split_act(
    const float* __restrict__ A, __half* __restrict__ hi,
    __half* __restrict__ lo, int n2)
{
    const int i = blockIdx.x * 256 + threadIdx.x;
    if (i >= n2) return;
    const float2 v = ((const float2*)A)[i];
    uint32_t uh, ul;
    split2(v.x, v.y, uh, ul);
    ((uint32_t*)hi)[i] = uh;
    ((uint32_t*)lo)[i] = ul;
}

template<int WITH_LO>
__global__ void __launch_bounds__(256) transpose_split(
    const float* __restrict__ W, int K, int N,
    __half* __restrict__ hi, __half* __restrict__ lo,
    int rowOff, int ldo)
{
    __shared__ float t[32][33];
    const int k0 = blockIdx.y * 32, n0 = blockIdx.x * 32;
    const int tx = threadIdx.x, ty = threadIdx.y;
    #pragma unroll
    for (int j = 0; j < 32; j += 8)
        t[ty + j][tx] = W[(size_t)(k0 + ty + j) * N + n0 + tx];
    __syncthreads();
    #pragma unroll
    for (int j = 0; j < 32; j += 8) {
        const float v = t[tx][ty + j];
        const size_t o = (size_t)(rowOff + n0 + ty + j) * ldo + k0 + tx;
        const __half h = __float2half_rn(v);
        hi[o] = h;
        if (WITH_LO) lo[o] = __float2half_rn(v - __half2float(h));
    }
}

__global__ void concat_bias(const float* a, const float* b, const float* c) {
    const int i = blockIdx.x * 256 + threadIdx.x;
    if (i < Ec) g_b3[i] = a[i];
    else if (i < 2 * Ec) g_b3[i] = b[i - Ec];
    else if (i < 3 * Ec) g_b3[i] = c[i - 2 * Ec];
}

__global__ void pe_split(const float* __restrict__ pos_emb) {
    const int i = blockIdx.x * 256 + threadIdx.x;
    if (i >= 256 * HDc) return;
    const int e = i >> 6;
    const float v = (e < NEc) ? pos_emb[i] : 0.f;
    const __half h = __float2half_rn(v);
    g_peh[i] = h;
    g_pel[i] = __float2half_rn(v - __half2float(h));
}

// ---------------------------------------------------------------------------
// Fused score assembly + softmax + bucket scatter; emits fp16 hi/lo aw_ext.
// ---------------------------------------------------------------------------
__global__ void __launch_bounds__(256) softmax_kernel(
    const float* __restrict__ dist, const int* __restrict__ dt)
{
    __shared__ float ssc[Sc];
    __shared__ int dts[Sc];
    __shared__ unsigned char es[Sc];
    __shared__ float bucket[NEc];
    __shared__ float red[8];

    const int i = blockIdx.x, h = blockIdx.y, b = blockIdx.z;
    const int tid = threadIdx.x;
    const int bh = b * Hc + h;
    const size_t rowbase = (size_t)(bh * Sc + i) * SE;
    const float* drow = dist + ((size_t)b * Sc + i) * Sc;

    for (int t = tid; t < Sc; t += 256) dts[t] = dt[b * Sc + t];
    for (int t = tid; t < NEc; t += 256) bucket[t] = 0.f;
    __syncthreads();

    const int dti = dts[i];
    float lmax = -1e30f;
    for (int t = tid; t < Sc; t += 256) {
        int rel = dts[t] - dti;
        rel = rel < -64 ? -64 : (rel > 64 ? 64 : rel);
        const int e = rel + 64;
        es[t] = (unsigned char)e;
        const float s = (g_aw[rowbase + t] + g_aw[rowbase + Sc + e]) * 0.125f + 0.6f * drow[t];
        ssc[t] = s;
        lmax = fmaxf(lmax, s);
    }
    #pragma unroll
    for (int o = 16; o; o >>= 1) lmax = fmaxf(lmax, __shfl_xor_sync(0xffffffffu, lmax, o));
    if ((tid & 31) == 0) red[tid >> 5] = lmax;
    __syncthreads();
    float mx = red[0];
    #pragma unroll
    for (int w = 1; w < 8; w++) mx = fmaxf(mx, red[w]);
    __syncthreads();

    float lsum = 0.f;
    for (int t = tid; t < Sc; t += 256) {
        const float p = __expf(ssc[t] - mx);
        ssc[t] = p;
        lsum += p;
    }
    #pragma unroll
    for (int o = 16; o; o >>= 1) lsum += __shfl_xor_sync(0xffffffffu, lsum, o);
    if ((tid & 31) == 0) red[tid >> 5] = lsum;
    __syncthreads();
    float tot = 0.f;
    #pragma unroll
    for (int w = 0; w < 8; w++) tot += red[w];
    const float inv = 1.f / tot;

    for (int t = tid; t < Sc; t += 256) {
        const float a = ssc[t] * inv;
        const __half hv = __float2half_rn(a);
        g_awh[rowbase + t] = hv;
        g_awl[rowbase + t] = __float2half_rn(a - __half2float(hv));
        atomicAdd(&bucket[es[t]], a);
    }
    __syncthreads();
    for (int t = tid; t < SE - Sc; t += 256) {
        const float v = (t < NEc) ? bucket[t] : 0.f;
        const __half hv = __float2half_rn(v);
        g_awh[rowbase + Sc + t] = hv;
        g_awl[rowbase + Sc + t] = __float2half_rn(v - __half2float(hv));
    }
}

// ---------------------------------------------------------------------------
// out = LayerNorm(X + R); optional fp16 hi/lo emission.
// ---------------------------------------------------------------------------
template<int SPLIT>
__global__ void __launch_bounds__(256) add_ln_kernel(
    const float* __restrict__ X, const float* __restrict__ Rr,
    const float* __restrict__ gam, const float* __restrict__ bet,
    float* __restrict__ Out, __half* __restrict__ Oh,
    __half* __restrict__ Ol)
{
    __shared__ float sh[Ec];
    __shared__ float red[8];
    const int row = blockIdx.x;
    const int tid = threadIdx.x;
    const float* xr = X + (size_t)row * Ec;
    const float* rr = Rr + (size_t)row * Ec;

    float lsum = 0.f;
    for (int t = tid; t < Ec; t += 256) {
        const float v = xr[t] + rr[t];
        sh[t] = v;
        lsum += v;
    }
    #pragma unroll
    for (int o = 16; o; o >>= 1) lsum += __shfl_xor_sync(0xffffffffu, lsum, o);
    if ((tid & 31) == 0) red[tid >> 5] = lsum;
    __syncthreads();
    float tot = 0.f;
    #pragma unroll
    for (int w = 0; w < 8; w++) tot += red[w];
    const float mu = tot * (1.f / Ec);
    __syncthreads();

    float lvar = 0.f;
    for (int t = tid; t < Ec; t += 256) {
        const float d = sh[t] - mu;
        lvar += d * d;
    }
    #pragma unroll
    for (int o = 16; o; o >>= 1) lvar += __shfl_xor_sync(0xffffffffu, lvar, o);
    if ((tid & 31) == 0) red[tid >> 5] = lvar;
    __syncthreads();
    float vtot = 0.f;
    #pragma unroll
    for (int w = 0; w < 8; w++) vtot += red[w];
    const float inv = rsqrtf(vtot * (1.f / Ec) + 1e-5f);

    float* orow = Out + (size_t)row * Ec;
    for (int t = tid; t < Ec; t += 256) {
        const float v = (sh[t] - mu) * inv * gam[t] + bet[t];
        orow[t] = v;
        if (SPLIT) {
            const size_t idx = (size_t)row * Ec + t;
            const __half hv = __float2half_rn(v);
            Oh[idx] = hv;
            Ol[idx] = __float2half_rn(v - __half2float(hv));
        }
    }
}

// ---------------------------------------------------------------------------
extern "C" void kernel_launch(void* const* d_in, const int* in_sizes, int n_in,
                              void* d_out, int out_size)
{
    (void)in_sizes; (void)n_in; (void)out_size;
    const float* x       = (const float*)d_in[0];
    const float* dist    = (const float*)d_in[1];
    const int*   dt      = (const int*)d_in[2];
    const float* pos_emb = (const float*)d_in[3];
    const float* wq_w = (const float*)d_in[4];
    const float* wq_b = (const float*)d_in[5];
    const float* wk_w = (const float*)d_in[6];
    const float* wk_b = (const float*)d_in[7];
    const float* wv_w = (const float*)d_in[8];
    const float* wv_b = (const float*)d_in[9];
    const float* wo_w = (const float*)d_in[10];
    const float* wo_b = (const float*)d_in[11];
    const float* ff1_w = (const float*)d_in[12];
    const float* ff1_b = (const float*)d_in[13];
    const float* ff2_w = (const float*)d_in[14];
    const float* ff2_b = (const float*)d_in[15];
    const float* ln1_g = (const float*)d_in[16];
    const float* ln1_b = (const float*)d_in[17];
    const float* ln2_g = (const float*)d_in[18];
    const float* ln2_b = (const float*)d_in[19];
    float* out = (float*)d_out;

    __half *xh, *xl, *W3h, *W3l, *Woh, *Wol, *W1h, *W2h;
    __half *qkvh, *qkvl, *ah, *al, *hh, *hl, *fh, *fl;
    float *b3, *AW, *T0, *Hs;
    cudaGetSymbolAddress((void**)&xh, g_xh);   cudaGetSymbolAddress((void**)&xl, g_xl);
    cudaGetSymbolAddress((void**)&W3h, g_W3h); cudaGetSymbolAddress((void**)&W3l, g_W3l);
    cudaGetSymbolAddress((void**)&Woh, g_Woh); cudaGetSymbolAddress((void**)&Wol, g_Wol);
    cudaGetSymbolAddress((void**)&W1h, g_W1h);
    cudaGetSymbolAddress((void**)&W2h, g_W2h);
    cudaGetSymbolAddress((void**)&qkvh, g_qkvh); cudaGetSymbolAddress((void**)&qkvl, g_qkvl);
    cudaGetSymbolAddress((void**)&ah, g_ah);   cudaGetSymbolAddress((void**)&al, g_al);
    cudaGetSymbolAddress((void**)&hh, g_hh);   cudaGetSymbolAddress((void**)&hl, g_hl);
    cudaGetSymbolAddress((void**)&fh, g_fh);   cudaGetSymbolAddress((void**)&fl, g_fl);
    cudaGetSymbolAddress((void**)&b3, g_b3);
    cudaGetSymbolAddress((void**)&AW, g_aw);
    cudaGetSymbolAddress((void**)&T0, g_t0);
    cudaGetSymbolAddress((void**)&Hs, g_h);

    cudaFuncSetAttribute(mma_gemm<0, 0, 3>, cudaFuncAttributeMaxDynamicSharedMemorySize, MMA_SMEM);
    cudaFuncSetAttribute(mma_gemm<0, 1, 3>, cudaFuncAttributeMaxDynamicSharedMemorySize, MMA_SMEM);
    cudaFuncSetAttribute(mma_gemm<1, 1, 2>, cudaFuncAttributeMaxDynamicSharedMemorySize, MMA_SMEM);
    cudaFuncSetAttribute(mma_gemm<0, 0, 2>, cudaFuncAttributeMaxDynamicSharedMemorySize, MMA_SMEM);
    cudaFuncSetAttribute(qk_scores, cudaFuncAttributeMaxDynamicSharedMemorySize, QK_SMEM);
    cudaFuncSetAttribute(av_mma, cudaFuncAttributeMaxDynamicSharedMemorySize, AV_SMEM);

    dim3 blk(256);
    dim3 tblk(32, 8);

    // operand prep
    split_act<<<(Mc * Ec / 2 + 255) / 256, blk>>>(x, xh, xl, Mc * Ec / 2);
    transpose_split<1><<<dim3(Ec / 32, Ec / 32), tblk>>>(wq_w, Ec, Ec, W3h, W3l, 0, Ec);
    transpose_split<1><<<dim3(Ec / 32, Ec / 32), tblk>>>(wk_w, Ec, Ec, W3h, W3l, Ec, Ec);
    transpose_split<1><<<dim3(Ec / 32, Ec / 32), tblk>>>(wv_w, Ec, Ec, W3h, W3l, 2 * Ec, Ec);
    transpose_split<1><<<dim3(Ec / 32, Ec / 32), tblk>>>(wo_w, Ec, Ec, Woh, Wol, 0, Ec);
    transpose_split<0><<<dim3(FFc / 32, Ec / 32), tblk>>>(ff1_w, Ec, FFc, W1h, nullptr, 0, Ec);
    transpose_split<0><<<dim3(Ec / 32, FFc / 32), tblk>>>(ff2_w, FFc, Ec, W2h, nullptr, 0, FFc);
    concat_bias<<<12, blk>>>(wq_b, wk_b, wv_b);
    pe_split<<<(256 * HDc + 255) / 256, blk>>>(pos_emb);

    // fused QKV projection -> fp16 hi/lo  (3-pass)
    mma_gemm<0, 1, 3><<<dim3(E3 / 128, Mc / 128), blk, MMA_SMEM>>>(
        xh, xl, W3h, W3l, b3, nullptr, qkvh, qkvl, Ec, E3);

    // per-head V^T (+pe^T) staging
    vt_build<<<dim3(SE / 32, 2, 128), tblk>>>();

    // fused scores: QK^T and q.pe in one HMMA GEMM (3-pass)
    qk_scores<<<dim3(6, 4, 128), blk, QK_SMEM>>>(AW);

    // softmax (+gather +bucket scatter)
    softmax_kernel<<<dim3(Sc, Hc, Bc), blk>>>(dist, dt);

    // attn = aw_ext @ vt^T  (3-pass)
    av_mma<<<dim3(4, 128), blk, AV_SMEM>>>();

    // output projection (3-pass)
    mma_gemm<0, 0, 3><<<dim3(Ec / 128, Mc / 128), blk, MMA_SMEM>>>(
        ah, al, Woh, Wol, wo_b, T0, nullptr, nullptr, Ec, Ec);

    // h = LN(x + attn_out), emit hi/lo for FF1
    add_ln_kernel<1><<<Mc, blk>>>(x, T0, ln1_g, ln1_b, Hs, hh, hl);

    // FFN: 2-pass fp16 (A split, B hi only)
    mma_gemm<1, 1, 2><<<dim3(FFc / 128, Mc / 128), blk, MMA_SMEM>>>(
        hh, hl, W1h, nullptr, ff1_b, nullptr, fh, fl, Ec, FFc);
    mma_gemm<0, 0, 2><<<dim3(Ec / 128, Mc / 128), blk, MMA_SMEM>>>(
        fh, fl, W2h, nullptr, ff2_b, T0, nullptr, nullptr, FFc, Ec);

    // out = LN(h + ffn)
    add_ln_kernel<0><<<Mc, blk>>>(Hs, T0, ln2_g, ln2_b, out, nullptr, nullptr);
}

// round 6
// speedup vs baseline: 2.1865x; 1.0551x over previous
#include <cuda_runtime.h>
#include <cuda_fp16.h>
#include <cstdint>
#include <math.h>

// Problem constants
constexpr int Bc  = 8;
constexpr int Sc  = 512;
constexpr int Ec  = 1024;
constexpr int Hc  = 16;
constexpr int HDc = 64;
constexpr int FFc = 4096;
constexpr int NEc = 129;           // 2P+1
constexpr int Mc  = Bc * Sc;       // 4096 rows
constexpr int E3  = 3 * Ec;        // 3072
constexpr int SE  = 672;           // extended score width: 512 + 129 + pad

// ---------------------------------------------------------------------------
// Scratch (device globals; no allocation allowed)
// ---------------------------------------------------------------------------
__device__ __align__(256) __half g_xh[Mc * Ec];
__device__ __align__(256) __half g_xl[Mc * Ec];
__device__ __align__(256) __half g_W3h[E3 * Ec];
__device__ __align__(256) __half g_Woh[Ec * Ec];
__device__ __align__(256) __half g_W1h[FFc * Ec];
__device__ __align__(256) __half g_W2h[Ec * FFc];
__device__ float g_b3[E3];
__device__ __align__(256) __half g_qkvh[Mc * E3];
__device__ __align__(256) __half g_qkvl[Mc * E3];
__device__ __align__(256) __half g_peh[256 * HDc];
__device__ float g_aw[128 * Sc * SE];                  // fp32 scores
__device__ __align__(256) __half g_awh[128 * Sc * SE];
__device__ __align__(256) __half g_awl[128 * Sc * SE];
__device__ __align__(256) __half g_vth[128 * HDc * SE];
__device__ __align__(256) __half g_ah[Mc * Ec];
__device__ __align__(256) __half g_al[Mc * Ec];
__device__ float g_t0[Mc * Ec];
__device__ float g_h[Mc * Ec];
__device__ __align__(256) __half g_hh[Mc * Ec];
__device__ __align__(256) __half g_hl[Mc * Ec];
__device__ __align__(256) __half g_fh[Mc * FFc];
__device__ __align__(256) __half g_fl[Mc * FFc];

// ---------------------------------------------------------------------------
// PTX helpers
// ---------------------------------------------------------------------------
__device__ __forceinline__ uint32_t smem_u32(const void* p) {
    uint32_t a;
    asm("{ .reg .u64 t; cvta.to.shared.u64 t, %1; cvt.u32.u64 %0, t; }" : "=r"(a) : "l"(p));
    return a;
}
__device__ __forceinline__ void cpasync16(uint32_t dst, const void* src) {
    asm volatile("cp.async.cg.shared.global [%0], [%1], 16;" :: "r"(dst), "l"(src));
}
#define CP_COMMIT()  asm volatile("cp.async.commit_group;" ::: "memory")
#define CP_WAIT(n)   asm volatile("cp.async.wait_group %0;" :: "n"(n) : "memory")

__device__ __forceinline__ void ldsm4(uint32_t* r, uint32_t addr) {
    asm volatile("ldmatrix.sync.aligned.m8n8.x4.shared.b16 {%0,%1,%2,%3}, [%4];"
                 : "=r"(r[0]), "=r"(r[1]), "=r"(r[2]), "=r"(r[3]) : "r"(addr));
}
__device__ __forceinline__ void mma_f16(float* c, const uint32_t* a, const uint32_t* b) {
    asm volatile(
        "mma.sync.aligned.m16n8k16.row.col.f32.f16.f16.f32 "
        "{%0,%1,%2,%3}, {%4,%5,%6,%7}, {%8,%9}, {%0,%1,%2,%3};"
        : "+f"(c[0]), "+f"(c[1]), "+f"(c[2]), "+f"(c[3])
        : "r"(a[0]), "r"(a[1]), "r"(a[2]), "r"(a[3]), "r"(b[0]), "r"(b[1]));
}
__device__ __forceinline__ void split2(float v0, float v1, uint32_t& uh, uint32_t& ul) {
    const __half h0 = __float2half_rn(v0), h1 = __float2half_rn(v1);
    __half2 ph = __halves2half2(h0, h1);
    __half2 pl = __halves2half2(
        __float2half_rn(v0 - __half2float(h0)),
        __float2half_rn(v1 - __half2float(h1)));
    uh = *(uint32_t*)&ph; ul = *(uint32_t*)&pl;
}

// ---------------------------------------------------------------------------
// HMMA GEMM (2-pass): C[M,N] = (Ah+Al)[M,K] @ Bh[N,K]^T + bias
// 128x128 CTA tile, BK=32, 8 warps of 32x64, cp.async double buffer.
// ---------------------------------------------------------------------------
constexpr int LDSp  = 40;
constexpr int TILEB = 128 * LDSp * 2;      // 10240
constexpr int BUFB  = 3 * TILEB;           // Ah,Al,Bh = 30720
constexpr int MMA_SMEM = 2 * BUFB;         // 61440 B

template<int RELU, int SPLIT>
__global__ void __launch_bounds__(256)
mma_gemm(const __half* __restrict__ Ah, const __half* __restrict__ Al,
         const __half* __restrict__ Bh,
         const float* __restrict__ bias, float* __restrict__ C,
         __half* __restrict__ Ch, __half* __restrict__ Cl,
         int K, int N)
{
    extern __shared__ char sm[];
    const uint32_t sbase = smem_u32(sm);
    const int tid = threadIdx.x;
    const int wid = tid >> 5, lane = tid & 31;
    const int wm = wid & 3, wn = wid >> 2;
    const int bm = blockIdx.y * 128, bn = blockIdx.x * 128;

    const int r0l = tid >> 2, sg = (tid & 3) << 3;

    auto load_chunk = [&](int kc) {
        const int buf = kc & 1;
        const uint32_t base = sbase + buf * BUFB;
        const int k0 = kc * 32;
        #pragma unroll
        for (int it = 0; it < 2; it++) {
            const int r = r0l + it * 64;
            const uint32_t dst = base + r * 80 + sg * 2;
            const size_t ao = (size_t)(bm + r) * K + k0 + sg;
            const size_t bo = (size_t)(bn + r) * K + k0 + sg;
            cpasync16(dst,             Ah + ao);
            cpasync16(dst + TILEB,     Al + ao);
            cpasync16(dst + 2 * TILEB, Bh + bo);
        }
        CP_COMMIT();
    };

    float acc[2][8][4];
    #pragma unroll
    for (int mt = 0; mt < 2; mt++)
        #pragma unroll
        for (int nt = 0; nt < 8; nt++)
            #pragma unroll
            for (int i = 0; i < 4; i++) acc[mt][nt][i] = 0.f;

    uint32_t aF[2][2][4];
    uint32_t bF[8][2][2];

    const int a_row = wm * 32 + (lane & 15);
    const int a_kof = (lane >> 4) << 3;
    const int b_n   = wn * 64 + (lane & 7) + ((lane & 16) >> 1);
    const int b_kof = ((lane >> 3) & 1) << 3;

    auto loadA = [&](uint32_t tbase) {
        #pragma unroll
        for (int mt = 0; mt < 2; mt++)
            #pragma unroll
            for (int ks = 0; ks < 2; ks++)
                ldsm4(aF[mt][ks], tbase + (a_row + mt * 16) * 80 + (ks * 16 + a_kof) * 2);
    };
    auto loadB = [&](uint32_t tbase) {
        #pragma unroll
        for (int ntp = 0; ntp < 4; ntp++)
            #pragma unroll
            for (int ks = 0; ks < 2; ks++) {
                uint32_t t4[4];
                ldsm4(t4, tbase + (b_n + ntp * 16) * 80 + (ks * 16 + b_kof) * 2);
                bF[ntp * 2 + 0][ks][0] = t4[0]; bF[ntp * 2 + 0][ks][1] = t4[1];
                bF[ntp * 2 + 1][ks][0] = t4[2]; bF[ntp * 2 + 1][ks][1] = t4[3];
            }
    };
    auto mma_all = [&]() {
        #pragma unroll
        for (int ks = 0; ks < 2; ks++)
            #pragma unroll
            for (int mt = 0; mt < 2; mt++)
                #pragma unroll
                for (int nt = 0; nt < 8; nt++)
                    mma_f16(acc[mt][nt], aF[mt][ks], bF[nt][ks]);
    };

    const int nk = K / 32;
    load_chunk(0);
    for (int kc = 0; kc < nk; kc++) {
        if (kc + 1 < nk) { load_chunk(kc + 1); CP_WAIT(1); }
        else             { CP_WAIT(0); }
        __syncthreads();

        const uint32_t base = sbase + (kc & 1) * BUFB;
        loadA(base);
        loadB(base + 2 * TILEB);
        mma_all();                   // hi*B
        loadA(base + TILEB);
        mma_all();                   // lo*B
        __syncthreads();
    }

    #pragma unroll
    for (int mt = 0; mt < 2; mt++) {
        #pragma unroll
        for (int nt = 0; nt < 8; nt++) {
            const int row = bm + wm * 32 + mt * 16 + (lane >> 2);
            const int col = bn + wn * 64 + nt * 8 + ((lane & 3) << 1);
            const float bi0 = bias[col], bi1 = bias[col + 1];
            float o00 = acc[mt][nt][0] + bi0, o01 = acc[mt][nt][1] + bi1;
            float o10 = acc[mt][nt][2] + bi0, o11 = acc[mt][nt][3] + bi1;
            if (RELU) {
                o00 = fmaxf(o00, 0.f); o01 = fmaxf(o01, 0.f);
                o10 = fmaxf(o10, 0.f); o11 = fmaxf(o11, 0.f);
            }
            const size_t i0 = (size_t)row * N + col;
            const size_t i1 = (size_t)(row + 8) * N + col;
            if (SPLIT) {
                uint32_t uh0, ul0, uh1, ul1;
                split2(o00, o01, uh0, ul0);
                split2(o10, o11, uh1, ul1);
                *(uint32_t*)(Ch + i0) = uh0;
                *(uint32_t*)(Ch + i1) = uh1;
                *(uint32_t*)(Cl + i0) = ul0;
                *(uint32_t*)(Cl + i1) = ul1;
            } else {
                *(float2*)(C + i0) = make_float2(o00, o01);
                *(float2*)(C + i1) = make_float2(o10, o11);
            }
        }
    }
}

// ---------------------------------------------------------------------------
// Fused scores GEMM (HMMA, 2-pass): per (b,h):
//   AW[i, j]     = Q_h[i,:] . K_h[j,:]       (j < 512)
//   AW[i, 512+e] = Q_h[i,:] . pos_emb[e,:]   (e < 129; pad rows zero)
// A = Q hi/lo, B = K/pe hi only.
// ---------------------------------------------------------------------------
constexpr int QK_LDS = 72;
constexpr int QK_T   = 128 * QK_LDS * 2;     // 18432
constexpr int QK_SMEM = 3 * QK_T;            // 55296 B

__global__ void __launch_bounds__(256)
qk_scores(float* __restrict__ AW)
{
    extern __shared__ char sm[];
    const uint32_t sA = smem_u32(sm);
    const uint32_t sB = sA + 2 * QK_T;
    const int tid = threadIdx.x;
    const int wid = tid >> 5, lane = tid & 31;
    const int wm = wid & 3, wn = wid >> 2;
    const int bn = blockIdx.x * 128, bm = blockIdx.y * 128;
    const int bh = blockIdx.z, b = bh >> 4, h = bh & 15;

    {
        const int r0 = tid >> 3, sg = (tid & 7) << 3;
        #pragma unroll
        for (int it = 0; it < 4; it++) {
            const int r = r0 + it * 32;
            const uint32_t off = (r * QK_LDS + sg) * 2;
            const size_t ao = (size_t)(b * Sc + bm + r) * E3 + h * HDc + sg;
            cpasync16(sA + off,        g_qkvh + ao);
            cpasync16(sA + QK_T + off, g_qkvl + ao);
            const int gr = bn + r;
            const __half* bph;
            if (gr < Sc) {
                bph = g_qkvh + (size_t)(b * Sc + gr) * E3 + Ec + h * HDc + sg;
            } else {
                bph = g_peh + (size_t)(gr - Sc) * HDc + sg;
            }
            cpasync16(sB + off, bph);
        }
        CP_COMMIT(); CP_WAIT(0);
        __syncthreads();
    }

    float acc[2][8][4];
    #pragma unroll
    for (int mt = 0; mt < 2; mt++)
        #pragma unroll
        for (int nt = 0; nt < 8; nt++)
            #pragma unroll
            for (int i = 0; i < 4; i++) acc[mt][nt][i] = 0.f;

    uint32_t aF[2][2][4], bF[8][2][2];
    const int a_row = wm * 32 + (lane & 15);
    const int a_kof = (lane >> 4) << 3;
    const int b_n   = wn * 64 + (lane & 7) + ((lane & 16) >> 1);
    const int b_kof = ((lane >> 3) & 1) << 3;

    auto loadA = [&](uint32_t tb, int k0) {
        #pragma unroll
        for (int mt = 0; mt < 2; mt++)
            #pragma unroll
            for (int ks = 0; ks < 2; ks++)
                ldsm4(aF[mt][ks], tb + ((a_row + mt * 16) * QK_LDS + k0 + ks * 16 + a_kof) * 2);
    };
    auto loadB = [&](uint32_t tb, int k0) {
        #pragma unroll
        for (int ntp = 0; ntp < 4; ntp++)
            #pragma unroll
            for (int ks = 0; ks < 2; ks++) {
                uint32_t t4[4];
                ldsm4(t4, tb + ((b_n + ntp * 16) * QK_LDS + k0 + ks * 16 + b_kof) * 2);
                bF[ntp * 2 + 0][ks][0] = t4[0]; bF[ntp * 2 + 0][ks][1] = t4[1];
                bF[ntp * 2 + 1][ks][0] = t4[2]; bF[ntp * 2 + 1][ks][1] = t4[3];
            }
    };
    auto mma_all = [&]() {
        #pragma unroll
        for (int ks = 0; ks < 2; ks++)
            #pragma unroll
            for (int mt = 0; mt < 2; mt++)
                #pragma unroll
                for (int nt = 0; nt < 8; nt++)
                    mma_f16(acc[mt][nt], aF[mt][ks], bF[nt][ks]);
    };

    #pragma unroll
    for (int kg = 0; kg < 2; kg++) {
        const int k0 = kg * 32;
        loadA(sA, k0);
        loadB(sB, k0);
        mma_all();
        loadA(sA + QK_T, k0);
        mma_all();
    }

    #pragma unroll
    for (int mt = 0; mt < 2; mt++) {
        #pragma unroll
        for (int nt = 0; nt < 8; nt++) {
            const int row = bm + wm * 32 + mt * 16 + (lane >> 2);
            const int col = bn + wn * 64 + nt * 8 + ((lane & 3) << 1);
            if (col < SE) {
                const size_t base = (size_t)(bh * Sc + row) * SE + col;
                *(float2*)(AW + base)             = make_float2(acc[mt][nt][0], acc[mt][nt][1]);
                *(float2*)(AW + base + 8ull * SE) = make_float2(acc[mt][nt][2], acc[mt][nt][3]);
            }
        }
    }
}

// ---------------------------------------------------------------------------
// Per-head V^T build (hi only)
// ---------------------------------------------------------------------------
__global__ void vt_build()
{
    __shared__ __half th[32][33];
    const int jt = blockIdx.x, dt = blockIdx.y, bh = blockIdx.z;
    const int b = bh >> 4, h = bh & 15;
    const int j0 = jt * 32, d0 = dt * 32;
    const int tx = threadIdx.x, ty = threadIdx.y;

    #pragma unroll
    for (int k = 0; k < 4; k++) {
        const int j = j0 + ty + k * 8;
        const int d = d0 + tx;
        __half vh;
        if (j < Sc) {
            vh = g_qkvh[(size_t)(b * Sc + j) * E3 + 2 * Ec + h * HDc + d];
        } else if (j < Sc + NEc) {
            vh = g_peh[(size_t)(j - Sc) * HDc + d];
        } else {
            vh = __float2half_rn(0.f);
        }
        th[ty + k * 8][tx] = vh;
    }
    __syncthreads();
    #pragma unroll
    for (int k = 0; k < 4; k++) {
        const int d = d0 + ty + k * 8;
        const int j = j0 + tx;
        g_vth[(size_t)bh * HDc * SE + (size_t)d * SE + j] = th[tx][ty + k * 8];
    }
}

// ---------------------------------------------------------------------------
// AV GEMM (HMMA, 2-pass): A = aw hi/lo, B = vt hi only
// ---------------------------------------------------------------------------
constexpr int AV_AT = 128 * LDSp * 2;          // 10240
constexpr int AV_BT = 64 * LDSp * 2;           // 5120
constexpr int AV_BUF = 2 * AV_AT + AV_BT;      // 25600
constexpr int AV_SMEM = 2 * AV_BUF;            // 51200

__global__ void __launch_bounds__(256)
av_mma()
{
    extern __shared__ char sm[];
    const uint32_t sbase = smem_u32(sm);
    const int tid = threadIdx.x;
    const int wid = tid >> 5, lane = tid & 31;
    const int bm = blockIdx.x * 128;
    const int bh = blockIdx.y, b = bh >> 4, h = bh & 15;

    auto load_chunk = [&](int kc) {
        const int buf = kc & 1;
        const uint32_t base = sbase + buf * AV_BUF;
        const int k0 = kc * 32;
        const int sg = (tid & 3) << 3;
        #pragma unroll
        for (int it = 0; it < 2; it++) {
            const int r = (tid >> 2) + it * 64;
            const uint32_t dst = base + r * 80 + sg * 2;
            const size_t ao = (size_t)(bh * Sc + bm + r) * SE + k0 + sg;
            cpasync16(dst,         g_awh + ao);
            cpasync16(dst + AV_AT, g_awl + ao);
        }
        {
            const int r = tid >> 2;
            if (r < 64) {
                const uint32_t dst = base + 2 * AV_AT + r * 80 + sg * 2;
                cpasync16(dst, g_vth + (size_t)bh * HDc * SE + (size_t)r * SE + k0 + sg);
            }
        }
        CP_COMMIT();
    };

    float acc[8][4];
    #pragma unroll
    for (int nt = 0; nt < 8; nt++)
        #pragma unroll
        for (int i = 0; i < 4; i++) acc[nt][i] = 0.f;

    uint32_t aF[2][4], bF[8][2][2];
    const int a_row = wid * 16 + (lane & 15);
    const int a_kof = (lane >> 4) << 3;
    const int b_n   = (lane & 7) + ((lane & 16) >> 1);
    const int b_kof = ((lane >> 3) & 1) << 3;

    auto loadA = [&](uint32_t tb) {
        #pragma unroll
        for (int ks = 0; ks < 2; ks++)
            ldsm4(aF[ks], tb + (a_row * 80) + (ks * 16 + a_kof) * 2);
    };
    auto loadB = [&](uint32_t tb) {
        #pragma unroll
        for (int ntp = 0; ntp < 4; ntp++)
            #pragma unroll
            for (int ks = 0; ks < 2; ks++) {
                uint32_t t4[4];
                ldsm4(t4, tb + (b_n + ntp * 16) * 80 + (ks * 16 + b_kof) * 2);
                bF[ntp * 2 + 0][ks][0] = t4[0]; bF[ntp * 2 + 0][ks][1] = t4[1];
                bF[ntp * 2 + 1][ks][0] = t4[2]; bF[ntp * 2 + 1][ks][1] = t4[3];
            }
    };
    auto mma_all = [&]() {
        #pragma unroll
        for (int ks = 0; ks < 2; ks++)
            #pragma unroll
            for (int nt = 0; nt < 8; nt++)
                mma_f16(acc[nt], aF[ks], bF[nt][ks]);
    };

    const int nk = SE / 32;   // 21
    load_chunk(0);
    for (int kc = 0; kc < nk; kc++) {
        if (kc + 1 < nk) { load_chunk(kc + 1); CP_WAIT(1); }
        else             { CP_WAIT(0); }
        __syncthreads();
        const uint32_t base = sbase + (kc & 1) * AV_BUF;
        loadA(base);
        loadB(base + 2 * AV_AT);
        mma_all();
        loadA(base + AV_AT);
        mma_all();
        __syncthreads();
    }

    #pragma unroll
    for (int nt = 0; nt < 8; nt++) {
        const int row = bm + wid * 16 + (lane >> 2);
        const int col = nt * 8 + ((lane & 3) << 1);
        const size_t i0 = (size_t)(b * Sc + row) * Ec + h * HDc + col;
        const size_t i1 = (size_t)(b * Sc + row + 8) * Ec + h * HDc + col;
        uint32_t uh0, ul0, uh1, ul1;
        split2(acc[nt][0], acc[nt][1], uh0, ul0);
        split2(acc[nt][2], acc[nt][3], uh1, ul1);
        *(uint32_t*)(g_ah + i0) = uh0;
        *(uint32_t*)(g_ah + i1) = uh1;
        *(uint32_t*)(g_al + i0) = ul0;
        *(uint32_t*)(g_al + i1) = ul1;
    }
}

// ---------------------------------------------------------------------------
// Elementwise prep kernels
// ---------------------------------------------------------------------------
__global__ void __launch_bounds__(256) split_act(
    const float* __restrict__ A, __half* __restrict__ hi,
    __half* __restrict__ lo, int n2)
{
    const int i = blockIdx.x * 256 + threadIdx.x;
    if (i >= n2) return;
    const float2 v = ((const float2*)A)[i];
    uint32_t uh, ul;
    split2(v.x, v.y, uh, ul);
    ((uint32_t*)hi)[i] = uh;
    ((uint32_t*)lo)[i] = ul;
}

__global__ void __launch_bounds__(256) transpose_round(
    const float* __restrict__ W, int K, int N,
    __half* __restrict__ hi, int rowOff, int ldo)
{
    __shared__ float t[32][33];
    const int k0 = blockIdx.y * 32, n0 = blockIdx.x * 32;
    const int tx = threadIdx.x, ty = threadIdx.y;
    #pragma unroll
    for (int j = 0; j < 32; j += 8)
        t[ty + j][tx] = W[(size_t)(k0 + ty + j) * N + n0 + tx];
    __syncthreads();
    #pragma unroll
    for (int j = 0; j < 32; j += 8) {
        const float v = t[tx][ty + j];
        hi[(size_t)(rowOff + n0 + ty + j) * ldo + k0 + tx] = __float2half_rn(v);
    }
}

__global__ void concat_bias(const float* a, const float* b, const float* c) {
    const int i = blockIdx.x * 256 + threadIdx.x;
    if (i < Ec) g_b3[i] = a[i];
    else if (i < 2 * Ec) g_b3[i] = b[i - Ec];
    else if (i < 3 * Ec) g_b3[i] = c[i - 2 * Ec];
}

__global__ void pe_round(const float* __restrict__ pos_emb) {
    const int i = blockIdx.x * 256 + threadIdx.x;
    if (i >= 256 * HDc) return;
    const int e = i >> 6;
    const float v = (e < NEc) ? pos_emb[i] : 0.f;
    g_peh[i] = __float2half_rn(v);
}

// ---------------------------------------------------------------------------
// Fused score assembly + softmax + bucket scatter; emits fp16 hi/lo aw_ext.
// ---------------------------------------------------------------------------
__global__ void __launch_bounds__(256) softmax_kernel(
    const float* __restrict__ dist, const int* __restrict__ dt)
{
    __shared__ float ssc[Sc];
    __shared__ int dts[Sc];
    __shared__ unsigned char es[Sc];
    __shared__ float bucket[NEc];
    __shared__ float red[8];

    const int i = blockIdx.x, h = blockIdx.y, b = blockIdx.z;
    const int tid = threadIdx.x;
    const int bh = b * Hc + h;
    const size_t rowbase = (size_t)(bh * Sc + i) * SE;
    const float* drow = dist + ((size_t)b * Sc + i) * Sc;

    for (int t = tid; t < Sc; t += 256) dts[t] = dt[b * Sc + t];
    for (int t = tid; t < NEc; t += 256) bucket[t] = 0.f;
    __syncthreads();

    const int dti = dts[i];
    float lmax = -1e30f;
    for (int t = tid; t < Sc; t += 256) {
        int rel = dts[t] - dti;
        rel = rel < -64 ? -64 : (rel > 64 ? 64 : rel);
        const int e = rel + 64;
        es[t] = (unsigned char)e;
        const float s = (g_aw[rowbase + t] + g_aw[rowbase + Sc + e]) * 0.125f + 0.6f * drow[t];
        ssc[t] = s;
        lmax = fmaxf(lmax, s);
    }
    #pragma unroll
    for (int o = 16; o; o >>= 1) lmax = fmaxf(lmax, __shfl_xor_sync(0xffffffffu, lmax, o));
    if ((tid & 31) == 0) red[tid >> 5] = lmax;
    __syncthreads();
    float mx = red[0];
    #pragma unroll
    for (int w = 1; w < 8; w++) mx = fmaxf(mx, red[w]);
    __syncthreads();

    float lsum = 0.f;
    for (int t = tid; t < Sc; t += 256) {
        const float p = __expf(ssc[t] - mx);
        ssc[t] = p;
        lsum += p;
    }
    #pragma unroll
    for (int o = 16; o; o >>= 1) lsum += __shfl_xor_sync(0xffffffffu, lsum, o);
    if ((tid & 31) == 0) red[tid >> 5] = lsum;
    __syncthreads();
    float tot = 0.f;
    #pragma unroll
    for (int w = 0; w < 8; w++) tot += red[w];
    const float inv = 1.f / tot;

    for (int t = tid; t < Sc; t += 256) {
        const float a = ssc[t] * inv;
        const __half hv = __float2half_rn(a);
        g_awh[rowbase + t] = hv;
        g_awl[rowbase + t] = __float2half_rn(a - __half2float(hv));
        atomicAdd(&bucket[es[t]], a);
    }
    __syncthreads();
    for (int t = tid; t < SE - Sc; t += 256) {
        const float v = (t < NEc) ? bucket[t] : 0.f;
        const __half hv = __float2half_rn(v);
        g_awh[rowbase + Sc + t] = hv;
        g_awl[rowbase + Sc + t] = __float2half_rn(v - __half2float(hv));
    }
}

// ---------------------------------------------------------------------------
// out = LayerNorm(X + R); optional fp16 hi/lo emission.
// ---------------------------------------------------------------------------
template<int SPLIT>
__global__ void __launch_bounds__(256) add_ln_kernel(
    const float* __restrict__ X, const float* __restrict__ Rr,
    const float* __restrict__ gam, const float* __restrict__ bet,
    float* __restrict__ Out, __half* __restrict__ Oh,
    __half* __restrict__ Ol)
{
    __shared__ float sh[Ec];
    __shared__ float red[8];
    const int row = blockIdx.x;
    const int tid = threadIdx.x;
    const float* xr = X + (size_t)row * Ec;
    const float* rr = Rr + (size_t)row * Ec;

    float lsum = 0.f;
    for (int t = tid; t < Ec; t += 256) {
        const float v = xr[t] + rr[t];
        sh[t] = v;
        lsum += v;
    }
    #pragma unroll
    for (int o = 16; o; o >>= 1) lsum += __shfl_xor_sync(0xffffffffu, lsum, o);
    if ((tid & 31) == 0) red[tid >> 5] = lsum;
    __syncthreads();
    float tot = 0.f;
    #pragma unroll
    for (int w = 0; w < 8; w++) tot += red[w];
    const float mu = tot * (1.f / Ec);
    __syncthreads();

    float lvar = 0.f;
    for (int t = tid; t < Ec; t += 256) {
        const float d = sh[t] - mu;
        lvar += d * d;
    }
    #pragma unroll
    for (int o = 16; o; o >>= 1) lvar += __shfl_xor_sync(0xffffffffu, lvar, o);
    if ((tid & 31) == 0) red[tid >> 5] = lvar;
    __syncthreads();
    float vtot = 0.f;
    #pragma unroll
    for (int w = 0; w < 8; w++) vtot += red[w];
    const float inv = rsqrtf(vtot * (1.f / Ec) + 1e-5f);

    float* orow = Out + (size_t)row * Ec;
    for (int t = tid; t < Ec; t += 256) {
        const float v = (sh[t] - mu) * inv * gam[t] + bet[t];
        orow[t] = v;
        if (SPLIT) {
            const size_t idx = (size_t)row * Ec + t;
            const __half hv = __float2half_rn(v);
            Oh[idx] = hv;
            Ol[idx] = __float2half_rn(v - __half2float(hv));
        }
    }
}

// ---------------------------------------------------------------------------
extern "C" void kernel_launch(void* const* d_in, const int* in_sizes, int n_in,
                              void* d_out, int out_size)
{
    (void)in_sizes; (void)n_in; (void)out_size;
    const float* x       = (const float*)d_in[0];
    const float* dist    = (const float*)d_in[1];
    const int*   dt      = (const int*)d_in[2];
    const float* pos_emb = (const float*)d_in[3];
    const float* wq_w = (const float*)d_in[4];
    const float* wq_b = (const float*)d_in[5];
    const float* wk_w = (const float*)d_in[6];
    const float* wk_b = (const float*)d_in[7];
    const float* wv_w = (const float*)d_in[8];
    const float* wv_b = (const float*)d_in[9];
    const float* wo_w = (const float*)d_in[10];
    const float* wo_b = (const float*)d_in[11];
    const float* ff1_w = (const float*)d_in[12];
    const float* ff1_b = (const float*)d_in[13];
    const float* ff2_w = (const float*)d_in[14];
    const float* ff2_b = (const float*)d_in[15];
    const float* ln1_g = (const float*)d_in[16];
    const float* ln1_b = (const float*)d_in[17];
    const float* ln2_g = (const float*)d_in[18];
    const float* ln2_b = (const float*)d_in[19];
    float* out = (float*)d_out;

    __half *xh, *xl, *W3h, *Woh, *W1h, *W2h;
    __half *qkvh, *qkvl, *ah, *al, *hh, *hl, *fh, *fl;
    float *b3, *AW, *T0, *Hs;
    cudaGetSymbolAddress((void**)&xh, g_xh);   cudaGetSymbolAddress((void**)&xl, g_xl);
    cudaGetSymbolAddress((void**)&W3h, g_W3h);
    cudaGetSymbolAddress((void**)&Woh, g_Woh);
    cudaGetSymbolAddress((void**)&W1h, g_W1h);
    cudaGetSymbolAddress((void**)&W2h, g_W2h);
    cudaGetSymbolAddress((void**)&qkvh, g_qkvh); cudaGetSymbolAddress((void**)&qkvl, g_qkvl);
    cudaGetSymbolAddress((void**)&ah, g_ah);   cudaGetSymbolAddress((void**)&al, g_al);
    cudaGetSymbolAddress((void**)&hh, g_hh);   cudaGetSymbolAddress((void**)&hl, g_hl);
    cudaGetSymbolAddress((void**)&fh, g_fh);   cudaGetSymbolAddress((void**)&fl, g_fl);
    cudaGetSymbolAddress((void**)&b3, g_b3);
    cudaGetSymbolAddress((void**)&AW, g_aw);
    cudaGetSymbolAddress((void**)&T0, g_t0);
    cudaGetSymbolAddress((void**)&Hs, g_h);

    cudaFuncSetAttribute(mma_gemm<0, 0>, cudaFuncAttributeMaxDynamicSharedMemorySize, MMA_SMEM);
    cudaFuncSetAttribute(mma_gemm<0, 1>, cudaFuncAttributeMaxDynamicSharedMemorySize, MMA_SMEM);
    cudaFuncSetAttribute(mma_gemm<1, 1>, cudaFuncAttributeMaxDynamicSharedMemorySize, MMA_SMEM);
    cudaFuncSetAttribute(qk_scores, cudaFuncAttributeMaxDynamicSharedMemorySize, QK_SMEM);
    cudaFuncSetAttribute(av_mma, cudaFuncAttributeMaxDynamicSharedMemorySize, AV_SMEM);

    dim3 blk(256);
    dim3 tblk(32, 8);

    // operand prep (weights: fp16 hi only)
    split_act<<<(Mc * Ec / 2 + 255) / 256, blk>>>(x, xh, xl, Mc * Ec / 2);
    transpose_round<<<dim3(Ec / 32, Ec / 32), tblk>>>(wq_w, Ec, Ec, W3h, 0, Ec);
    transpose_round<<<dim3(Ec / 32, Ec / 32), tblk>>>(wk_w, Ec, Ec, W3h, Ec, Ec);
    transpose_round<<<dim3(Ec / 32, Ec / 32), tblk>>>(wv_w, Ec, Ec, W3h, 2 * Ec, Ec);
    transpose_round<<<dim3(Ec / 32, Ec / 32), tblk>>>(wo_w, Ec, Ec, Woh, 0, Ec);
    transpose_round<<<dim3(FFc / 32, Ec / 32), tblk>>>(ff1_w, Ec, FFc, W1h, 0, Ec);
    transpose_round<<<dim3(Ec / 32, FFc / 32), tblk>>>(ff2_w, FFc, Ec, W2h, 0, FFc);
    concat_bias<<<12, blk>>>(wq_b, wk_b, wv_b);
    pe_round<<<(256 * HDc + 255) / 256, blk>>>(pos_emb);

    // fused QKV projection -> fp16 hi/lo (2-pass)
    mma_gemm<0, 1><<<dim3(E3 / 128, Mc / 128), blk, MMA_SMEM>>>(
        xh, xl, W3h, b3, nullptr, qkvh, qkvl, Ec, E3);

    // per-head V^T (+pe^T) staging (hi only)
    vt_build<<<dim3(SE / 32, 2, 128), tblk>>>();

    // fused scores: QK^T and q.pe in one HMMA GEMM (2-pass)
    qk_scores<<<dim3(6, 4, 128), blk, QK_SMEM>>>(AW);

    // softmax (+gather +bucket scatter)
    softmax_kernel<<<dim3(Sc, Hc, Bc), blk>>>(dist, dt);

    // attn = aw_ext @ vt^T (2-pass)
    av_mma<<<dim3(4, 128), blk, AV_SMEM>>>();

    // output projection (2-pass)
    mma_gemm<0, 0><<<dim3(Ec / 128, Mc / 128), blk, MMA_SMEM>>>(
        ah, al, Woh, wo_b, T0, nullptr, nullptr, Ec, Ec);

    // h = LN(x + attn_out), emit hi/lo for FF1
    add_ln_kernel<1><<<Mc, blk>>>(x, T0, ln1_g, ln1_b, Hs, hh, hl);

    // FFN (2-pass)
    mma_gemm<1, 1><<<dim3(FFc / 128, Mc / 128), blk, MMA_SMEM>>>(
        hh, hl, W1h, ff1_b, nullptr, fh, fl, Ec, FFc);
    mma_gemm<0, 0><<<dim3(Ec / 128, Mc / 128), blk, MMA_SMEM>>>(
        fh, fl, W2h, ff2_b, T0, nullptr, nullptr, FFc, Ec);

    // out = LN(h + ffn)
    add_ln_kernel<0><<<Mc, blk>>>(Hs, T0, ln2_g, ln2_b, out, nullptr, nullptr);
}

// round 7
// speedup vs baseline: 2.2898x; 1.0472x over previous
#include <cuda_runtime.h>
#include <cuda_fp16.h>
#include <cstdint>
#include <math.h>

// Problem constants
constexpr int Bc  = 8;
constexpr int Sc  = 512;
constexpr int Ec  = 1024;
constexpr int Hc  = 16;
constexpr int HDc = 64;
constexpr int FFc = 4096;
constexpr int NEc = 129;           // 2P+1
constexpr int Mc  = Bc * Sc;       // 4096 rows
constexpr int E3  = 3 * Ec;        // 3072
constexpr int SE  = 672;           // extended score width: 512 + 129 + pad

// ---------------------------------------------------------------------------
// Scratch (device globals; no allocation allowed)
// ---------------------------------------------------------------------------
__device__ __align__(256) __half g_xh[Mc * Ec];
__device__ __align__(256) __half g_xl[Mc * Ec];
__device__ __align__(256) __half g_W3h[E3 * Ec];
__device__ __align__(256) __half g_Woh[Ec * Ec];
__device__ __align__(256) __half g_W1h[FFc * Ec];
__device__ __align__(256) __half g_W2h[Ec * FFc];
__device__ float g_b3[E3];
__device__ __align__(256) __half g_qkvh[Mc * E3];
__device__ __align__(256) __half g_qkvl[Mc * E3];     // only q-part written/used
__device__ __align__(256) __half g_peh[256 * HDc];
__device__ float g_aw[128 * Sc * SE];                  // fp32 scores
__device__ __align__(256) __half g_awh[128 * Sc * SE];
__device__ __align__(256) __half g_vth[128 * HDc * SE];
__device__ __align__(256) __half g_ah[Mc * Ec];
__device__ __align__(256) __half g_al[Mc * Ec];
__device__ float g_t0[Mc * Ec];
__device__ float g_h[Mc * Ec];
__device__ __align__(256) __half g_hh[Mc * Ec];
__device__ __align__(256) __half g_hl[Mc * Ec];
__device__ __align__(256) __half g_fh[Mc * FFc];
__device__ __align__(256) __half g_fl[Mc * FFc];

// ---------------------------------------------------------------------------
// PTX helpers
// ---------------------------------------------------------------------------
__device__ __forceinline__ uint32_t smem_u32(const void* p) {
    uint32_t a;
    asm("{ .reg .u64 t; cvta.to.shared.u64 t, %1; cvt.u32.u64 %0, t; }" : "=r"(a) : "l"(p));
    return a;
}
__device__ __forceinline__ void cpasync16(uint32_t dst, const void* src) {
    asm volatile("cp.async.cg.shared.global [%0], [%1], 16;" :: "r"(dst), "l"(src));
}
#define CP_COMMIT()  asm volatile("cp.async.commit_group;" ::: "memory")
#define CP_WAIT(n)   asm volatile("cp.async.wait_group %0;" :: "n"(n) : "memory")

__device__ __forceinline__ void ldsm4(uint32_t* r, uint32_t addr) {
    asm volatile("ldmatrix.sync.aligned.m8n8.x4.shared.b16 {%0,%1,%2,%3}, [%4];"
                 : "=r"(r[0]), "=r"(r[1]), "=r"(r[2]), "=r"(r[3]) : "r"(addr));
}
__device__ __forceinline__ void mma_f16(float* c, const uint32_t* a, const uint32_t* b) {
    asm volatile(
        "mma.sync.aligned.m16n8k16.row.col.f32.f16.f16.f32 "
        "{%0,%1,%2,%3}, {%4,%5,%6,%7}, {%8,%9}, {%0,%1,%2,%3};"
        : "+f"(c[0]), "+f"(c[1]), "+f"(c[2]), "+f"(c[3])
        : "r"(a[0]), "r"(a[1]), "r"(a[2]), "r"(a[3]), "r"(b[0]), "r"(b[1]));
}
__device__ __forceinline__ void split2(float v0, float v1, uint32_t& uh, uint32_t& ul) {
    const __half h0 = __float2half_rn(v0), h1 = __float2half_rn(v1);
    __half2 ph = __halves2half2(h0, h1);
    __half2 pl = __halves2half2(
        __float2half_rn(v0 - __half2float(h0)),
        __float2half_rn(v1 - __half2float(h1)));
    uh = *(uint32_t*)&ph; ul = *(uint32_t*)&pl;
}

// ---------------------------------------------------------------------------
// HMMA GEMM (2-pass): C[M,N] = (Ah+Al)[M,K] @ Bh[N,K]^T + bias
// 128x128 CTA tile, BK=32, 8 warps of 32x64.
// 3-stage cp.async pipeline, ONE __syncthreads per chunk.
// ---------------------------------------------------------------------------
constexpr int LDSp  = 40;
constexpr int TILEB = 128 * LDSp * 2;      // 10240
constexpr int BUFB  = 3 * TILEB;           // Ah,Al,Bh = 30720
constexpr int MMA_SMEM = 3 * BUFB;         // 92160 B

template<int RELU, int SPLIT>
__global__ void __launch_bounds__(256)
mma_gemm(const __half* __restrict__ Ah, const __half* __restrict__ Al,
         const __half* __restrict__ Bh,
         const float* __restrict__ bias, float* __restrict__ C,
         __half* __restrict__ Ch, __half* __restrict__ Cl,
         int K, int N, int loCols)
{
    extern __shared__ char sm[];
    const uint32_t sbase = smem_u32(sm);
    const int tid = threadIdx.x;
    const int wid = tid >> 5, lane = tid & 31;
    const int wm = wid & 3, wn = wid >> 2;
    const int bm = blockIdx.y * 128, bn = blockIdx.x * 128;
    const int nk = K / 32;

    const int r0l = tid >> 2, sg = (tid & 3) << 3;

    auto load_chunk = [&](int kc) {
        if (kc < nk) {
            const uint32_t base = sbase + (kc % 3) * BUFB;
            const int k0 = kc * 32;
            #pragma unroll
            for (int it = 0; it < 2; it++) {
                const int r = r0l + it * 64;
                const uint32_t dst = base + r * 80 + sg * 2;
                const size_t ao = (size_t)(bm + r) * K + k0 + sg;
                const size_t bo = (size_t)(bn + r) * K + k0 + sg;
                cpasync16(dst,             Ah + ao);
                cpasync16(dst + TILEB,     Al + ao);
                cpasync16(dst + 2 * TILEB, Bh + bo);
            }
        }
        CP_COMMIT();
    };

    float acc[2][8][4];
    #pragma unroll
    for (int mt = 0; mt < 2; mt++)
        #pragma unroll
        for (int nt = 0; nt < 8; nt++)
            #pragma unroll
            for (int i = 0; i < 4; i++) acc[mt][nt][i] = 0.f;

    uint32_t aF[2][2][4];
    uint32_t bF[8][2][2];

    const int a_row = wm * 32 + (lane & 15);
    const int a_kof = (lane >> 4) << 3;
    const int b_n   = wn * 64 + (lane & 7) + ((lane & 16) >> 1);
    const int b_kof = ((lane >> 3) & 1) << 3;

    auto loadA = [&](uint32_t tbase) {
        #pragma unroll
        for (int mt = 0; mt < 2; mt++)
            #pragma unroll
            for (int ks = 0; ks < 2; ks++)
                ldsm4(aF[mt][ks], tbase + (a_row + mt * 16) * 80 + (ks * 16 + a_kof) * 2);
    };
    auto loadB = [&](uint32_t tbase) {
        #pragma unroll
        for (int ntp = 0; ntp < 4; ntp++)
            #pragma unroll
            for (int ks = 0; ks < 2; ks++) {
                uint32_t t4[4];
                ldsm4(t4, tbase + (b_n + ntp * 16) * 80 + (ks * 16 + b_kof) * 2);
                bF[ntp * 2 + 0][ks][0] = t4[0]; bF[ntp * 2 + 0][ks][1] = t4[1];
                bF[ntp * 2 + 1][ks][0] = t4[2]; bF[ntp * 2 + 1][ks][1] = t4[3];
            }
    };
    auto mma_all = [&]() {
        #pragma unroll
        for (int ks = 0; ks < 2; ks++)
            #pragma unroll
            for (int mt = 0; mt < 2; mt++)
                #pragma unroll
                for (int nt = 0; nt < 8; nt++)
                    mma_f16(acc[mt][nt], aF[mt][ks], bF[nt][ks]);
    };

    load_chunk(0);
    load_chunk(1);
    for (int kc = 0; kc < nk; kc++) {
        CP_WAIT(1);              // chunk kc complete
        __syncthreads();         // publish; also protects stage being overwritten
        load_chunk(kc + 2);      // prefetch into stage (kc+2)%3 (= stage of kc-1)

        const uint32_t base = sbase + (kc % 3) * BUFB;
        loadA(base);
        loadB(base + 2 * TILEB);
        mma_all();               // hi*B
        loadA(base + TILEB);
        mma_all();               // lo*B
    }

    #pragma unroll
    for (int mt = 0; mt < 2; mt++) {
        #pragma unroll
        for (int nt = 0; nt < 8; nt++) {
            const int row = bm + wm * 32 + mt * 16 + (lane >> 2);
            const int col = bn + wn * 64 + nt * 8 + ((lane & 3) << 1);
            const float bi0 = bias[col], bi1 = bias[col + 1];
            float o00 = acc[mt][nt][0] + bi0, o01 = acc[mt][nt][1] + bi1;
            float o10 = acc[mt][nt][2] + bi0, o11 = acc[mt][nt][3] + bi1;
            if (RELU) {
                o00 = fmaxf(o00, 0.f); o01 = fmaxf(o01, 0.f);
                o10 = fmaxf(o10, 0.f); o11 = fmaxf(o11, 0.f);
            }
            const size_t i0 = (size_t)row * N + col;
            const size_t i1 = (size_t)(row + 8) * N + col;
            if (SPLIT) {
                uint32_t uh0, ul0, uh1, ul1;
                split2(o00, o01, uh0, ul0);
                split2(o10, o11, uh1, ul1);
                *(uint32_t*)(Ch + i0) = uh0;
                *(uint32_t*)(Ch + i1) = uh1;
                if (col < loCols) {
                    *(uint32_t*)(Cl + i0) = ul0;
                    *(uint32_t*)(Cl + i1) = ul1;
                }
            } else {
                *(float2*)(C + i0) = make_float2(o00, o01);
                *(float2*)(C + i1) = make_float2(o10, o11);
            }
        }
    }
}

// ---------------------------------------------------------------------------
// Fused scores GEMM (HMMA, 2-pass): per (b,h):
//   AW[i, j]     = Q_h[i,:] . K_h[j,:]       (j < 512)
//   AW[i, 512+e] = Q_h[i,:] . pos_emb[e,:]   (e < 129; pad rows zero)
// A = Q hi/lo, B = K/pe hi only. Single K-block (K=64).
// ---------------------------------------------------------------------------
constexpr int QK_LDS = 72;
constexpr int QK_T   = 128 * QK_LDS * 2;     // 18432
constexpr int QK_SMEM = 3 * QK_T;            // 55296 B

__global__ void __launch_bounds__(256)
qk_scores(float* __restrict__ AW)
{
    extern __shared__ char sm[];
    const uint32_t sA = smem_u32(sm);
    const uint32_t sB = sA + 2 * QK_T;
    const int tid = threadIdx.x;
    const int wid = tid >> 5, lane = tid & 31;
    const int wm = wid & 3, wn = wid >> 2;
    const int bn = blockIdx.x * 128, bm = blockIdx.y * 128;
    const int bh = blockIdx.z, b = bh >> 4, h = bh & 15;

    {
        const int r0 = tid >> 3, sg = (tid & 7) << 3;
        #pragma unroll
        for (int it = 0; it < 4; it++) {
            const int r = r0 + it * 32;
            const uint32_t off = (r * QK_LDS + sg) * 2;
            const size_t ao = (size_t)(b * Sc + bm + r) * E3 + h * HDc + sg;
            cpasync16(sA + off,        g_qkvh + ao);
            cpasync16(sA + QK_T + off, g_qkvl + ao);
            const int gr = bn + r;
            const __half* bph;
            if (gr < Sc) {
                bph = g_qkvh + (size_t)(b * Sc + gr) * E3 + Ec + h * HDc + sg;
            } else {
                bph = g_peh + (size_t)(gr - Sc) * HDc + sg;
            }
            cpasync16(sB + off, bph);
        }
        CP_COMMIT(); CP_WAIT(0);
        __syncthreads();
    }

    float acc[2][8][4];
    #pragma unroll
    for (int mt = 0; mt < 2; mt++)
        #pragma unroll
        for (int nt = 0; nt < 8; nt++)
            #pragma unroll
            for (int i = 0; i < 4; i++) acc[mt][nt][i] = 0.f;

    uint32_t aF[2][2][4], bF[8][2][2];
    const int a_row = wm * 32 + (lane & 15);
    const int a_kof = (lane >> 4) << 3;
    const int b_n   = wn * 64 + (lane & 7) + ((lane & 16) >> 1);
    const int b_kof = ((lane >> 3) & 1) << 3;

    auto loadA = [&](uint32_t tb, int k0) {
        #pragma unroll
        for (int mt = 0; mt < 2; mt++)
            #pragma unroll
            for (int ks = 0; ks < 2; ks++)
                ldsm4(aF[mt][ks], tb + ((a_row + mt * 16) * QK_LDS + k0 + ks * 16 + a_kof) * 2);
    };
    auto loadB = [&](uint32_t tb, int k0) {
        #pragma unroll
        for (int ntp = 0; ntp < 4; ntp++)
            #pragma unroll
            for (int ks = 0; ks < 2; ks++) {
                uint32_t t4[4];
                ldsm4(t4, tb + ((b_n + ntp * 16) * QK_LDS + k0 + ks * 16 + b_kof) * 2);
                bF[ntp * 2 + 0][ks][0] = t4[0]; bF[ntp * 2 + 0][ks][1] = t4[1];
                bF[ntp * 2 + 1][ks][0] = t4[2]; bF[ntp * 2 + 1][ks][1] = t4[3];
            }
    };
    auto mma_all = [&]() {
        #pragma unroll
        for (int ks = 0; ks < 2; ks++)
            #pragma unroll
            for (int mt = 0; mt < 2; mt++)
                #pragma unroll
                for (int nt = 0; nt < 8; nt++)
                    mma_f16(acc[mt][nt], aF[mt][ks], bF[nt][ks]);
    };

    #pragma unroll
    for (int kg = 0; kg < 2; kg++) {
        const int k0 = kg * 32;
        loadA(sA, k0);
        loadB(sB, k0);
        mma_all();
        loadA(sA + QK_T, k0);
        mma_all();
    }

    #pragma unroll
    for (int mt = 0; mt < 2; mt++) {
        #pragma unroll
        for (int nt = 0; nt < 8; nt++) {
            const int row = bm + wm * 32 + mt * 16 + (lane >> 2);
            const int col = bn + wn * 64 + nt * 8 + ((lane & 3) << 1);
            if (col < SE) {
                const size_t base = (size_t)(bh * Sc + row) * SE + col;
                *(float2*)(AW + base)             = make_float2(acc[mt][nt][0], acc[mt][nt][1]);
                *(float2*)(AW + base + 8ull * SE) = make_float2(acc[mt][nt][2], acc[mt][nt][3]);
            }
        }
    }
}

// ---------------------------------------------------------------------------
// Per-head V^T build (hi only)
// ---------------------------------------------------------------------------
__global__ void vt_build()
{
    __shared__ __half th[32][33];
    const int jt = blockIdx.x, dt = blockIdx.y, bh = blockIdx.z;
    const int b = bh >> 4, h = bh & 15;
    const int j0 = jt * 32, d0 = dt * 32;
    const int tx = threadIdx.x, ty = threadIdx.y;

    #pragma unroll
    for (int k = 0; k < 4; k++) {
        const int j = j0 + ty + k * 8;
        const int d = d0 + tx;
        __half vh;
        if (j < Sc) {
            vh = g_qkvh[(size_t)(b * Sc + j) * E3 + 2 * Ec + h * HDc + d];
        } else if (j < Sc + NEc) {
            vh = g_peh[(size_t)(j - Sc) * HDc + d];
        } else {
            vh = __float2half_rn(0.f);
        }
        th[ty + k * 8][tx] = vh;
    }
    __syncthreads();
    #pragma unroll
    for (int k = 0; k < 4; k++) {
        const int d = d0 + ty + k * 8;
        const int j = j0 + tx;
        g_vth[(size_t)bh * HDc * SE + (size_t)d * SE + j] = th[tx][ty + k * 8];
    }
}

// ---------------------------------------------------------------------------
// AV GEMM (HMMA, single-pass): A = aw hi, B = vt hi. 3-stage pipeline.
// ---------------------------------------------------------------------------
constexpr int AV_AT = 128 * LDSp * 2;          // 10240
constexpr int AV_BT = 64 * LDSp * 2;           // 5120
constexpr int AV_ST = AV_AT + AV_BT;           // 15360
constexpr int AV_SMEM = 3 * AV_ST;             // 46080

__global__ void __launch_bounds__(256)
av_mma()
{
    extern __shared__ char sm[];
    const uint32_t sbase = smem_u32(sm);
    const int tid = threadIdx.x;
    const int wid = tid >> 5, lane = tid & 31;
    const int bm = blockIdx.x * 128;
    const int bh = blockIdx.y, b = bh >> 4, h = bh & 15;
    const int nk = SE / 32;   // 21

    auto load_chunk = [&](int kc) {
        if (kc < nk) {
            const uint32_t base = sbase + (kc % 3) * AV_ST;
            const int k0 = kc * 32;
            const int sg = (tid & 3) << 3;
            #pragma unroll
            for (int it = 0; it < 2; it++) {
                const int r = (tid >> 2) + it * 64;
                cpasync16(base + r * 80 + sg * 2,
                          g_awh + (size_t)(bh * Sc + bm + r) * SE + k0 + sg);
            }
            {
                const int r = tid >> 2;
                if (r < 64) {
                    cpasync16(base + AV_AT + r * 80 + sg * 2,
                              g_vth + (size_t)bh * HDc * SE + (size_t)r * SE + k0 + sg);
                }
            }
        }
        CP_COMMIT();
    };

    float acc[8][4];
    #pragma unroll
    for (int nt = 0; nt < 8; nt++)
        #pragma unroll
        for (int i = 0; i < 4; i++) acc[nt][i] = 0.f;

    uint32_t aF[2][4], bF[8][2][2];
    const int a_row = wid * 16 + (lane & 15);
    const int a_kof = (lane >> 4) << 3;
    const int b_n   = (lane & 7) + ((lane & 16) >> 1);
    const int b_kof = ((lane >> 3) & 1) << 3;

    auto loadA = [&](uint32_t tb) {
        #pragma unroll
        for (int ks = 0; ks < 2; ks++)
            ldsm4(aF[ks], tb + (a_row * 80) + (ks * 16 + a_kof) * 2);
    };
    auto loadB = [&](uint32_t tb) {
        #pragma unroll
        for (int ntp = 0; ntp < 4; ntp++)
            #pragma unroll
            for (int ks = 0; ks < 2; ks++) {
                uint32_t t4[4];
                ldsm4(t4, tb + (b_n + ntp * 16) * 80 + (ks * 16 + b_kof) * 2);
                bF[ntp * 2 + 0][ks][0] = t4[0]; bF[ntp * 2 + 0][ks][1] = t4[1];
                bF[ntp * 2 + 1][ks][0] = t4[2]; bF[ntp * 2 + 1][ks][1] = t4[3];
            }
    };
    auto mma_all = [&]() {
        #pragma unroll
        for (int ks = 0; ks < 2; ks++)
            #pragma unroll
            for (int nt = 0; nt < 8; nt++)
                mma_f16(acc[nt], aF[ks], bF[nt][ks]);
    };

    load_chunk(0);
    load_chunk(1);
    for (int kc = 0; kc < nk; kc++) {
        CP_WAIT(1);
        __syncthreads();
        load_chunk(kc + 2);
        const uint32_t base = sbase + (kc % 3) * AV_ST;
        loadA(base);
        loadB(base + AV_AT);
        mma_all();
    }

    #pragma unroll
    for (int nt = 0; nt < 8; nt++) {
        const int row = bm + wid * 16 + (lane >> 2);
        const int col = nt * 8 + ((lane & 3) << 1);
        const size_t i0 = (size_t)(b * Sc + row) * Ec + h * HDc + col;
        const size_t i1 = (size_t)(b * Sc + row + 8) * Ec + h * HDc + col;
        uint32_t uh0, ul0, uh1, ul1;
        split2(acc[nt][0], acc[nt][1], uh0, ul0);
        split2(acc[nt][2], acc[nt][3], uh1, ul1);
        *(uint32_t*)(g_ah + i0) = uh0;
        *(uint32_t*)(g_ah + i1) = uh1;
        *(uint32_t*)(g_al + i0) = ul0;
        *(uint32_t*)(g_al + i1) = ul1;
    }
}

// ---------------------------------------------------------------------------
// Elementwise prep kernels
// ---------------------------------------------------------------------------
__global__ void __launch_bounds__(256) split_act(
    const float* __restrict__ A, __half* __restrict__ hi,
    __half* __restrict__ lo, int n2)
{
    const int i = blockIdx.x * 256 + threadIdx.x;
    if (i >= n2) return;
    const float2 v = ((const float2*)A)[i];
    uint32_t uh, ul;
    split2(v.x, v.y, uh, ul);
    ((uint32_t*)hi)[i] = uh;
    ((uint32_t*)lo)[i] = ul;
}

// Merged weight prep: all 6 transposes + pos_emb rounding in one launch.
// Tile blocks: wq[0,1024) wk[1024,2048) wv[2048,3072) wo[3072,4096)
// ff1[4096,8192) ff2[8192,12288) pe[12288,12352)
__device__ __forceinline__ void tr_tile(
    const float* __restrict__ W, int N, __half* __restrict__ dst,
    int rowOff, int ldo, int idx, int xTiles, int tx, int ty)
{
    __shared__ float t[32][33];
    const int n0 = (idx % xTiles) * 32;
    const int k0 = (idx / xTiles) * 32;
    #pragma unroll
    for (int j = 0; j < 32; j += 8)
        t[ty + j][tx] = W[(size_t)(k0 + ty + j) * N + n0 + tx];
    __syncthreads();
    #pragma unroll
    for (int j = 0; j < 32; j += 8)
        dst[(size_t)(rowOff + n0 + ty + j) * ldo + k0 + tx] = __float2half_rn(t[tx][ty + j]);
}

__global__ void __launch_bounds__(256) prep_weights(
    const float* __restrict__ wq, const float* __restrict__ wk,
    const float* __restrict__ wv, const float* __restrict__ wo,
    const float* __restrict__ ff1, const float* __restrict__ ff2,
    const float* __restrict__ pos_emb)
{
    const int bidx = blockIdx.x;
    const int tid = threadIdx.x;
    const int tx = tid & 31, ty = tid >> 5;
    if (bidx < 1024)       tr_tile(wq,  Ec,  g_W3h, 0,      Ec,  bidx,         32,  tx, ty);
    else if (bidx < 2048)  tr_tile(wk,  Ec,  g_W3h, Ec,     Ec,  bidx - 1024,  32,  tx, ty);
    else if (bidx < 3072)  tr_tile(wv,  Ec,  g_W3h, 2 * Ec, Ec,  bidx - 2048,  32,  tx, ty);
    else if (bidx < 4096)  tr_tile(wo,  Ec,  g_Woh, 0,      Ec,  bidx - 3072,  32,  tx, ty);
    else if (bidx < 8192)  tr_tile(ff1, FFc, g_W1h, 0,      Ec,  bidx - 4096,  128, tx, ty);
    else if (bidx < 12288) tr_tile(ff2, Ec,  g_W2h, 0,      FFc, bidx - 8192,  32,  tx, ty);
    else {
        const int i = (bidx - 12288) * 256 + tid;
        if (i < 256 * HDc) {
            const int e = i >> 6;
            g_peh[i] = __float2half_rn((e < NEc) ? pos_emb[i] : 0.f);
        }
    }
}

__global__ void concat_bias(const float* a, const float* b, const float* c) {
    const int i = blockIdx.x * 256 + threadIdx.x;
    if (i < Ec) g_b3[i] = a[i];
    else if (i < 2 * Ec) g_b3[i] = b[i - Ec];
    else if (i < 3 * Ec) g_b3[i] = c[i - 2 * Ec];
}

// ---------------------------------------------------------------------------
// Fused score assembly + softmax + bucket scatter; emits fp16 aw_ext (hi only).
// ---------------------------------------------------------------------------
__global__ void __launch_bounds__(256) softmax_kernel(
    const float* __restrict__ dist, const int* __restrict__ dt)
{
    __shared__ float ssc[Sc];
    __shared__ int dts[Sc];
    __shared__ unsigned char es[Sc];
    __shared__ float bucket[NEc];
    __shared__ float red[8];

    const int i = blockIdx.x, h = blockIdx.y, b = blockIdx.z;
    const int tid = threadIdx.x;
    const int bh = b * Hc + h;
    const size_t rowbase = (size_t)(bh * Sc + i) * SE;
    const float* drow = dist + ((size_t)b * Sc + i) * Sc;

    for (int t = tid; t < Sc; t += 256) dts[t] = dt[b * Sc + t];
    for (int t = tid; t < NEc; t += 256) bucket[t] = 0.f;
    __syncthreads();

    const int dti = dts[i];
    float lmax = -1e30f;
    for (int t = tid; t < Sc; t += 256) {
        int rel = dts[t] - dti;
        rel = rel < -64 ? -64 : (rel > 64 ? 64 : rel);
        const int e = rel + 64;
        es[t] = (unsigned char)e;
        const float s = (g_aw[rowbase + t] + g_aw[rowbase + Sc + e]) * 0.125f + 0.6f * drow[t];
        ssc[t] = s;
        lmax = fmaxf(lmax, s);
    }
    #pragma unroll
    for (int o = 16; o; o >>= 1) lmax = fmaxf(lmax, __shfl_xor_sync(0xffffffffu, lmax, o));
    if ((tid & 31) == 0) red[tid >> 5] = lmax;
    __syncthreads();
    float mx = red[0];
    #pragma unroll
    for (int w = 1; w < 8; w++) mx = fmaxf(mx, red[w]);
    __syncthreads();

    float lsum = 0.f;
    for (int t = tid; t < Sc; t += 256) {
        const float p = __expf(ssc[t] - mx);
        ssc[t] = p;
        lsum += p;
    }
    #pragma unroll
    for (int o = 16; o; o >>= 1) lsum += __shfl_xor_sync(0xffffffffu, lsum, o);
    if ((tid & 31) == 0) red[tid >> 5] = lsum;
    __syncthreads();
    float tot = 0.f;
    #pragma unroll
    for (int w = 0; w < 8; w++) tot += red[w];
    const float inv = 1.f / tot;

    for (int t = tid; t < Sc; t += 256) {
        const float a = ssc[t] * inv;
        g_awh[rowbase + t] = __float2half_rn(a);
        atomicAdd(&bucket[es[t]], a);
    }
    __syncthreads();
    for (int t = tid; t < SE - Sc; t += 256) {
        const float v = (t < NEc) ? bucket[t] : 0.f;
        g_awh[rowbase + Sc + t] = __float2half_rn(v);
    }
}

// ---------------------------------------------------------------------------
// out = LayerNorm(X + R); optional fp16 hi/lo emission.
// ---------------------------------------------------------------------------
template<int SPLIT>
__global__ void __launch_bounds__(256) add_ln_kernel(
    const float* __restrict__ X, const float* __restrict__ Rr,
    const float* __restrict__ gam, const float* __restrict__ bet,
    float* __restrict__ Out, __half* __restrict__ Oh,
    __half* __restrict__ Ol)
{
    __shared__ float sh[Ec];
    __shared__ float red[8];
    const int row = blockIdx.x;
    const int tid = threadIdx.x;
    const float* xr = X + (size_t)row * Ec;
    const float* rr = Rr + (size_t)row * Ec;

    float lsum = 0.f;
    for (int t = tid; t < Ec; t += 256) {
        const float v = xr[t] + rr[t];
        sh[t] = v;
        lsum += v;
    }
    #pragma unroll
    for (int o = 16; o; o >>= 1) lsum += __shfl_xor_sync(0xffffffffu, lsum, o);
    if ((tid & 31) == 0) red[tid >> 5] = lsum;
    __syncthreads();
    float tot = 0.f;
    #pragma unroll
    for (int w = 0; w < 8; w++) tot += red[w];
    const float mu = tot * (1.f / Ec);
    __syncthreads();

    float lvar = 0.f;
    for (int t = tid; t < Ec; t += 256) {
        const float d = sh[t] - mu;
        lvar += d * d;
    }
    #pragma unroll
    for (int o = 16; o; o >>= 1) lvar += __shfl_xor_sync(0xffffffffu, lvar, o);
    if ((tid & 31) == 0) red[tid >> 5] = lvar;
    __syncthreads();
    float vtot = 0.f;
    #pragma unroll
    for (int w = 0; w < 8; w++) vtot += red[w];
    const float inv = rsqrtf(vtot * (1.f / Ec) + 1e-5f);

    float* orow = Out + (size_t)row * Ec;
    for (int t = tid; t < Ec; t += 256) {
        const float v = (sh[t] - mu) * inv * gam[t] + bet[t];
        orow[t] = v;
        if (SPLIT) {
            const size_t idx = (size_t)row * Ec + t;
            const __half hv = __float2half_rn(v);
            Oh[idx] = hv;
            Ol[idx] = __float2half_rn(v - __half2float(hv));
        }
    }
}

// ---------------------------------------------------------------------------
extern "C" void kernel_launch(void* const* d_in, const int* in_sizes, int n_in,
                              void* d_out, int out_size)
{
    (void)in_sizes; (void)n_in; (void)out_size;
    const float* x       = (const float*)d_in[0];
    const float* dist    = (const float*)d_in[1];
    const int*   dt      = (const int*)d_in[2];
    const float* pos_emb = (const float*)d_in[3];
    const float* wq_w = (const float*)d_in[4];
    const float* wq_b = (const float*)d_in[5];
    const float* wk_w = (const float*)d_in[6];
    const float* wk_b = (const float*)d_in[7];
    const float* wv_w = (const float*)d_in[8];
    const float* wv_b = (const float*)d_in[9];
    const float* wo_w = (const float*)d_in[10];
    const float* wo_b = (const float*)d_in[11];
    const float* ff1_w = (const float*)d_in[12];
    const float* ff1_b = (const float*)d_in[13];
    const float* ff2_w = (const float*)d_in[14];
    const float* ff2_b = (const float*)d_in[15];
    const float* ln1_g = (const float*)d_in[16];
    const float* ln1_b = (const float*)d_in[17];
    const float* ln2_g = (const float*)d_in[18];
    const float* ln2_b = (const float*)d_in[19];
    float* out = (float*)d_out;

    __half *xh, *xl, *W3h, *Woh, *W1h, *W2h;
    __half *qkvh, *qkvl, *ah, *al, *hh, *hl, *fh, *fl;
    float *b3, *AW, *T0, *Hs;
    cudaGetSymbolAddress((void**)&xh, g_xh);   cudaGetSymbolAddress((void**)&xl, g_xl);
    cudaGetSymbolAddress((void**)&W3h, g_W3h);
    cudaGetSymbolAddress((void**)&Woh, g_Woh);
    cudaGetSymbolAddress((void**)&W1h, g_W1h);
    cudaGetSymbolAddress((void**)&W2h, g_W2h);
    cudaGetSymbolAddress((void**)&qkvh, g_qkvh); cudaGetSymbolAddress((void**)&qkvl, g_qkvl);
    cudaGetSymbolAddress((void**)&ah, g_ah);   cudaGetSymbolAddress((void**)&al, g_al);
    cudaGetSymbolAddress((void**)&hh, g_hh);   cudaGetSymbolAddress((void**)&hl, g_hl);
    cudaGetSymbolAddress((void**)&fh, g_fh);   cudaGetSymbolAddress((void**)&fl, g_fl);
    cudaGetSymbolAddress((void**)&b3, g_b3);
    cudaGetSymbolAddress((void**)&AW, g_aw);
    cudaGetSymbolAddress((void**)&T0, g_t0);
    cudaGetSymbolAddress((void**)&Hs, g_h);

    cudaFuncSetAttribute(mma_gemm<0, 0>, cudaFuncAttributeMaxDynamicSharedMemorySize, MMA_SMEM);
    cudaFuncSetAttribute(mma_gemm<0, 1>, cudaFuncAttributeMaxDynamicSharedMemorySize, MMA_SMEM);
    cudaFuncSetAttribute(mma_gemm<1, 1>, cudaFuncAttributeMaxDynamicSharedMemorySize, MMA_SMEM);
    cudaFuncSetAttribute(qk_scores, cudaFuncAttributeMaxDynamicSharedMemorySize, QK_SMEM);
    cudaFuncSetAttribute(av_mma, cudaFuncAttributeMaxDynamicSharedMemorySize, AV_SMEM);

    dim3 blk(256);
    dim3 tblk(32, 8);

    // prep: activations split + all weights in one launch
    split_act<<<(Mc * Ec / 2 + 255) / 256, blk>>>(x, xh, xl, Mc * Ec / 2);
    prep_weights<<<12288 + 64, blk>>>(wq_w, wk_w, wv_w, wo_w, ff1_w, ff2_w, pos_emb);
    concat_bias<<<12, blk>>>(wq_b, wk_b, wv_b);

    // fused QKV projection -> fp16 hi everywhere, lo only for q columns
    mma_gemm<0, 1><<<dim3(E3 / 128, Mc / 128), blk, MMA_SMEM>>>(
        xh, xl, W3h, b3, nullptr, qkvh, qkvl, Ec, E3, Ec);

    // per-head V^T (+pe^T) staging (hi only)
    vt_build<<<dim3(SE / 32, 2, 128), tblk>>>();

    // fused scores: QK^T and q.pe in one HMMA GEMM (2-pass)    [launch #6]
    qk_scores<<<dim3(6, 4, 128), blk, QK_SMEM>>>(AW);

    // softmax (+gather +bucket scatter), emits fp16 aw_ext (hi only)
    softmax_kernel<<<dim3(Sc, Hc, Bc), blk>>>(dist, dt);

    // attn = aw_ext @ vt^T (single-pass)
    av_mma<<<dim3(4, 128), blk, AV_SMEM>>>();

    // output projection (2-pass)
    mma_gemm<0, 0><<<dim3(Ec / 128, Mc / 128), blk, MMA_SMEM>>>(
        ah, al, Woh, wo_b, T0, nullptr, nullptr, Ec, Ec, 0);

    // h = LN(x + attn_out), emit hi/lo for FF1
    add_ln_kernel<1><<<Mc, blk>>>(x, T0, ln1_g, ln1_b, Hs, hh, hl);

    // FFN (2-pass)
    mma_gemm<1, 1><<<dim3(FFc / 128, Mc / 128), blk, MMA_SMEM>>>(
        hh, hl, W1h, ff1_b, nullptr, fh, fl, Ec, FFc, FFc);
    mma_gemm<0, 0><<<dim3(Ec / 128, Mc / 128), blk, MMA_SMEM>>>(
        fh, fl, W2h, ff2_b, T0, nullptr, nullptr, FFc, Ec, 0);

    // out = LN(h + ffn)
    add_ln_kernel<0><<<Mc, blk>>>(Hs, T0, ln2_g, ln2_b, out, nullptr, nullptr);
}

// round 8
// speedup vs baseline: 3.8295x; 1.6724x over previous
#include <cuda_runtime.h>
#include <cuda_fp16.h>
#include <cstdint>
#include <math.h>

// Problem constants
constexpr int Bc  = 8;
constexpr int Sc  = 512;
constexpr int Ec  = 1024;
constexpr int Hc  = 16;
constexpr int HDc = 64;
constexpr int FFc = 4096;
constexpr int NEc = 129;           // 2P+1
constexpr int Mc  = Bc * Sc;       // 4096 rows
constexpr int E3  = 3 * Ec;        // 3072
constexpr int SE  = 672;           // extended score width: 512 + 129 + pad

// ---------------------------------------------------------------------------
// Scratch (device globals; no allocation allowed)
// ---------------------------------------------------------------------------
__device__ __align__(256) __half g_xh[Mc * Ec];
__device__ __align__(256) __half g_xl[Mc * Ec];
__device__ __align__(256) __half g_W3h[E3 * Ec];
__device__ __align__(256) __half g_Woh[Ec * Ec];
__device__ __align__(256) __half g_W1h[FFc * Ec];
__device__ __align__(256) __half g_W2h[Ec * FFc];
__device__ float g_b3[E3];
__device__ __align__(256) __half g_qkvh[Mc * E3];
__device__ __align__(256) __half g_qkvl[Mc * E3];     // only q-part written/used
__device__ __align__(256) __half g_peh[256 * HDc];
__device__ float g_aw[128 * Sc * SE];                  // fp32 scores
__device__ __align__(256) __half g_awh[128 * Sc * SE];
__device__ __align__(256) __half g_vth[128 * HDc * SE];
__device__ __align__(256) __half g_ah[Mc * Ec];
__device__ __align__(256) __half g_al[Mc * Ec];
__device__ float g_t0[Mc * Ec];
__device__ float g_h[Mc * Ec];
__device__ __align__(256) __half g_hh[Mc * Ec];
__device__ __align__(256) __half g_hl[Mc * Ec];
__device__ __align__(256) __half g_fh[Mc * FFc];
__device__ __align__(256) __half g_fl[Mc * FFc];

// ---------------------------------------------------------------------------
// PTX helpers
// ---------------------------------------------------------------------------
__device__ __forceinline__ uint32_t smem_u32(const void* p) {
    uint32_t a;
    asm("{ .reg .u64 t; cvta.to.shared.u64 t, %1; cvt.u32.u64 %0, t; }" : "=r"(a) : "l"(p));
    return a;
}
__device__ __forceinline__ void cpasync16(uint32_t dst, const void* src) {
    asm volatile("cp.async.cg.shared.global [%0], [%1], 16;" :: "r"(dst), "l"(src));
}
#define CP_COMMIT()  asm volatile("cp.async.commit_group;" ::: "memory")
#define CP_WAIT(n)   asm volatile("cp.async.wait_group %0;" :: "n"(n) : "memory")

__device__ __forceinline__ void ldsm4(uint32_t* r, uint32_t addr) {
    asm volatile("ldmatrix.sync.aligned.m8n8.x4.shared.b16 {%0,%1,%2,%3}, [%4];"
                 : "=r"(r[0]), "=r"(r[1]), "=r"(r[2]), "=r"(r[3]) : "r"(addr));
}
__device__ __forceinline__ void mma_f16(float* c, const uint32_t* a, const uint32_t* b) {
    asm volatile(
        "mma.sync.aligned.m16n8k16.row.col.f32.f16.f16.f32 "
        "{%0,%1,%2,%3}, {%4,%5,%6,%7}, {%8,%9}, {%0,%1,%2,%3};"
        : "+f"(c[0]), "+f"(c[1]), "+f"(c[2]), "+f"(c[3])
        : "r"(a[0]), "r"(a[1]), "r"(a[2]), "r"(a[3]), "r"(b[0]), "r"(b[1]));
}
__device__ __forceinline__ void split2(float v0, float v1, uint32_t& uh, uint32_t& ul) {
    const __half h0 = __float2half_rn(v0), h1 = __float2half_rn(v1);
    __half2 ph = __halves2half2(h0, h1);
    __half2 pl = __halves2half2(
        __float2half_rn(v0 - __half2float(h0)),
        __float2half_rn(v1 - __half2float(h1)));
    uh = *(uint32_t*)&ph; ul = *(uint32_t*)&pl;
}

// ---------------------------------------------------------------------------
// HMMA GEMM (2-pass): C[M,N] = (Ah+Al)[M,K] @ Bh[N,K]^T + bias
// 128x128 CTA tile, BK=32, 8 warps of 32x64.
// 3-stage cp.async pipeline, ONE __syncthreads per chunk.
// ---------------------------------------------------------------------------
constexpr int LDSp  = 40;
constexpr int TILEB = 128 * LDSp * 2;      // 10240
constexpr int BUFB  = 3 * TILEB;           // Ah,Al,Bh = 30720
constexpr int MMA_SMEM = 3 * BUFB;         // 92160 B

template<int RELU, int SPLIT>
__global__ void __launch_bounds__(256)
mma_gemm(const __half* __restrict__ Ah, const __half* __restrict__ Al,
         const __half* __restrict__ Bh,
         const float* __restrict__ bias, float* __restrict__ C,
         __half* __restrict__ Ch, __half* __restrict__ Cl,
         int K, int N, int loCols)
{
    extern __shared__ char sm[];
    const uint32_t sbase = smem_u32(sm);
    const int tid = threadIdx.x;
    const int wid = tid >> 5, lane = tid & 31;
    const int wm = wid & 3, wn = wid >> 2;
    const int bm = blockIdx.y * 128, bn = blockIdx.x * 128;
    const int nk = K / 32;

    const int r0l = tid >> 2, sg = (tid & 3) << 3;

    auto load_chunk = [&](int kc) {
        if (kc < nk) {
            const uint32_t base = sbase + (kc % 3) * BUFB;
            const int k0 = kc * 32;
            #pragma unroll
            for (int it = 0; it < 2; it++) {
                const int r = r0l + it * 64;
                const uint32_t dst = base + r * 80 + sg * 2;
                const size_t ao = (size_t)(bm + r) * K + k0 + sg;
                const size_t bo = (size_t)(bn + r) * K + k0 + sg;
                cpasync16(dst,             Ah + ao);
                cpasync16(dst + TILEB,     Al + ao);
                cpasync16(dst + 2 * TILEB, Bh + bo);
            }
        }
        CP_COMMIT();
    };

    float acc[2][8][4];
    #pragma unroll
    for (int mt = 0; mt < 2; mt++)
        #pragma unroll
        for (int nt = 0; nt < 8; nt++)
            #pragma unroll
            for (int i = 0; i < 4; i++) acc[mt][nt][i] = 0.f;

    uint32_t aF[2][2][4];
    uint32_t bF[8][2][2];

    const int a_row = wm * 32 + (lane & 15);
    const int a_kof = (lane >> 4) << 3;
    const int b_n   = wn * 64 + (lane & 7) + ((lane & 16) >> 1);
    const int b_kof = ((lane >> 3) & 1) << 3;

    auto loadA = [&](uint32_t tbase) {
        #pragma unroll
        for (int mt = 0; mt < 2; mt++)
            #pragma unroll
            for (int ks = 0; ks < 2; ks++)
                ldsm4(aF[mt][ks], tbase + (a_row + mt * 16) * 80 + (ks * 16 + a_kof) * 2);
    };
    auto loadB = [&](uint32_t tbase) {
        #pragma unroll
        for (int ntp = 0; ntp < 4; ntp++)
            #pragma unroll
            for (int ks = 0; ks < 2; ks++) {
                uint32_t t4[4];
                ldsm4(t4, tbase + (b_n + ntp * 16) * 80 + (ks * 16 + b_kof) * 2);
                bF[ntp * 2 + 0][ks][0] = t4[0]; bF[ntp * 2 + 0][ks][1] = t4[1];
                bF[ntp * 2 + 1][ks][0] = t4[2]; bF[ntp * 2 + 1][ks][1] = t4[3];
            }
    };
    auto mma_all = [&]() {
        #pragma unroll
        for (int ks = 0; ks < 2; ks++)
            #pragma unroll
            for (int mt = 0; mt < 2; mt++)
                #pragma unroll
                for (int nt = 0; nt < 8; nt++)
                    mma_f16(acc[mt][nt], aF[mt][ks], bF[nt][ks]);
    };

    load_chunk(0);
    load_chunk(1);
    for (int kc = 0; kc < nk; kc++) {
        CP_WAIT(1);
        __syncthreads();
        load_chunk(kc + 2);

        const uint32_t base = sbase + (kc % 3) * BUFB;
        loadA(base);
        loadB(base + 2 * TILEB);
        mma_all();               // hi*B
        loadA(base + TILEB);
        mma_all();               // lo*B
    }

    #pragma unroll
    for (int mt = 0; mt < 2; mt++) {
        #pragma unroll
        for (int nt = 0; nt < 8; nt++) {
            const int row = bm + wm * 32 + mt * 16 + (lane >> 2);
            const int col = bn + wn * 64 + nt * 8 + ((lane & 3) << 1);
            const float bi0 = bias[col], bi1 = bias[col + 1];
            float o00 = acc[mt][nt][0] + bi0, o01 = acc[mt][nt][1] + bi1;
            float o10 = acc[mt][nt][2] + bi0, o11 = acc[mt][nt][3] + bi1;
            if (RELU) {
                o00 = fmaxf(o00, 0.f); o01 = fmaxf(o01, 0.f);
                o10 = fmaxf(o10, 0.f); o11 = fmaxf(o11, 0.f);
            }
            const size_t i0 = (size_t)row * N + col;
            const size_t i1 = (size_t)(row + 8) * N + col;
            if (SPLIT) {
                uint32_t uh0, ul0, uh1, ul1;
                split2(o00, o01, uh0, ul0);
                split2(o10, o11, uh1, ul1);
                *(uint32_t*)(Ch + i0) = uh0;
                *(uint32_t*)(Ch + i1) = uh1;
                if (col < loCols) {
                    *(uint32_t*)(Cl + i0) = ul0;
                    *(uint32_t*)(Cl + i1) = ul1;
                }
            } else {
                *(float2*)(C + i0) = make_float2(o00, o01);
                *(float2*)(C + i1) = make_float2(o10, o11);
            }
        }
    }
}

// ---------------------------------------------------------------------------
// Fused scores GEMM (HMMA, 2-pass)
// ---------------------------------------------------------------------------
constexpr int QK_LDS = 72;
constexpr int QK_T   = 128 * QK_LDS * 2;     // 18432
constexpr int QK_SMEM = 3 * QK_T;            // 55296 B

__global__ void __launch_bounds__(256)
qk_scores(float* __restrict__ AW)
{
    extern __shared__ char sm[];
    const uint32_t sA = smem_u32(sm);
    const uint32_t sB = sA + 2 * QK_T;
    const int tid = threadIdx.x;
    const int wid = tid >> 5, lane = tid & 31;
    const int wm = wid & 3, wn = wid >> 2;
    const int bn = blockIdx.x * 128, bm = blockIdx.y * 128;
    const int bh = blockIdx.z, b = bh >> 4, h = bh & 15;

    {
        const int r0 = tid >> 3, sg = (tid & 7) << 3;
        #pragma unroll
        for (int it = 0; it < 4; it++) {
            const int r = r0 + it * 32;
            const uint32_t off = (r * QK_LDS + sg) * 2;
            const size_t ao = (size_t)(b * Sc + bm + r) * E3 + h * HDc + sg;
            cpasync16(sA + off,        g_qkvh + ao);
            cpasync16(sA + QK_T + off, g_qkvl + ao);
            const int gr = bn + r;
            const __half* bph;
            if (gr < Sc) {
                bph = g_qkvh + (size_t)(b * Sc + gr) * E3 + Ec + h * HDc + sg;
            } else {
                bph = g_peh + (size_t)(gr - Sc) * HDc + sg;
            }
            cpasync16(sB + off, bph);
        }
        CP_COMMIT(); CP_WAIT(0);
        __syncthreads();
    }

    float acc[2][8][4];
    #pragma unroll
    for (int mt = 0; mt < 2; mt++)
        #pragma unroll
        for (int nt = 0; nt < 8; nt++)
            #pragma unroll
            for (int i = 0; i < 4; i++) acc[mt][nt][i] = 0.f;

    uint32_t aF[2][2][4], bF[8][2][2];
    const int a_row = wm * 32 + (lane & 15);
    const int a_kof = (lane >> 4) << 3;
    const int b_n   = wn * 64 + (lane & 7) + ((lane & 16) >> 1);
    const int b_kof = ((lane >> 3) & 1) << 3;

    auto loadA = [&](uint32_t tb, int k0) {
        #pragma unroll
        for (int mt = 0; mt < 2; mt++)
            #pragma unroll
            for (int ks = 0; ks < 2; ks++)
                ldsm4(aF[mt][ks], tb + ((a_row + mt * 16) * QK_LDS + k0 + ks * 16 + a_kof) * 2);
    };
    auto loadB = [&](uint32_t tb, int k0) {
        #pragma unroll
        for (int ntp = 0; ntp < 4; ntp++)
            #pragma unroll
            for (int ks = 0; ks < 2; ks++) {
                uint32_t t4[4];
                ldsm4(t4, tb + ((b_n + ntp * 16) * QK_LDS + k0 + ks * 16 + b_kof) * 2);
                bF[ntp * 2 + 0][ks][0] = t4[0]; bF[ntp * 2 + 0][ks][1] = t4[1];
                bF[ntp * 2 + 1][ks][0] = t4[2]; bF[ntp * 2 + 1][ks][1] = t4[3];
            }
    };
    auto mma_all = [&]() {
        #pragma unroll
        for (int ks = 0; ks < 2; ks++)
            #pragma unroll
            for (int mt = 0; mt < 2; mt++)
                #pragma unroll
                for (int nt = 0; nt < 8; nt++)
                    mma_f16(acc[mt][nt], aF[mt][ks], bF[nt][ks]);
    };

    #pragma unroll
    for (int kg = 0; kg < 2; kg++) {
        const int k0 = kg * 32;
        loadA(sA, k0);
        loadB(sB, k0);
        mma_all();
        loadA(sA + QK_T, k0);
        mma_all();
    }

    #pragma unroll
    for (int mt = 0; mt < 2; mt++) {
        #pragma unroll
        for (int nt = 0; nt < 8; nt++) {
            const int row = bm + wm * 32 + mt * 16 + (lane >> 2);
            const int col = bn + wn * 64 + nt * 8 + ((lane & 3) << 1);
            if (col < SE) {
                const size_t base = (size_t)(bh * Sc + row) * SE + col;
                *(float2*)(AW + base)             = make_float2(acc[mt][nt][0], acc[mt][nt][1]);
                *(float2*)(AW + base + 8ull * SE) = make_float2(acc[mt][nt][2], acc[mt][nt][3]);
            }
        }
    }
}

// ---------------------------------------------------------------------------
// Per-head V^T build (hi only)
// ---------------------------------------------------------------------------
__global__ void vt_build()
{
    __shared__ __half th[32][33];
    const int jt = blockIdx.x, dt = blockIdx.y, bh = blockIdx.z;
    const int b = bh >> 4, h = bh & 15;
    const int j0 = jt * 32, d0 = dt * 32;
    const int tx = threadIdx.x, ty = threadIdx.y;

    #pragma unroll
    for (int k = 0; k < 4; k++) {
        const int j = j0 + ty + k * 8;
        const int d = d0 + tx;
        __half vh;
        if (j < Sc) {
            vh = g_qkvh[(size_t)(b * Sc + j) * E3 + 2 * Ec + h * HDc + d];
        } else if (j < Sc + NEc) {
            vh = g_peh[(size_t)(j - Sc) * HDc + d];
        } else {
            vh = __float2half_rn(0.f);
        }
        th[ty + k * 8][tx] = vh;
    }
    __syncthreads();
    #pragma unroll
    for (int k = 0; k < 4; k++) {
        const int d = d0 + ty + k * 8;
        const int j = j0 + tx;
        g_vth[(size_t)bh * HDc * SE + (size_t)d * SE + j] = th[tx][ty + k * 8];
    }
}

// ---------------------------------------------------------------------------
// AV GEMM (HMMA, single-pass): A = aw hi, B = vt hi. 3-stage pipeline.
// ---------------------------------------------------------------------------
constexpr int AV_AT = 128 * LDSp * 2;          // 10240
constexpr int AV_BT = 64 * LDSp * 2;           // 5120
constexpr int AV_ST = AV_AT + AV_BT;           // 15360
constexpr int AV_SMEM = 3 * AV_ST;             // 46080

__global__ void __launch_bounds__(256)
av_mma()
{
    extern __shared__ char sm[];
    const uint32_t sbase = smem_u32(sm);
    const int tid = threadIdx.x;
    const int wid = tid >> 5, lane = tid & 31;
    const int bm = blockIdx.x * 128;
    const int bh = blockIdx.y, b = bh >> 4, h = bh & 15;
    const int nk = SE / 32;   // 21

    auto load_chunk = [&](int kc) {
        if (kc < nk) {
            const uint32_t base = sbase + (kc % 3) * AV_ST;
            const int k0 = kc * 32;
            const int sg = (tid & 3) << 3;
            #pragma unroll
            for (int it = 0; it < 2; it++) {
                const int r = (tid >> 2) + it * 64;
                cpasync16(base + r * 80 + sg * 2,
                          g_awh + (size_t)(bh * Sc + bm + r) * SE + k0 + sg);
            }
            {
                const int r = tid >> 2;
                if (r < 64) {
                    cpasync16(base + AV_AT + r * 80 + sg * 2,
                              g_vth + (size_t)bh * HDc * SE + (size_t)r * SE + k0 + sg);
                }
            }
        }
        CP_COMMIT();
    };

    float acc[8][4];
    #pragma unroll
    for (int nt = 0; nt < 8; nt++)
        #pragma unroll
        for (int i = 0; i < 4; i++) acc[nt][i] = 0.f;

    uint32_t aF[2][4], bF[8][2][2];
    const int a_row = wid * 16 + (lane & 15);
    const int a_kof = (lane >> 4) << 3;
    const int b_n   = (lane & 7) + ((lane & 16) >> 1);
    const int b_kof = ((lane >> 3) & 1) << 3;

    auto loadA = [&](uint32_t tb) {
        #pragma unroll
        for (int ks = 0; ks < 2; ks++)
            ldsm4(aF[ks], tb + (a_row * 80) + (ks * 16 + a_kof) * 2);
    };
    auto loadB = [&](uint32_t tb) {
        #pragma unroll
        for (int ntp = 0; ntp < 4; ntp++)
            #pragma unroll
            for (int ks = 0; ks < 2; ks++) {
                uint32_t t4[4];
                ldsm4(t4, tb + (b_n + ntp * 16) * 80 + (ks * 16 + b_kof) * 2);
                bF[ntp * 2 + 0][ks][0] = t4[0]; bF[ntp * 2 + 0][ks][1] = t4[1];
                bF[ntp * 2 + 1][ks][0] = t4[2]; bF[ntp * 2 + 1][ks][1] = t4[3];
            }
    };
    auto mma_all = [&]() {
        #pragma unroll
        for (int ks = 0; ks < 2; ks++)
            #pragma unroll
            for (int nt = 0; nt < 8; nt++)
                mma_f16(acc[nt], aF[ks], bF[nt][ks]);
    };

    load_chunk(0);
    load_chunk(1);
    for (int kc = 0; kc < nk; kc++) {
        CP_WAIT(1);
        __syncthreads();
        load_chunk(kc + 2);
        const uint32_t base = sbase + (kc % 3) * AV_ST;
        loadA(base);
        loadB(base + AV_AT);
        mma_all();
    }

    #pragma unroll
    for (int nt = 0; nt < 8; nt++) {
        const int row = bm + wid * 16 + (lane >> 2);
        const int col = nt * 8 + ((lane & 3) << 1);
        const size_t i0 = (size_t)(b * Sc + row) * Ec + h * HDc + col;
        const size_t i1 = (size_t)(b * Sc + row + 8) * Ec + h * HDc + col;
        uint32_t uh0, ul0, uh1, ul1;
        split2(acc[nt][0], acc[nt][1], uh0, ul0);
        split2(acc[nt][2], acc[nt][3], uh1, ul1);
        *(uint32_t*)(g_ah + i0) = uh0;
        *(uint32_t*)(g_ah + i1) = uh1;
        *(uint32_t*)(g_al + i0) = ul0;
        *(uint32_t*)(g_al + i1) = ul1;
    }
}

// ---------------------------------------------------------------------------
// Elementwise prep kernels
// ---------------------------------------------------------------------------
__global__ void __launch_bounds__(256) split_act(
    const float* __restrict__ A, __half* __restrict__ hi,
    __half* __restrict__ lo, int n2)
{
    const int i = blockIdx.x * 256 + threadIdx.x;
    if (i >= n2) return;
    const float2 v = ((const float2*)A)[i];
    uint32_t uh, ul;
    split2(v.x, v.y, uh, ul);
    ((uint32_t*)hi)[i] = uh;
    ((uint32_t*)lo)[i] = ul;
}

__device__ __forceinline__ void tr_tile(
    const float* __restrict__ W, int N, __half* __restrict__ dst,
    int rowOff, int ldo, int idx, int xTiles, int tx, int ty)
{
    __shared__ float t[32][33];
    const int n0 = (idx % xTiles) * 32;
    const int k0 = (idx / xTiles) * 32;
    #pragma unroll
    for (int j = 0; j < 32; j += 8)
        t[ty + j][tx] = W[(size_t)(k0 + ty + j) * N + n0 + tx];
    __syncthreads();
    #pragma unroll
    for (int j = 0; j < 32; j += 8)
        dst[(size_t)(rowOff + n0 + ty + j) * ldo + k0 + tx] = __float2half_rn(t[tx][ty + j]);
}

__global__ void __launch_bounds__(256) prep_weights(
    const float* __restrict__ wq, const float* __restrict__ wk,
    const float* __restrict__ wv, const float* __restrict__ wo,
    const float* __restrict__ ff1, const float* __restrict__ ff2,
    const float* __restrict__ pos_emb)
{
    const int bidx = blockIdx.x;
    const int tid = threadIdx.x;
    const int tx = tid & 31, ty = tid >> 5;
    if (bidx < 1024)       tr_tile(wq,  Ec,  g_W3h, 0,      Ec,  bidx,         32,  tx, ty);
    else if (bidx < 2048)  tr_tile(wk,  Ec,  g_W3h, Ec,     Ec,  bidx - 1024,  32,  tx, ty);
    else if (bidx < 3072)  tr_tile(wv,  Ec,  g_W3h, 2 * Ec, Ec,  bidx - 2048,  32,  tx, ty);
    else if (bidx < 4096)  tr_tile(wo,  Ec,  g_Woh, 0,      Ec,  bidx - 3072,  32,  tx, ty);
    else if (bidx < 8192)  tr_tile(ff1, FFc, g_W1h, 0,      Ec,  bidx - 4096,  128, tx, ty);
    else if (bidx < 12288) tr_tile(ff2, Ec,  g_W2h, 0,      FFc, bidx - 8192,  32,  tx, ty);
    else {
        const int i = (bidx - 12288) * 256 + tid;
        if (i < 256 * HDc) {
            const int e = i >> 6;
            g_peh[i] = __float2half_rn((e < NEc) ? pos_emb[i] : 0.f);
        }
    }
}

__global__ void concat_bias(const float* a, const float* b, const float* c) {
    const int i = blockIdx.x * 256 + threadIdx.x;
    if (i < Ec) g_b3[i] = a[i];
    else if (i < 2 * Ec) g_b3[i] = b[i - Ec];
    else if (i < 3 * Ec) g_b3[i] = c[i - 2 * Ec];
}

// ---------------------------------------------------------------------------
// Softmax, warp-per-row: 8 rows per 256-thread block; scores in registers;
// shuffle reductions only; per-row private bucket; emits fp16 aw_ext (hi).
// grid (Sc/8, Hc, Bc)
// ---------------------------------------------------------------------------
__global__ void __launch_bounds__(256) softmax_kernel(
    const float* __restrict__ dist, const int* __restrict__ dt)
{
    __shared__ int dts[Sc];
    __shared__ float bucket[8][NEc + 1];

    const int rg = blockIdx.x, h = blockIdx.y, b = blockIdx.z;
    const int tid = threadIdx.x;
    const int w = tid >> 5, lane = tid & 31;
    const int i = rg * 8 + w;                  // this warp's row
    const int bh = b * Hc + h;
    const size_t rowbase = (size_t)(bh * Sc + i) * SE;
    const float* drow = dist + ((size_t)b * Sc + i) * Sc;
    float* buck = bucket[w];

    for (int t = tid; t < Sc; t += 256) dts[t] = dt[b * Sc + t];
    // zero this warp's bucket
    for (int t = lane; t < NEc; t += 32) buck[t] = 0.f;
    __syncthreads();

    const int dti = dts[i];

    float s[16];
    int e[16];
    float lmax = -1e30f;
    #pragma unroll
    for (int t = 0; t < 16; t++) {
        const int j = lane + t * 32;
        int rel = dts[j] - dti;
        rel = rel < -64 ? -64 : (rel > 64 ? 64 : rel);
        e[t] = rel + 64;
        const float v = (g_aw[rowbase + j] + g_aw[rowbase + Sc + e[t]]) * 0.125f
                        + 0.6f * drow[j];
        s[t] = v;
        lmax = fmaxf(lmax, v);
    }
    #pragma unroll
    for (int o = 16; o; o >>= 1) lmax = fmaxf(lmax, __shfl_xor_sync(0xffffffffu, lmax, o));

    float lsum = 0.f;
    #pragma unroll
    for (int t = 0; t < 16; t++) {
        s[t] = __expf(s[t] - lmax);
        lsum += s[t];
    }
    #pragma unroll
    for (int o = 16; o; o >>= 1) lsum += __shfl_xor_sync(0xffffffffu, lsum, o);
    const float inv = 1.f / lsum;

    #pragma unroll
    for (int t = 0; t < 16; t++) {
        const float a = s[t] * inv;
        g_awh[rowbase + lane + t * 32] = __float2half_rn(a);
        atomicAdd(&buck[e[t]], a);
    }
    __syncwarp();
    // write bucket tail (cols 512..671; >NEc are zero)
    for (int t = lane; t < SE - Sc; t += 32) {
        g_awh[rowbase + Sc + t] = __float2half_rn((t < NEc) ? buck[t] : 0.f);
    }
}

// ---------------------------------------------------------------------------
// out = LayerNorm(X + R); optional fp16 hi/lo emission.
// ---------------------------------------------------------------------------
template<int SPLIT>
__global__ void __launch_bounds__(256) add_ln_kernel(
    const float* __restrict__ X, const float* __restrict__ Rr,
    const float* __restrict__ gam, const float* __restrict__ bet,
    float* __restrict__ Out, __half* __restrict__ Oh,
    __half* __restrict__ Ol)
{
    __shared__ float sh[Ec];
    __shared__ float red[8];
    const int row = blockIdx.x;
    const int tid = threadIdx.x;
    const float* xr = X + (size_t)row * Ec;
    const float* rr = Rr + (size_t)row * Ec;

    float lsum = 0.f;
    for (int t = tid; t < Ec; t += 256) {
        const float v = xr[t] + rr[t];
        sh[t] = v;
        lsum += v;
    }
    #pragma unroll
    for (int o = 16; o; o >>= 1) lsum += __shfl_xor_sync(0xffffffffu, lsum, o);
    if ((tid & 31) == 0) red[tid >> 5] = lsum;
    __syncthreads();
    float tot = 0.f;
    #pragma unroll
    for (int w = 0; w < 8; w++) tot += red[w];
    const float mu = tot * (1.f / Ec);
    __syncthreads();

    float lvar = 0.f;
    for (int t = tid; t < Ec; t += 256) {
        const float d = sh[t] - mu;
        lvar += d * d;
    }
    #pragma unroll
    for (int o = 16; o; o >>= 1) lvar += __shfl_xor_sync(0xffffffffu, lvar, o);
    if ((tid & 31) == 0) red[tid >> 5] = lvar;
    __syncthreads();
    float vtot = 0.f;
    #pragma unroll
    for (int w = 0; w < 8; w++) vtot += red[w];
    const float inv = rsqrtf(vtot * (1.f / Ec) + 1e-5f);

    float* orow = Out + (size_t)row * Ec;
    for (int t = tid; t < Ec; t += 256) {
        const float v = (sh[t] - mu) * inv * gam[t] + bet[t];
        orow[t] = v;
        if (SPLIT) {
            const size_t idx = (size_t)row * Ec + t;
            const __half hv = __float2half_rn(v);
            Oh[idx] = hv;
            Ol[idx] = __float2half_rn(v - __half2float(hv));
        }
    }
}

// ---------------------------------------------------------------------------
extern "C" void kernel_launch(void* const* d_in, const int* in_sizes, int n_in,
                              void* d_out, int out_size)
{
    (void)in_sizes; (void)n_in; (void)out_size;
    const float* x       = (const float*)d_in[0];
    const float* dist    = (const float*)d_in[1];
    const int*   dt      = (const int*)d_in[2];
    const float* pos_emb = (const float*)d_in[3];
    const float* wq_w = (const float*)d_in[4];
    const float* wq_b = (const float*)d_in[5];
    const float* wk_w = (const float*)d_in[6];
    const float* wk_b = (const float*)d_in[7];
    const float* wv_w = (const float*)d_in[8];
    const float* wv_b = (const float*)d_in[9];
    const float* wo_w = (const float*)d_in[10];
    const float* wo_b = (const float*)d_in[11];
    const float* ff1_w = (const float*)d_in[12];
    const float* ff1_b = (const float*)d_in[13];
    const float* ff2_w = (const float*)d_in[14];
    const float* ff2_b = (const float*)d_in[15];
    const float* ln1_g = (const float*)d_in[16];
    const float* ln1_b = (const float*)d_in[17];
    const float* ln2_g = (const float*)d_in[18];
    const float* ln2_b = (const float*)d_in[19];
    float* out = (float*)d_out;

    __half *xh, *xl, *W3h, *Woh, *W1h, *W2h;
    __half *qkvh, *qkvl, *ah, *al, *hh, *hl, *fh, *fl;
    float *b3, *AW, *T0, *Hs;
    cudaGetSymbolAddress((void**)&xh, g_xh);   cudaGetSymbolAddress((void**)&xl, g_xl);
    cudaGetSymbolAddress((void**)&W3h, g_W3h);
    cudaGetSymbolAddress((void**)&Woh, g_Woh);
    cudaGetSymbolAddress((void**)&W1h, g_W1h);
    cudaGetSymbolAddress((void**)&W2h, g_W2h);
    cudaGetSymbolAddress((void**)&qkvh, g_qkvh); cudaGetSymbolAddress((void**)&qkvl, g_qkvl);
    cudaGetSymbolAddress((void**)&ah, g_ah);   cudaGetSymbolAddress((void**)&al, g_al);
    cudaGetSymbolAddress((void**)&hh, g_hh);   cudaGetSymbolAddress((void**)&hl, g_hl);
    cudaGetSymbolAddress((void**)&fh, g_fh);   cudaGetSymbolAddress((void**)&fl, g_fl);
    cudaGetSymbolAddress((void**)&b3, g_b3);
    cudaGetSymbolAddress((void**)&AW, g_aw);
    cudaGetSymbolAddress((void**)&T0, g_t0);
    cudaGetSymbolAddress((void**)&Hs, g_h);

    cudaFuncSetAttribute(mma_gemm<0, 0>, cudaFuncAttributeMaxDynamicSharedMemorySize, MMA_SMEM);
    cudaFuncSetAttribute(mma_gemm<0, 1>, cudaFuncAttributeMaxDynamicSharedMemorySize, MMA_SMEM);
    cudaFuncSetAttribute(mma_gemm<1, 1>, cudaFuncAttributeMaxDynamicSharedMemorySize, MMA_SMEM);
    cudaFuncSetAttribute(qk_scores, cudaFuncAttributeMaxDynamicSharedMemorySize, QK_SMEM);
    cudaFuncSetAttribute(av_mma, cudaFuncAttributeMaxDynamicSharedMemorySize, AV_SMEM);

    dim3 blk(256);
    dim3 tblk(32, 8);

    // prep
    split_act<<<(Mc * Ec / 2 + 255) / 256, blk>>>(x, xh, xl, Mc * Ec / 2);
    prep_weights<<<12288 + 64, blk>>>(wq_w, wk_w, wv_w, wo_w, ff1_w, ff2_w, pos_emb);
    concat_bias<<<12, blk>>>(wq_b, wk_b, wv_b);

    // fused QKV projection
    mma_gemm<0, 1><<<dim3(E3 / 128, Mc / 128), blk, MMA_SMEM>>>(
        xh, xl, W3h, b3, nullptr, qkvh, qkvl, Ec, E3, Ec);

    // per-head V^T (+pe^T) staging
    vt_build<<<dim3(SE / 32, 2, 128), tblk>>>();

    // fused scores
    qk_scores<<<dim3(6, 4, 128), blk, QK_SMEM>>>(AW);

    // softmax, warp-per-row
    softmax_kernel<<<dim3(Sc / 8, Hc, Bc), blk>>>(dist, dt);

    // attn = aw_ext @ vt^T (single-pass)
    av_mma<<<dim3(4, 128), blk, AV_SMEM>>>();

    // output projection
    mma_gemm<0, 0><<<dim3(Ec / 128, Mc / 128), blk, MMA_SMEM>>>(
        ah, al, Woh, wo_b, T0, nullptr, nullptr, Ec, Ec, 0);

    // h = LN(x + attn_out)
    add_ln_kernel<1><<<Mc, blk>>>(x, T0, ln1_g, ln1_b, Hs, hh, hl);

    // FFN
    mma_gemm<1, 1><<<dim3(FFc / 128, Mc / 128), blk, MMA_SMEM>>>(
        hh, hl, W1h, ff1_b, nullptr, fh, fl, Ec, FFc, FFc);
    mma_gemm<0, 0><<<dim3(Ec / 128, Mc / 128), blk, MMA_SMEM>>>(
        fh, fl, W2h, ff2_b, T0, nullptr, nullptr, FFc, Ec, 0);

    // out = LN(h + ffn)
    add_ln_kernel<0><<<Mc, blk>>>(Hs, T0, ln2_g, ln2_b, out, nullptr, nullptr);
}

// round 9
// speedup vs baseline: 4.6305x; 1.2092x over previous
#include <cuda_runtime.h>
#include <cuda_fp16.h>
#include <cstdint>
#include <math.h>

// Problem constants
constexpr int Bc  = 8;
constexpr int Sc  = 512;
constexpr int Ec  = 1024;
constexpr int Hc  = 16;
constexpr int HDc = 64;
constexpr int FFc = 4096;
constexpr int NEc = 129;           // 2P+1
constexpr int Mc  = Bc * Sc;       // 4096 rows
constexpr int E3  = 3 * Ec;        // 3072
constexpr int SE  = 672;           // extended score width: 512 + 129 + pad

// ---------------------------------------------------------------------------
// Scratch (device globals; no allocation allowed)
// ---------------------------------------------------------------------------
__device__ __align__(256) __half g_xh[Mc * Ec];
__device__ __align__(256) __half g_xl[Mc * Ec];
__device__ __align__(256) __half g_W3h[E3 * Ec];
__device__ __align__(256) __half g_Woh[Ec * Ec];
__device__ __align__(256) __half g_W1h[FFc * Ec];
__device__ __align__(256) __half g_W2h[Ec * FFc];
__device__ float g_b3[E3];
__device__ __align__(256) __half g_qkvh[Mc * E3];
__device__ __align__(256) __half g_qkvl[Mc * E3];     // only q-part written/used
__device__ __align__(256) __half g_peh[256 * HDc];
__device__ float g_aw[128 * Sc * SE];                  // fp32 scores
__device__ __align__(256) __half g_awh[128 * Sc * SE];
__device__ __align__(256) __half g_vth[128 * HDc * SE];
__device__ __align__(256) __half g_ah[Mc * Ec];
__device__ float g_t0[Mc * Ec];
__device__ float g_h[Mc * Ec];
__device__ __align__(256) __half g_hh[Mc * Ec];
__device__ __align__(256) __half g_fh[Mc * FFc];

// ---------------------------------------------------------------------------
// PTX helpers
// ---------------------------------------------------------------------------
__device__ __forceinline__ uint32_t smem_u32(const void* p) {
    uint32_t a;
    asm("{ .reg .u64 t; cvta.to.shared.u64 t, %1; cvt.u32.u64 %0, t; }" : "=r"(a) : "l"(p));
    return a;
}
__device__ __forceinline__ void cpasync16(uint32_t dst, const void* src) {
    asm volatile("cp.async.cg.shared.global [%0], [%1], 16;" :: "r"(dst), "l"(src));
}
#define CP_COMMIT()  asm volatile("cp.async.commit_group;" ::: "memory")
#define CP_WAIT(n)   asm volatile("cp.async.wait_group %0;" :: "n"(n) : "memory")

__device__ __forceinline__ void ldsm4(uint32_t* r, uint32_t addr) {
    asm volatile("ldmatrix.sync.aligned.m8n8.x4.shared.b16 {%0,%1,%2,%3}, [%4];"
                 : "=r"(r[0]), "=r"(r[1]), "=r"(r[2]), "=r"(r[3]) : "r"(addr));
}
__device__ __forceinline__ void mma_f16(float* c, const uint32_t* a, const uint32_t* b) {
    asm volatile(
        "mma.sync.aligned.m16n8k16.row.col.f32.f16.f16.f32 "
        "{%0,%1,%2,%3}, {%4,%5,%6,%7}, {%8,%9}, {%0,%1,%2,%3};"
        : "+f"(c[0]), "+f"(c[1]), "+f"(c[2]), "+f"(c[3])
        : "r"(a[0]), "r"(a[1]), "r"(a[2]), "r"(a[3]), "r"(b[0]), "r"(b[1]));
}
__device__ __forceinline__ void split2(float v0, float v1, uint32_t& uh, uint32_t& ul) {
    const __half h0 = __float2half_rn(v0), h1 = __float2half_rn(v1);
    __half2 ph = __halves2half2(h0, h1);
    __half2 pl = __halves2half2(
        __float2half_rn(v0 - __half2float(h0)),
        __float2half_rn(v1 - __half2float(h1)));
    uh = *(uint32_t*)&ph; ul = *(uint32_t*)&pl;
}
__device__ __forceinline__ uint32_t pack2(float v0, float v1) {
    __half2 ph = __halves2half2(__float2half_rn(v0), __float2half_rn(v1));
    return *(uint32_t*)&ph;
}

// ---------------------------------------------------------------------------
// HMMA GEMM: C[M,N] = (Ah[+Al])[M,K] @ Bh[N,K]^T + bias
// PASSES=2: A hi + A lo.  PASSES=1: A hi only.
// 128x128 CTA tile, BK=32, 8 warps of 32x64.
// 3-stage cp.async pipeline, ONE __syncthreads per chunk.
// ---------------------------------------------------------------------------
constexpr int LDSp  = 40;
constexpr int TILEB = 128 * LDSp * 2;      // 10240

template<int RELU, int SPLIT, int PASSES>
__global__ void __launch_bounds__(256)
mma_gemm(const __half* __restrict__ Ah, const __half* __restrict__ Al,
         const __half* __restrict__ Bh,
         const float* __restrict__ bias, float* __restrict__ C,
         __half* __restrict__ Ch, __half* __restrict__ Cl,
         int K, int N, int loCols)
{
    constexpr int NT   = (PASSES == 2) ? 3 : 2;     // tiles per stage
    const int BUFB = NT * TILEB;
    extern __shared__ char sm[];
    const uint32_t sbase = smem_u32(sm);
    const int tid = threadIdx.x;
    const int wid = tid >> 5, lane = tid & 31;
    const int wm = wid & 3, wn = wid >> 2;
    const int bm = blockIdx.y * 128, bn = blockIdx.x * 128;
    const int nk = K / 32;

    const int r0l = tid >> 2, sg = (tid & 3) << 3;

    auto load_chunk = [&](int kc) {
        if (kc < nk) {
            const uint32_t base = sbase + (kc % 3) * BUFB;
            const int k0 = kc * 32;
            #pragma unroll
            for (int it = 0; it < 2; it++) {
                const int r = r0l + it * 64;
                const uint32_t dst = base + r * 80 + sg * 2;
                const size_t ao = (size_t)(bm + r) * K + k0 + sg;
                const size_t bo = (size_t)(bn + r) * K + k0 + sg;
                cpasync16(dst, Ah + ao);
                if (PASSES == 2) cpasync16(dst + TILEB, Al + ao);
                cpasync16(dst + (NT - 1) * TILEB, Bh + bo);
            }
        }
        CP_COMMIT();
    };

    float acc[2][8][4];
    #pragma unroll
    for (int mt = 0; mt < 2; mt++)
        #pragma unroll
        for (int nt = 0; nt < 8; nt++)
            #pragma unroll
            for (int i = 0; i < 4; i++) acc[mt][nt][i] = 0.f;

    uint32_t aF[2][2][4];
    uint32_t bF[8][2][2];

    const int a_row = wm * 32 + (lane & 15);
    const int a_kof = (lane >> 4) << 3;
    const int b_n   = wn * 64 + (lane & 7) + ((lane & 16) >> 1);
    const int b_kof = ((lane >> 3) & 1) << 3;

    auto loadA = [&](uint32_t tbase) {
        #pragma unroll
        for (int mt = 0; mt < 2; mt++)
            #pragma unroll
            for (int ks = 0; ks < 2; ks++)
                ldsm4(aF[mt][ks], tbase + (a_row + mt * 16) * 80 + (ks * 16 + a_kof) * 2);
    };
    auto loadB = [&](uint32_t tbase) {
        #pragma unroll
        for (int ntp = 0; ntp < 4; ntp++)
            #pragma unroll
            for (int ks = 0; ks < 2; ks++) {
                uint32_t t4[4];
                ldsm4(t4, tbase + (b_n + ntp * 16) * 80 + (ks * 16 + b_kof) * 2);
                bF[ntp * 2 + 0][ks][0] = t4[0]; bF[ntp * 2 + 0][ks][1] = t4[1];
                bF[ntp * 2 + 1][ks][0] = t4[2]; bF[ntp * 2 + 1][ks][1] = t4[3];
            }
    };
    auto mma_all = [&]() {
        #pragma unroll
        for (int ks = 0; ks < 2; ks++)
            #pragma unroll
            for (int mt = 0; mt < 2; mt++)
                #pragma unroll
                for (int nt = 0; nt < 8; nt++)
                    mma_f16(acc[mt][nt], aF[mt][ks], bF[nt][ks]);
    };

    load_chunk(0);
    load_chunk(1);
    for (int kc = 0; kc < nk; kc++) {
        CP_WAIT(1);
        __syncthreads();
        load_chunk(kc + 2);

        const uint32_t base = sbase + (kc % 3) * BUFB;
        loadA(base);
        loadB(base + (NT - 1) * TILEB);
        mma_all();               // hi*B
        if (PASSES == 2) {
            loadA(base + TILEB);
            mma_all();           // lo*B
        }
    }

    #pragma unroll
    for (int mt = 0; mt < 2; mt++) {
        #pragma unroll
        for (int nt = 0; nt < 8; nt++) {
            const int row = bm + wm * 32 + mt * 16 + (lane >> 2);
            const int col = bn + wn * 64 + nt * 8 + ((lane & 3) << 1);
            const float bi0 = bias[col], bi1 = bias[col + 1];
            float o00 = acc[mt][nt][0] + bi0, o01 = acc[mt][nt][1] + bi1;
            float o10 = acc[mt][nt][2] + bi0, o11 = acc[mt][nt][3] + bi1;
            if (RELU) {
                o00 = fmaxf(o00, 0.f); o01 = fmaxf(o01, 0.f);
                o10 = fmaxf(o10, 0.f); o11 = fmaxf(o11, 0.f);
            }
            const size_t i0 = (size_t)row * N + col;
            const size_t i1 = (size_t)(row + 8) * N + col;
            if (SPLIT) {
                uint32_t uh0, ul0, uh1, ul1;
                split2(o00, o01, uh0, ul0);
                split2(o10, o11, uh1, ul1);
                *(uint32_t*)(Ch + i0) = uh0;
                *(uint32_t*)(Ch + i1) = uh1;
                if (col < loCols) {
                    *(uint32_t*)(Cl + i0) = ul0;
                    *(uint32_t*)(Cl + i1) = ul1;
                }
            } else {
                *(float2*)(C + i0) = make_float2(o00, o01);
                *(float2*)(C + i1) = make_float2(o10, o11);
            }
        }
    }
}

constexpr int MMA_SMEM2 = 3 * 3 * TILEB;   // 2-pass stages
constexpr int MMA_SMEM1 = 3 * 2 * TILEB;   // 1-pass stages

// ---------------------------------------------------------------------------
// Fused scores GEMM (HMMA, 2-pass)
// ---------------------------------------------------------------------------
constexpr int QK_LDS = 72;
constexpr int QK_T   = 128 * QK_LDS * 2;     // 18432
constexpr int QK_SMEM = 3 * QK_T;            // 55296 B

__global__ void __launch_bounds__(256)
qk_scores(float* __restrict__ AW)
{
    extern __shared__ char sm[];
    const uint32_t sA = smem_u32(sm);
    const uint32_t sB = sA + 2 * QK_T;
    const int tid = threadIdx.x;
    const int wid = tid >> 5, lane = tid & 31;
    const int wm = wid & 3, wn = wid >> 2;
    const int bn = blockIdx.x * 128, bm = blockIdx.y * 128;
    const int bh = blockIdx.z, b = bh >> 4, h = bh & 15;

    {
        const int r0 = tid >> 3, sg = (tid & 7) << 3;
        #pragma unroll
        for (int it = 0; it < 4; it++) {
            const int r = r0 + it * 32;
            const uint32_t off = (r * QK_LDS + sg) * 2;
            const size_t ao = (size_t)(b * Sc + bm + r) * E3 + h * HDc + sg;
            cpasync16(sA + off,        g_qkvh + ao);
            cpasync16(sA + QK_T + off, g_qkvl + ao);
            const int gr = bn + r;
            const __half* bph;
            if (gr < Sc) {
                bph = g_qkvh + (size_t)(b * Sc + gr) * E3 + Ec + h * HDc + sg;
            } else {
                bph = g_peh + (size_t)(gr - Sc) * HDc + sg;
            }
            cpasync16(sB + off, bph);
        }
        CP_COMMIT(); CP_WAIT(0);
        __syncthreads();
    }

    float acc[2][8][4];
    #pragma unroll
    for (int mt = 0; mt < 2; mt++)
        #pragma unroll
        for (int nt = 0; nt < 8; nt++)
            #pragma unroll
            for (int i = 0; i < 4; i++) acc[mt][nt][i] = 0.f;

    uint32_t aF[2][2][4], bF[8][2][2];
    const int a_row = wm * 32 + (lane & 15);
    const int a_kof = (lane >> 4) << 3;
    const int b_n   = wn * 64 + (lane & 7) + ((lane & 16) >> 1);
    const int b_kof = ((lane >> 3) & 1) << 3;

    auto loadA = [&](uint32_t tb, int k0) {
        #pragma unroll
        for (int mt = 0; mt < 2; mt++)
            #pragma unroll
            for (int ks = 0; ks < 2; ks++)
                ldsm4(aF[mt][ks], tb + ((a_row + mt * 16) * QK_LDS + k0 + ks * 16 + a_kof) * 2);
    };
    auto loadB = [&](uint32_t tb, int k0) {
        #pragma unroll
        for (int ntp = 0; ntp < 4; ntp++)
            #pragma unroll
            for (int ks = 0; ks < 2; ks++) {
                uint32_t t4[4];
                ldsm4(t4, tb + ((b_n + ntp * 16) * QK_LDS + k0 + ks * 16 + b_kof) * 2);
                bF[ntp * 2 + 0][ks][0] = t4[0]; bF[ntp * 2 + 0][ks][1] = t4[1];
                bF[ntp * 2 + 1][ks][0] = t4[2]; bF[ntp * 2 + 1][ks][1] = t4[3];
            }
    };
    auto mma_all = [&]() {
        #pragma unroll
        for (int ks = 0; ks < 2; ks++)
            #pragma unroll
            for (int mt = 0; mt < 2; mt++)
                #pragma unroll
                for (int nt = 0; nt < 8; nt++)
                    mma_f16(acc[mt][nt], aF[mt][ks], bF[nt][ks]);
    };

    #pragma unroll
    for (int kg = 0; kg < 2; kg++) {
        const int k0 = kg * 32;
        loadA(sA, k0);
        loadB(sB, k0);
        mma_all();
        loadA(sA + QK_T, k0);
        mma_all();
    }

    #pragma unroll
    for (int mt = 0; mt < 2; mt++) {
        #pragma unroll
        for (int nt = 0; nt < 8; nt++) {
            const int row = bm + wm * 32 + mt * 16 + (lane >> 2);
            const int col = bn + wn * 64 + nt * 8 + ((lane & 3) << 1);
            if (col < SE) {
                const size_t base = (size_t)(bh * Sc + row) * SE + col;
                *(float2*)(AW + base)             = make_float2(acc[mt][nt][0], acc[mt][nt][1]);
                *(float2*)(AW + base + 8ull * SE) = make_float2(acc[mt][nt][2], acc[mt][nt][3]);
            }
        }
    }
}

// ---------------------------------------------------------------------------
// Per-head V^T build (hi only)
// ---------------------------------------------------------------------------
__global__ void vt_build()
{
    __shared__ __half th[32][33];
    const int jt = blockIdx.x, dt = blockIdx.y, bh = blockIdx.z;
    const int b = bh >> 4, h = bh & 15;
    const int j0 = jt * 32, d0 = dt * 32;
    const int tx = threadIdx.x, ty = threadIdx.y;

    #pragma unroll
    for (int k = 0; k < 4; k++) {
        const int j = j0 + ty + k * 8;
        const int d = d0 + tx;
        __half vh;
        if (j < Sc) {
            vh = g_qkvh[(size_t)(b * Sc + j) * E3 + 2 * Ec + h * HDc + d];
        } else if (j < Sc + NEc) {
            vh = g_peh[(size_t)(j - Sc) * HDc + d];
        } else {
            vh = __float2half_rn(0.f);
        }
        th[ty + k * 8][tx] = vh;
    }
    __syncthreads();
    #pragma unroll
    for (int k = 0; k < 4; k++) {
        const int d = d0 + ty + k * 8;
        const int j = j0 + tx;
        g_vth[(size_t)bh * HDc * SE + (size_t)d * SE + j] = th[tx][ty + k * 8];
    }
}

// ---------------------------------------------------------------------------
// AV GEMM (HMMA, single-pass): A = aw hi, B = vt hi. 3-stage pipeline.
// Emits attn concat as fp16 (hi only).
// ---------------------------------------------------------------------------
constexpr int AV_AT = 128 * LDSp * 2;          // 10240
constexpr int AV_BT = 64 * LDSp * 2;           // 5120
constexpr int AV_ST = AV_AT + AV_BT;           // 15360
constexpr int AV_SMEM = 3 * AV_ST;             // 46080

__global__ void __launch_bounds__(256)
av_mma()
{
    extern __shared__ char sm[];
    const uint32_t sbase = smem_u32(sm);
    const int tid = threadIdx.x;
    const int wid = tid >> 5, lane = tid & 31;
    const int bm = blockIdx.x * 128;
    const int bh = blockIdx.y, b = bh >> 4, h = bh & 15;
    const int nk = SE / 32;   // 21

    auto load_chunk = [&](int kc) {
        if (kc < nk) {
            const uint32_t base = sbase + (kc % 3) * AV_ST;
            const int k0 = kc * 32;
            const int sg = (tid & 3) << 3;
            #pragma unroll
            for (int it = 0; it < 2; it++) {
                const int r = (tid >> 2) + it * 64;
                cpasync16(base + r * 80 + sg * 2,
                          g_awh + (size_t)(bh * Sc + bm + r) * SE + k0 + sg);
            }
            {
                const int r = tid >> 2;
                if (r < 64) {
                    cpasync16(base + AV_AT + r * 80 + sg * 2,
                              g_vth + (size_t)bh * HDc * SE + (size_t)r * SE + k0 + sg);
                }
            }
        }
        CP_COMMIT();
    };

    float acc[8][4];
    #pragma unroll
    for (int nt = 0; nt < 8; nt++)
        #pragma unroll
        for (int i = 0; i < 4; i++) acc[nt][i] = 0.f;

    uint32_t aF[2][4], bF[8][2][2];
    const int a_row = wid * 16 + (lane & 15);
    const int a_kof = (lane >> 4) << 3;
    const int b_n   = (lane & 7) + ((lane & 16) >> 1);
    const int b_kof = ((lane >> 3) & 1) << 3;

    auto loadA = [&](uint32_t tb) {
        #pragma unroll
        for (int ks = 0; ks < 2; ks++)
            ldsm4(aF[ks], tb + (a_row * 80) + (ks * 16 + a_kof) * 2);
    };
    auto loadB = [&](uint32_t tb) {
        #pragma unroll
        for (int ntp = 0; ntp < 4; ntp++)
            #pragma unroll
            for (int ks = 0; ks < 2; ks++) {
                uint32_t t4[4];
                ldsm4(t4, tb + (b_n + ntp * 16) * 80 + (ks * 16 + b_kof) * 2);
                bF[ntp * 2 + 0][ks][0] = t4[0]; bF[ntp * 2 + 0][ks][1] = t4[1];
                bF[ntp * 2 + 1][ks][0] = t4[2]; bF[ntp * 2 + 1][ks][1] = t4[3];
            }
    };
    auto mma_all = [&]() {
        #pragma unroll
        for (int ks = 0; ks < 2; ks++)
            #pragma unroll
            for (int nt = 0; nt < 8; nt++)
                mma_f16(acc[nt], aF[ks], bF[nt][ks]);
    };

    load_chunk(0);
    load_chunk(1);
    for (int kc = 0; kc < nk; kc++) {
        CP_WAIT(1);
        __syncthreads();
        load_chunk(kc + 2);
        const uint32_t base = sbase + (kc % 3) * AV_ST;
        loadA(base);
        loadB(base + AV_AT);
        mma_all();
    }

    #pragma unroll
    for (int nt = 0; nt < 8; nt++) {
        const int row = bm + wid * 16 + (lane >> 2);
        const int col = nt * 8 + ((lane & 3) << 1);
        const size_t i0 = (size_t)(b * Sc + row) * Ec + h * HDc + col;
        const size_t i1 = (size_t)(b * Sc + row + 8) * Ec + h * HDc + col;
        *(uint32_t*)(g_ah + i0) = pack2(acc[nt][0], acc[nt][1]);
        *(uint32_t*)(g_ah + i1) = pack2(acc[nt][2], acc[nt][3]);
    }
}

// ---------------------------------------------------------------------------
// Elementwise prep kernels
// ---------------------------------------------------------------------------
__global__ void __launch_bounds__(256) split_act(
    const float* __restrict__ A, __half* __restrict__ hi,
    __half* __restrict__ lo, int n2)
{
    const int i = blockIdx.x * 256 + threadIdx.x;
    if (i >= n2) return;
    const float2 v = ((const float2*)A)[i];
    uint32_t uh, ul;
    split2(v.x, v.y, uh, ul);
    ((uint32_t*)hi)[i] = uh;
    ((uint32_t*)lo)[i] = ul;
}

__device__ __forceinline__ void tr_tile(
    const float* __restrict__ W, int N, __half* __restrict__ dst,
    int rowOff, int ldo, int idx, int xTiles, int tx, int ty)
{
    __shared__ float t[32][33];
    const int n0 = (idx % xTiles) * 32;
    const int k0 = (idx / xTiles) * 32;
    #pragma unroll
    for (int j = 0; j < 32; j += 8)
        t[ty + j][tx] = W[(size_t)(k0 + ty + j) * N + n0 + tx];
    __syncthreads();
    #pragma unroll
    for (int j = 0; j < 32; j += 8)
        dst[(size_t)(rowOff + n0 + ty + j) * ldo + k0 + tx] = __float2half_rn(t[tx][ty + j]);
}

__global__ void __launch_bounds__(256) prep_weights(
    const float* __restrict__ wq, const float* __restrict__ wk,
    const float* __restrict__ wv, const float* __restrict__ wo,
    const float* __restrict__ ff1, const float* __restrict__ ff2,
    const float* __restrict__ pos_emb)
{
    const int bidx = blockIdx.x;
    const int tid = threadIdx.x;
    const int tx = tid & 31, ty = tid >> 5;
    if (bidx < 1024)       tr_tile(wq,  Ec,  g_W3h, 0,      Ec,  bidx,         32,  tx, ty);
    else if (bidx < 2048)  tr_tile(wk,  Ec,  g_W3h, Ec,     Ec,  bidx - 1024,  32,  tx, ty);
    else if (bidx < 3072)  tr_tile(wv,  Ec,  g_W3h, 2 * Ec, Ec,  bidx - 2048,  32,  tx, ty);
    else if (bidx < 4096)  tr_tile(wo,  Ec,  g_Woh, 0,      Ec,  bidx - 3072,  32,  tx, ty);
    else if (bidx < 8192)  tr_tile(ff1, FFc, g_W1h, 0,      Ec,  bidx - 4096,  128, tx, ty);
    else if (bidx < 12288) tr_tile(ff2, Ec,  g_W2h, 0,      FFc, bidx - 8192,  32,  tx, ty);
    else {
        const int i = (bidx - 12288) * 256 + tid;
        if (i < 256 * HDc) {
            const int e = i >> 6;
            g_peh[i] = __float2half_rn((e < NEc) ? pos_emb[i] : 0.f);
        }
    }
}

__global__ void concat_bias(const float* a, const float* b, const float* c) {
    const int i = blockIdx.x * 256 + threadIdx.x;
    if (i < Ec) g_b3[i] = a[i];
    else if (i < 2 * Ec) g_b3[i] = b[i - Ec];
    else if (i < 3 * Ec) g_b3[i] = c[i - 2 * Ec];
}

// ---------------------------------------------------------------------------
// Softmax, warp-per-row: 8 rows per 256-thread block; scores in registers;
// shuffle reductions only; per-row private bucket; emits fp16 aw_ext (hi).
// grid (Sc/8, Hc, Bc)
// ---------------------------------------------------------------------------
__global__ void __launch_bounds__(256) softmax_kernel(
    const float* __restrict__ dist, const int* __restrict__ dt)
{
    __shared__ int dts[Sc];
    __shared__ float bucket[8][NEc + 1];

    const int rg = blockIdx.x, h = blockIdx.y, b = blockIdx.z;
    const int tid = threadIdx.x;
    const int w = tid >> 5, lane = tid & 31;
    const int i = rg * 8 + w;
    const int bh = b * Hc + h;
    const size_t rowbase = (size_t)(bh * Sc + i) * SE;
    const float* drow = dist + ((size_t)b * Sc + i) * Sc;
    float* buck = bucket[w];

    for (int t = tid; t < Sc; t += 256) dts[t] = dt[b * Sc + t];
    for (int t = lane; t < NEc; t += 32) buck[t] = 0.f;
    __syncthreads();

    const int dti = dts[i];

    float s[16];
    int e[16];
    float lmax = -1e30f;
    #pragma unroll
    for (int t = 0; t < 16; t++) {
        const int j = lane + t * 32;
        int rel = dts[j] - dti;
        rel = rel < -64 ? -64 : (rel > 64 ? 64 : rel);
        e[t] = rel + 64;
        const float v = (g_aw[rowbase + j] + g_aw[rowbase + Sc + e[t]]) * 0.125f
                        + 0.6f * drow[j];
        s[t] = v;
        lmax = fmaxf(lmax, v);
    }
    #pragma unroll
    for (int o = 16; o; o >>= 1) lmax = fmaxf(lmax, __shfl_xor_sync(0xffffffffu, lmax, o));

    float lsum = 0.f;
    #pragma unroll
    for (int t = 0; t < 16; t++) {
        s[t] = __expf(s[t] - lmax);
        lsum += s[t];
    }
    #pragma unroll
    for (int o = 16; o; o >>= 1) lsum += __shfl_xor_sync(0xffffffffu, lsum, o);
    const float inv = 1.f / lsum;

    #pragma unroll
    for (int t = 0; t < 16; t++) {
        const float a = s[t] * inv;
        g_awh[rowbase + lane + t * 32] = __float2half_rn(a);
        atomicAdd(&buck[e[t]], a);
    }
    __syncwarp();
    for (int t = lane; t < SE - Sc; t += 32) {
        g_awh[rowbase + Sc + t] = __float2half_rn((t < NEc) ? buck[t] : 0.f);
    }
}

// ---------------------------------------------------------------------------
// out = LayerNorm(X + R); optional fp16 (hi-only) emission.
// ---------------------------------------------------------------------------
template<int EMIT>
__global__ void __launch_bounds__(256) add_ln_kernel(
    const float* __restrict__ X, const float* __restrict__ Rr,
    const float* __restrict__ gam, const float* __restrict__ bet,
    float* __restrict__ Out, __half* __restrict__ Oh)
{
    __shared__ float sh[Ec];
    __shared__ float red[8];
    const int row = blockIdx.x;
    const int tid = threadIdx.x;
    const float* xr = X + (size_t)row * Ec;
    const float* rr = Rr + (size_t)row * Ec;

    float lsum = 0.f;
    for (int t = tid; t < Ec; t += 256) {
        const float v = xr[t] + rr[t];
        sh[t] = v;
        lsum += v;
    }
    #pragma unroll
    for (int o = 16; o; o >>= 1) lsum += __shfl_xor_sync(0xffffffffu, lsum, o);
    if ((tid & 31) == 0) red[tid >> 5] = lsum;
    __syncthreads();
    float tot = 0.f;
    #pragma unroll
    for (int w = 0; w < 8; w++) tot += red[w];
    const float mu = tot * (1.f / Ec);
    __syncthreads();

    float lvar = 0.f;
    for (int t = tid; t < Ec; t += 256) {
        const float d = sh[t] - mu;
        lvar += d * d;
    }
    #pragma unroll
    for (int o = 16; o; o >>= 1) lvar += __shfl_xor_sync(0xffffffffu, lvar, o);
    if ((tid & 31) == 0) red[tid >> 5] = lvar;
    __syncthreads();
    float vtot = 0.f;
    #pragma unroll
    for (int w = 0; w < 8; w++) vtot += red[w];
    const float inv = rsqrtf(vtot * (1.f / Ec) + 1e-5f);

    float* orow = Out + (size_t)row * Ec;
    for (int t = tid; t < Ec; t += 256) {
        const float v = (sh[t] - mu) * inv * gam[t] + bet[t];
        orow[t] = v;
        if (EMIT) Oh[(size_t)row * Ec + t] = __float2half_rn(v);
    }
}

// ---------------------------------------------------------------------------
extern "C" void kernel_launch(void* const* d_in, const int* in_sizes, int n_in,
                              void* d_out, int out_size)
{
    (void)in_sizes; (void)n_in; (void)out_size;
    const float* x       = (const float*)d_in[0];
    const float* dist    = (const float*)d_in[1];
    const int*   dt      = (const int*)d_in[2];
    const float* pos_emb = (const float*)d_in[3];
    const float* wq_w = (const float*)d_in[4];
    const float* wq_b = (const float*)d_in[5];
    const float* wk_w = (const float*)d_in[6];
    const float* wk_b = (const float*)d_in[7];
    const float* wv_w = (const float*)d_in[8];
    const float* wv_b = (const float*)d_in[9];
    const float* wo_w = (const float*)d_in[10];
    const float* wo_b = (const float*)d_in[11];
    const float* ff1_w = (const float*)d_in[12];
    const float* ff1_b = (const float*)d_in[13];
    const float* ff2_w = (const float*)d_in[14];
    const float* ff2_b = (const float*)d_in[15];
    const float* ln1_g = (const float*)d_in[16];
    const float* ln1_b = (const float*)d_in[17];
    const float* ln2_g = (const float*)d_in[18];
    const float* ln2_b = (const float*)d_in[19];
    float* out = (float*)d_out;

    __half *xh, *xl, *W3h, *Woh, *W1h, *W2h;
    __half *qkvh, *qkvl, *ah, *hh, *fh;
    float *b3, *AW, *T0, *Hs;
    cudaGetSymbolAddress((void**)&xh, g_xh);   cudaGetSymbolAddress((void**)&xl, g_xl);
    cudaGetSymbolAddress((void**)&W3h, g_W3h);
    cudaGetSymbolAddress((void**)&Woh, g_Woh);
    cudaGetSymbolAddress((void**)&W1h, g_W1h);
    cudaGetSymbolAddress((void**)&W2h, g_W2h);
    cudaGetSymbolAddress((void**)&qkvh, g_qkvh); cudaGetSymbolAddress((void**)&qkvl, g_qkvl);
    cudaGetSymbolAddress((void**)&ah, g_ah);
    cudaGetSymbolAddress((void**)&hh, g_hh);
    cudaGetSymbolAddress((void**)&fh, g_fh);
    cudaGetSymbolAddress((void**)&b3, g_b3);
    cudaGetSymbolAddress((void**)&AW, g_aw);
    cudaGetSymbolAddress((void**)&T0, g_t0);
    cudaGetSymbolAddress((void**)&Hs, g_h);

    cudaFuncSetAttribute(mma_gemm<0, 1, 2>, cudaFuncAttributeMaxDynamicSharedMemorySize, MMA_SMEM2);
    cudaFuncSetAttribute(mma_gemm<0, 0, 1>, cudaFuncAttributeMaxDynamicSharedMemorySize, MMA_SMEM1);
    cudaFuncSetAttribute(mma_gemm<1, 1, 1>, cudaFuncAttributeMaxDynamicSharedMemorySize, MMA_SMEM1);
    cudaFuncSetAttribute(qk_scores, cudaFuncAttributeMaxDynamicSharedMemorySize, QK_SMEM);
    cudaFuncSetAttribute(av_mma, cudaFuncAttributeMaxDynamicSharedMemorySize, AV_SMEM);

    dim3 blk(256);
    dim3 tblk(32, 8);

    // prep
    split_act<<<(Mc * Ec / 2 + 255) / 256, blk>>>(x, xh, xl, Mc * Ec / 2);
    prep_weights<<<12288 + 64, blk>>>(wq_w, wk_w, wv_w, wo_w, ff1_w, ff2_w, pos_emb);
    concat_bias<<<12, blk>>>(wq_b, wk_b, wv_b);

    // fused QKV projection (2-pass; lo emitted only for q columns)
    mma_gemm<0, 1, 2><<<dim3(E3 / 128, Mc / 128), blk, MMA_SMEM2>>>(
        xh, xl, W3h, b3, nullptr, qkvh, qkvl, Ec, E3, Ec);

    // per-head V^T (+pe^T) staging
    vt_build<<<dim3(SE / 32, 2, 128), tblk>>>();

    // fused scores (2-pass)
    qk_scores<<<dim3(6, 4, 128), blk, QK_SMEM>>>(AW);

    // softmax, warp-per-row
    softmax_kernel<<<dim3(Sc / 8, Hc, Bc), blk>>>(dist, dt);

    // attn = aw_ext @ vt^T (single-pass)
    av_mma<<<dim3(4, 128), blk, AV_SMEM>>>();

    // output projection (single-pass)
    mma_gemm<0, 0, 1><<<dim3(Ec / 128, Mc / 128), blk, MMA_SMEM1>>>(
        ah, nullptr, Woh, wo_b, T0, nullptr, nullptr, Ec, Ec, 0);

    // h = LN(x + attn_out), emit fp16 hi for FF1
    add_ln_kernel<1><<<Mc, blk>>>(x, T0, ln1_g, ln1_b, Hs, hh);

    // FFN (single-pass both)
    mma_gemm<1, 1, 1><<<dim3(FFc / 128, Mc / 128), blk, MMA_SMEM1>>>(
        hh, nullptr, W1h, ff1_b, nullptr, fh, nullptr, Ec, FFc, 0);
    mma_gemm<0, 0, 1><<<dim3(Ec / 128, Mc / 128), blk, MMA_SMEM1>>>(
        fh, nullptr, W2h, ff2_b, T0, nullptr, nullptr, FFc, Ec, 0);

    // out = LN(h + ffn)
    add_ln_kernel<0><<<Mc, blk>>>(Hs, T0, ln2_g, ln2_b, out, nullptr);
}

// round 10
// speedup vs baseline: 5.0906x; 1.0993x over previous
#include <cuda_runtime.h>
#include <cuda_fp16.h>
#include <cstdint>
#include <math.h>

// Problem constants
constexpr int Bc  = 8;
constexpr int Sc  = 512;
constexpr int Ec  = 1024;
constexpr int Hc  = 16;
constexpr int HDc = 64;
constexpr int FFc = 4096;
constexpr int NEc = 129;           // 2P+1
constexpr int Mc  = Bc * Sc;       // 4096 rows
constexpr int E3  = 3 * Ec;        // 3072
constexpr int SE  = 672;           // extended score width: 512 + 129 + pad

// ---------------------------------------------------------------------------
// Scratch (device globals; no allocation allowed)
// ---------------------------------------------------------------------------
__device__ __align__(256) __half g_xh[Mc * Ec];
__device__ __align__(256) __half g_W3h[E3 * Ec];
__device__ __align__(256) __half g_Woh[Ec * Ec];
__device__ __align__(256) __half g_W1h[FFc * Ec];
__device__ __align__(256) __half g_W2h[Ec * FFc];
__device__ float g_b3[E3];
__device__ __align__(256) __half g_qkvh[Mc * E3];
__device__ __align__(256) __half g_peh[256 * HDc];
__device__ float g_aw[128 * Sc * SE];                  // fp32 scores
__device__ __align__(256) __half g_awh[128 * Sc * SE];
__device__ __align__(256) __half g_vth[128 * HDc * SE];
__device__ __align__(256) __half g_ah[Mc * Ec];
__device__ float g_t0[Mc * Ec];
__device__ float g_h[Mc * Ec];
__device__ __align__(256) __half g_hh[Mc * Ec];
__device__ __align__(256) __half g_fh[Mc * FFc];

// ---------------------------------------------------------------------------
// PTX helpers
// ---------------------------------------------------------------------------
__device__ __forceinline__ uint32_t smem_u32(const void* p) {
    uint32_t a;
    asm("{ .reg .u64 t; cvta.to.shared.u64 t, %1; cvt.u32.u64 %0, t; }" : "=r"(a) : "l"(p));
    return a;
}
__device__ __forceinline__ void cpasync16(uint32_t dst, const void* src) {
    asm volatile("cp.async.cg.shared.global [%0], [%1], 16;" :: "r"(dst), "l"(src));
}
#define CP_COMMIT()  asm volatile("cp.async.commit_group;" ::: "memory")
#define CP_WAIT(n)   asm volatile("cp.async.wait_group %0;" :: "n"(n) : "memory")

__device__ __forceinline__ void ldsm4(uint32_t* r, uint32_t addr) {
    asm volatile("ldmatrix.sync.aligned.m8n8.x4.shared.b16 {%0,%1,%2,%3}, [%4];"
                 : "=r"(r[0]), "=r"(r[1]), "=r"(r[2]), "=r"(r[3]) : "r"(addr));
}
__device__ __forceinline__ void mma_f16(float* c, const uint32_t* a, const uint32_t* b) {
    asm volatile(
        "mma.sync.aligned.m16n8k16.row.col.f32.f16.f16.f32 "
        "{%0,%1,%2,%3}, {%4,%5,%6,%7}, {%8,%9}, {%0,%1,%2,%3};"
        : "+f"(c[0]), "+f"(c[1]), "+f"(c[2]), "+f"(c[3])
        : "r"(a[0]), "r"(a[1]), "r"(a[2]), "r"(a[3]), "r"(b[0]), "r"(b[1]));
}
__device__ __forceinline__ uint32_t pack2(float v0, float v1) {
    __half2 ph = __halves2half2(__float2half_rn(v0), __float2half_rn(v1));
    return *(uint32_t*)&ph;
}

// ---------------------------------------------------------------------------
// HMMA GEMM (single-pass): C[M,N] = Ah[M,K] @ Bh[N,K]^T + bias
// 128x128 CTA tile, BK=32, 8 warps of 32x64.
// 3-stage cp.async pipeline, ONE __syncthreads per chunk.
// ---------------------------------------------------------------------------
constexpr int LDSp  = 40;
constexpr int TILEB = 128 * LDSp * 2;      // 10240
constexpr int BUFB1 = 2 * TILEB;           // A,B = 20480
constexpr int MMA_SMEM = 3 * BUFB1;        // 61440

template<int RELU, int EMITH>
__global__ void __launch_bounds__(256)
mma_gemm(const __half* __restrict__ Ah, const __half* __restrict__ Bh,
         const float* __restrict__ bias, float* __restrict__ C,
         __half* __restrict__ Ch, int K, int N)
{
    extern __shared__ char sm[];
    const uint32_t sbase = smem_u32(sm);
    const int tid = threadIdx.x;
    const int wid = tid >> 5, lane = tid & 31;
    const int wm = wid & 3, wn = wid >> 2;
    const int bm = blockIdx.y * 128, bn = blockIdx.x * 128;
    const int nk = K / 32;

    const int r0l = tid >> 2, sg = (tid & 3) << 3;

    auto load_chunk = [&](int kc) {
        if (kc < nk) {
            const uint32_t base = sbase + (kc % 3) * BUFB1;
            const int k0 = kc * 32;
            #pragma unroll
            for (int it = 0; it < 2; it++) {
                const int r = r0l + it * 64;
                const uint32_t dst = base + r * 80 + sg * 2;
                cpasync16(dst,         Ah + (size_t)(bm + r) * K + k0 + sg);
                cpasync16(dst + TILEB, Bh + (size_t)(bn + r) * K + k0 + sg);
            }
        }
        CP_COMMIT();
    };

    float acc[2][8][4];
    #pragma unroll
    for (int mt = 0; mt < 2; mt++)
        #pragma unroll
        for (int nt = 0; nt < 8; nt++)
            #pragma unroll
            for (int i = 0; i < 4; i++) acc[mt][nt][i] = 0.f;

    uint32_t aF[2][2][4];
    uint32_t bF[8][2][2];

    const int a_row = wm * 32 + (lane & 15);
    const int a_kof = (lane >> 4) << 3;
    const int b_n   = wn * 64 + (lane & 7) + ((lane & 16) >> 1);
    const int b_kof = ((lane >> 3) & 1) << 3;

    auto loadA = [&](uint32_t tbase) {
        #pragma unroll
        for (int mt = 0; mt < 2; mt++)
            #pragma unroll
            for (int ks = 0; ks < 2; ks++)
                ldsm4(aF[mt][ks], tbase + (a_row + mt * 16) * 80 + (ks * 16 + a_kof) * 2);
    };
    auto loadB = [&](uint32_t tbase) {
        #pragma unroll
        for (int ntp = 0; ntp < 4; ntp++)
            #pragma unroll
            for (int ks = 0; ks < 2; ks++) {
                uint32_t t4[4];
                ldsm4(t4, tbase + (b_n + ntp * 16) * 80 + (ks * 16 + b_kof) * 2);
                bF[ntp * 2 + 0][ks][0] = t4[0]; bF[ntp * 2 + 0][ks][1] = t4[1];
                bF[ntp * 2 + 1][ks][0] = t4[2]; bF[ntp * 2 + 1][ks][1] = t4[3];
            }
    };
    auto mma_all = [&]() {
        #pragma unroll
        for (int ks = 0; ks < 2; ks++)
            #pragma unroll
            for (int mt = 0; mt < 2; mt++)
                #pragma unroll
                for (int nt = 0; nt < 8; nt++)
                    mma_f16(acc[mt][nt], aF[mt][ks], bF[nt][ks]);
    };

    load_chunk(0);
    load_chunk(1);
    for (int kc = 0; kc < nk; kc++) {
        CP_WAIT(1);
        __syncthreads();
        load_chunk(kc + 2);

        const uint32_t base = sbase + (kc % 3) * BUFB1;
        loadA(base);
        loadB(base + TILEB);
        mma_all();
    }

    #pragma unroll
    for (int mt = 0; mt < 2; mt++) {
        #pragma unroll
        for (int nt = 0; nt < 8; nt++) {
            const int row = bm + wm * 32 + mt * 16 + (lane >> 2);
            const int col = bn + wn * 64 + nt * 8 + ((lane & 3) << 1);
            const float bi0 = bias[col], bi1 = bias[col + 1];
            float o00 = acc[mt][nt][0] + bi0, o01 = acc[mt][nt][1] + bi1;
            float o10 = acc[mt][nt][2] + bi0, o11 = acc[mt][nt][3] + bi1;
            if (RELU) {
                o00 = fmaxf(o00, 0.f); o01 = fmaxf(o01, 0.f);
                o10 = fmaxf(o10, 0.f); o11 = fmaxf(o11, 0.f);
            }
            const size_t i0 = (size_t)row * N + col;
            const size_t i1 = (size_t)(row + 8) * N + col;
            if (EMITH) {
                *(uint32_t*)(Ch + i0) = pack2(o00, o01);
                *(uint32_t*)(Ch + i1) = pack2(o10, o11);
            } else {
                *(float2*)(C + i0) = make_float2(o00, o01);
                *(float2*)(C + i1) = make_float2(o10, o11);
            }
        }
    }
}

// ---------------------------------------------------------------------------
// Fused scores GEMM (HMMA, single-pass): per (b,h):
//   AW[i, j]     = Q_h[i,:] . K_h[j,:]       (j < 512)
//   AW[i, 512+e] = Q_h[i,:] . pos_emb[e,:]   (e < 129; pad rows zero)
// ---------------------------------------------------------------------------
constexpr int QK_LDS = 72;
constexpr int QK_T   = 128 * QK_LDS * 2;     // 18432
constexpr int QK_SMEM = 2 * QK_T;            // 36864 B

__global__ void __launch_bounds__(256)
qk_scores(float* __restrict__ AW)
{
    extern __shared__ char sm[];
    const uint32_t sA = smem_u32(sm);
    const uint32_t sB = sA + QK_T;
    const int tid = threadIdx.x;
    const int wid = tid >> 5, lane = tid & 31;
    const int wm = wid & 3, wn = wid >> 2;
    const int bn = blockIdx.x * 128, bm = blockIdx.y * 128;
    const int bh = blockIdx.z, b = bh >> 4, h = bh & 15;

    {
        const int r0 = tid >> 3, sg = (tid & 7) << 3;
        #pragma unroll
        for (int it = 0; it < 4; it++) {
            const int r = r0 + it * 32;
            const uint32_t off = (r * QK_LDS + sg) * 2;
            cpasync16(sA + off, g_qkvh + (size_t)(b * Sc + bm + r) * E3 + h * HDc + sg);
            const int gr = bn + r;
            const __half* bph;
            if (gr < Sc) {
                bph = g_qkvh + (size_t)(b * Sc + gr) * E3 + Ec + h * HDc + sg;
            } else {
                bph = g_peh + (size_t)(gr - Sc) * HDc + sg;
            }
            cpasync16(sB + off, bph);
        }
        CP_COMMIT(); CP_WAIT(0);
        __syncthreads();
    }

    float acc[2][8][4];
    #pragma unroll
    for (int mt = 0; mt < 2; mt++)
        #pragma unroll
        for (int nt = 0; nt < 8; nt++)
            #pragma unroll
            for (int i = 0; i < 4; i++) acc[mt][nt][i] = 0.f;

    uint32_t aF[2][2][4], bF[8][2][2];
    const int a_row = wm * 32 + (lane & 15);
    const int a_kof = (lane >> 4) << 3;
    const int b_n   = wn * 64 + (lane & 7) + ((lane & 16) >> 1);
    const int b_kof = ((lane >> 3) & 1) << 3;

    auto loadA = [&](int k0) {
        #pragma unroll
        for (int mt = 0; mt < 2; mt++)
            #pragma unroll
            for (int ks = 0; ks < 2; ks++)
                ldsm4(aF[mt][ks], sA + ((a_row + mt * 16) * QK_LDS + k0 + ks * 16 + a_kof) * 2);
    };
    auto loadB = [&](int k0) {
        #pragma unroll
        for (int ntp = 0; ntp < 4; ntp++)
            #pragma unroll
            for (int ks = 0; ks < 2; ks++) {
                uint32_t t4[4];
                ldsm4(t4, sB + ((b_n + ntp * 16) * QK_LDS + k0 + ks * 16 + b_kof) * 2);
                bF[ntp * 2 + 0][ks][0] = t4[0]; bF[ntp * 2 + 0][ks][1] = t4[1];
                bF[ntp * 2 + 1][ks][0] = t4[2]; bF[ntp * 2 + 1][ks][1] = t4[3];
            }
    };
    auto mma_all = [&]() {
        #pragma unroll
        for (int ks = 0; ks < 2; ks++)
            #pragma unroll
            for (int mt = 0; mt < 2; mt++)
                #pragma unroll
                for (int nt = 0; nt < 8; nt++)
                    mma_f16(acc[mt][nt], aF[mt][ks], bF[nt][ks]);
    };

    #pragma unroll
    for (int kg = 0; kg < 2; kg++) {
        const int k0 = kg * 32;
        loadA(k0);
        loadB(k0);
        mma_all();
    }

    #pragma unroll
    for (int mt = 0; mt < 2; mt++) {
        #pragma unroll
        for (int nt = 0; nt < 8; nt++) {
            const int row = bm + wm * 32 + mt * 16 + (lane >> 2);
            const int col = bn + wn * 64 + nt * 8 + ((lane & 3) << 1);
            if (col < SE) {
                const size_t base = (size_t)(bh * Sc + row) * SE + col;
                *(float2*)(AW + base)             = make_float2(acc[mt][nt][0], acc[mt][nt][1]);
                *(float2*)(AW + base + 8ull * SE) = make_float2(acc[mt][nt][2], acc[mt][nt][3]);
            }
        }
    }
}

// ---------------------------------------------------------------------------
// Per-head V^T build (hi only)
// ---------------------------------------------------------------------------
__global__ void vt_build()
{
    __shared__ __half th[32][33];
    const int jt = blockIdx.x, dt = blockIdx.y, bh = blockIdx.z;
    const int b = bh >> 4, h = bh & 15;
    const int j0 = jt * 32, d0 = dt * 32;
    const int tx = threadIdx.x, ty = threadIdx.y;

    #pragma unroll
    for (int k = 0; k < 4; k++) {
        const int j = j0 + ty + k * 8;
        const int d = d0 + tx;
        __half vh;
        if (j < Sc) {
            vh = g_qkvh[(size_t)(b * Sc + j) * E3 + 2 * Ec + h * HDc + d];
        } else if (j < Sc + NEc) {
            vh = g_peh[(size_t)(j - Sc) * HDc + d];
        } else {
            vh = __float2half_rn(0.f);
        }
        th[ty + k * 8][tx] = vh;
    }
    __syncthreads();
    #pragma unroll
    for (int k = 0; k < 4; k++) {
        const int d = d0 + ty + k * 8;
        const int j = j0 + tx;
        g_vth[(size_t)bh * HDc * SE + (size_t)d * SE + j] = th[tx][ty + k * 8];
    }
}

// ---------------------------------------------------------------------------
// AV GEMM (HMMA, single-pass): A = aw hi, B = vt hi. 3-stage pipeline.
// ---------------------------------------------------------------------------
constexpr int AV_AT = 128 * LDSp * 2;          // 10240
constexpr int AV_BT = 64 * LDSp * 2;           // 5120
constexpr int AV_ST = AV_AT + AV_BT;           // 15360
constexpr int AV_SMEM = 3 * AV_ST;             // 46080

__global__ void __launch_bounds__(256)
av_mma()
{
    extern __shared__ char sm[];
    const uint32_t sbase = smem_u32(sm);
    const int tid = threadIdx.x;
    const int wid = tid >> 5, lane = tid & 31;
    const int bm = blockIdx.x * 128;
    const int bh = blockIdx.y, b = bh >> 4, h = bh & 15;
    const int nk = SE / 32;   // 21

    auto load_chunk = [&](int kc) {
        if (kc < nk) {
            const uint32_t base = sbase + (kc % 3) * AV_ST;
            const int k0 = kc * 32;
            const int sg = (tid & 3) << 3;
            #pragma unroll
            for (int it = 0; it < 2; it++) {
                const int r = (tid >> 2) + it * 64;
                cpasync16(base + r * 80 + sg * 2,
                          g_awh + (size_t)(bh * Sc + bm + r) * SE + k0 + sg);
            }
            {
                const int r = tid >> 2;
                if (r < 64) {
                    cpasync16(base + AV_AT + r * 80 + sg * 2,
                              g_vth + (size_t)bh * HDc * SE + (size_t)r * SE + k0 + sg);
                }
            }
        }
        CP_COMMIT();
    };

    float acc[8][4];
    #pragma unroll
    for (int nt = 0; nt < 8; nt++)
        #pragma unroll
        for (int i = 0; i < 4; i++) acc[nt][i] = 0.f;

    uint32_t aF[2][4], bF[8][2][2];
    const int a_row = wid * 16 + (lane & 15);
    const int a_kof = (lane >> 4) << 3;
    const int b_n   = (lane & 7) + ((lane & 16) >> 1);
    const int b_kof = ((lane >> 3) & 1) << 3;

    auto loadA = [&](uint32_t tb) {
        #pragma unroll
        for (int ks = 0; ks < 2; ks++)
            ldsm4(aF[ks], tb + (a_row * 80) + (ks * 16 + a_kof) * 2);
    };
    auto loadB = [&](uint32_t tb) {
        #pragma unroll
        for (int ntp = 0; ntp < 4; ntp++)
            #pragma unroll
            for (int ks = 0; ks < 2; ks++) {
                uint32_t t4[4];
                ldsm4(t4, tb + (b_n + ntp * 16) * 80 + (ks * 16 + b_kof) * 2);
                bF[ntp * 2 + 0][ks][0] = t4[0]; bF[ntp * 2 + 0][ks][1] = t4[1];
                bF[ntp * 2 + 1][ks][0] = t4[2]; bF[ntp * 2 + 1][ks][1] = t4[3];
            }
    };
    auto mma_all = [&]() {
        #pragma unroll
        for (int ks = 0; ks < 2; ks++)
            #pragma unroll
            for (int nt = 0; nt < 8; nt++)
                mma_f16(acc[nt], aF[ks], bF[nt][ks]);
    };

    load_chunk(0);
    load_chunk(1);
    for (int kc = 0; kc < nk; kc++) {
        CP_WAIT(1);
        __syncthreads();
        load_chunk(kc + 2);
        const uint32_t base = sbase + (kc % 3) * AV_ST;
        loadA(base);
        loadB(base + AV_AT);
        mma_all();
    }

    #pragma unroll
    for (int nt = 0; nt < 8; nt++) {
        const int row = bm + wid * 16 + (lane >> 2);
        const int col = nt * 8 + ((lane & 3) << 1);
        const size_t i0 = (size_t)(b * Sc + row) * Ec + h * HDc + col;
        const size_t i1 = (size_t)(b * Sc + row + 8) * Ec + h * HDc + col;
        *(uint32_t*)(g_ah + i0) = pack2(acc[nt][0], acc[nt][1]);
        *(uint32_t*)(g_ah + i1) = pack2(acc[nt][2], acc[nt][3]);
    }
}

// ---------------------------------------------------------------------------
// Elementwise prep kernels
// ---------------------------------------------------------------------------
__global__ void __launch_bounds__(256) round_act(
    const float* __restrict__ A, __half* __restrict__ hi, int n2)
{
    const int i = blockIdx.x * 256 + threadIdx.x;
    if (i >= n2) return;
    const float2 v = ((const float2*)A)[i];
    ((uint32_t*)hi)[i] = pack2(v.x, v.y);
}

__device__ __forceinline__ void tr_tile(
    const float* __restrict__ W, int N, __half* __restrict__ dst,
    int rowOff, int ldo, int idx, int xTiles, int tx, int ty)
{
    __shared__ float t[32][33];
    const int n0 = (idx % xTiles) * 32;
    const int k0 = (idx / xTiles) * 32;
    #pragma unroll
    for (int j = 0; j < 32; j += 8)
        t[ty + j][tx] = W[(size_t)(k0 + ty + j) * N + n0 + tx];
    __syncthreads();
    #pragma unroll
    for (int j = 0; j < 32; j += 8)
        dst[(size_t)(rowOff + n0 + ty + j) * ldo + k0 + tx] = __float2half_rn(t[tx][ty + j]);
}

__global__ void __launch_bounds__(256) prep_weights(
    const float* __restrict__ wq, const float* __restrict__ wk,
    const float* __restrict__ wv, const float* __restrict__ wo,
    const float* __restrict__ ff1, const float* __restrict__ ff2,
    const float* __restrict__ pos_emb)
{
    const int bidx = blockIdx.x;
    const int tid = threadIdx.x;
    const int tx = tid & 31, ty = tid >> 5;
    if (bidx < 1024)       tr_tile(wq,  Ec,  g_W3h, 0,      Ec,  bidx,         32,  tx, ty);
    else if (bidx < 2048)  tr_tile(wk,  Ec,  g_W3h, Ec,     Ec,  bidx - 1024,  32,  tx, ty);
    else if (bidx < 3072)  tr_tile(wv,  Ec,  g_W3h, 2 * Ec, Ec,  bidx - 2048,  32,  tx, ty);
    else if (bidx < 4096)  tr_tile(wo,  Ec,  g_Woh, 0,      Ec,  bidx - 3072,  32,  tx, ty);
    else if (bidx < 8192)  tr_tile(ff1, FFc, g_W1h, 0,      Ec,  bidx - 4096,  128, tx, ty);
    else if (bidx < 12288) tr_tile(ff2, Ec,  g_W2h, 0,      FFc, bidx - 8192,  32,  tx, ty);
    else {
        const int i = (bidx - 12288) * 256 + tid;
        if (i < 256 * HDc) {
            const int e = i >> 6;
            g_peh[i] = __float2half_rn((e < NEc) ? pos_emb[i] : 0.f);
        }
    }
}

__global__ void concat_bias(const float* a, const float* b, const float* c) {
    const int i = blockIdx.x * 256 + threadIdx.x;
    if (i < Ec) g_b3[i] = a[i];
    else if (i < 2 * Ec) g_b3[i] = b[i - Ec];
    else if (i < 3 * Ec) g_b3[i] = c[i - 2 * Ec];
}

// ---------------------------------------------------------------------------
// Softmax, warp-per-row: 8 rows per 256-thread block; scores in registers;
// shuffle reductions only; per-row private bucket; emits fp16 aw_ext (hi).
// grid (Sc/8, Hc, Bc)
// ---------------------------------------------------------------------------
__global__ void __launch_bounds__(256) softmax_kernel(
    const float* __restrict__ dist, const int* __restrict__ dt)
{
    __shared__ int dts[Sc];
    __shared__ float bucket[8][NEc + 1];

    const int rg = blockIdx.x, h = blockIdx.y, b = blockIdx.z;
    const int tid = threadIdx.x;
    const int w = tid >> 5, lane = tid & 31;
    const int i = rg * 8 + w;
    const int bh = b * Hc + h;
    const size_t rowbase = (size_t)(bh * Sc + i) * SE;
    const float* drow = dist + ((size_t)b * Sc + i) * Sc;
    float* buck = bucket[w];

    for (int t = tid; t < Sc; t += 256) dts[t] = dt[b * Sc + t];
    for (int t = lane; t < NEc; t += 32) buck[t] = 0.f;
    __syncthreads();

    const int dti = dts[i];

    float s[16];
    int e[16];
    float lmax = -1e30f;
    #pragma unroll
    for (int t = 0; t < 16; t++) {
        const int j = lane + t * 32;
        int rel = dts[j] - dti;
        rel = rel < -64 ? -64 : (rel > 64 ? 64 : rel);
        e[t] = rel + 64;
        const float v = (g_aw[rowbase + j] + g_aw[rowbase + Sc + e[t]]) * 0.125f
                        + 0.6f * drow[j];
        s[t] = v;
        lmax = fmaxf(lmax, v);
    }
    #pragma unroll
    for (int o = 16; o; o >>= 1) lmax = fmaxf(lmax, __shfl_xor_sync(0xffffffffu, lmax, o));

    float lsum = 0.f;
    #pragma unroll
    for (int t = 0; t < 16; t++) {
        s[t] = __expf(s[t] - lmax);
        lsum += s[t];
    }
    #pragma unroll
    for (int o = 16; o; o >>= 1) lsum += __shfl_xor_sync(0xffffffffu, lsum, o);
    const float inv = 1.f / lsum;

    #pragma unroll
    for (int t = 0; t < 16; t++) {
        const float a = s[t] * inv;
        g_awh[rowbase + lane + t * 32] = __float2half_rn(a);
        atomicAdd(&buck[e[t]], a);
    }
    __syncwarp();
    for (int t = lane; t < SE - Sc; t += 32) {
        g_awh[rowbase + Sc + t] = __float2half_rn((t < NEc) ? buck[t] : 0.f);
    }
}

// ---------------------------------------------------------------------------
// out = LayerNorm(X + R); optional fp16 (hi-only) emission.
// ---------------------------------------------------------------------------
template<int EMIT>
__global__ void __launch_bounds__(256) add_ln_kernel(
    const float* __restrict__ X, const float* __restrict__ Rr,
    const float* __restrict__ gam, const float* __restrict__ bet,
    float* __restrict__ Out, __half* __restrict__ Oh)
{
    __shared__ float sh[Ec];
    __shared__ float red[8];
    const int row = blockIdx.x;
    const int tid = threadIdx.x;
    const float* xr = X + (size_t)row * Ec;
    const float* rr = Rr + (size_t)row * Ec;

    float lsum = 0.f;
    for (int t = tid; t < Ec; t += 256) {
        const float v = xr[t] + rr[t];
        sh[t] = v;
        lsum += v;
    }
    #pragma unroll
    for (int o = 16; o; o >>= 1) lsum += __shfl_xor_sync(0xffffffffu, lsum, o);
    if ((tid & 31) == 0) red[tid >> 5] = lsum;
    __syncthreads();
    float tot = 0.f;
    #pragma unroll
    for (int w = 0; w < 8; w++) tot += red[w];
    const float mu = tot * (1.f / Ec);
    __syncthreads();

    float lvar = 0.f;
    for (int t = tid; t < Ec; t += 256) {
        const float d = sh[t] - mu;
        lvar += d * d;
    }
    #pragma unroll
    for (int o = 16; o; o >>= 1) lvar += __shfl_xor_sync(0xffffffffu, lvar, o);
    if ((tid & 31) == 0) red[tid >> 5] = lvar;
    __syncthreads();
    float vtot = 0.f;
    #pragma unroll
    for (int w = 0; w < 8; w++) vtot += red[w];
    const float inv = rsqrtf(vtot * (1.f / Ec) + 1e-5f);

    float* orow = Out + (size_t)row * Ec;
    for (int t = tid; t < Ec; t += 256) {
        const float v = (sh[t] - mu) * inv * gam[t] + bet[t];
        orow[t] = v;
        if (EMIT) Oh[(size_t)row * Ec + t] = __float2half_rn(v);
    }
}

// ---------------------------------------------------------------------------
extern "C" void kernel_launch(void* const* d_in, const int* in_sizes, int n_in,
                              void* d_out, int out_size)
{
    (void)in_sizes; (void)n_in; (void)out_size;
    const float* x       = (const float*)d_in[0];
    const float* dist    = (const float*)d_in[1];
    const int*   dt      = (const int*)d_in[2];
    const float* pos_emb = (const float*)d_in[3];
    const float* wq_w = (const float*)d_in[4];
    const float* wq_b = (const float*)d_in[5];
    const float* wk_w = (const float*)d_in[6];
    const float* wk_b = (const float*)d_in[7];
    const float* wv_w = (const float*)d_in[8];
    const float* wv_b = (const float*)d_in[9];
    const float* wo_w = (const float*)d_in[10];
    const float* wo_b = (const float*)d_in[11];
    const float* ff1_w = (const float*)d_in[12];
    const float* ff1_b = (const float*)d_in[13];
    const float* ff2_w = (const float*)d_in[14];
    const float* ff2_b = (const float*)d_in[15];
    const float* ln1_g = (const float*)d_in[16];
    const float* ln1_b = (const float*)d_in[17];
    const float* ln2_g = (const float*)d_in[18];
    const float* ln2_b = (const float*)d_in[19];
    float* out = (float*)d_out;

    __half *xh, *W3h, *Woh, *W1h, *W2h;
    __half *qkvh, *ah, *hh, *fh;
    float *b3, *AW, *T0, *Hs;
    cudaGetSymbolAddress((void**)&xh, g_xh);
    cudaGetSymbolAddress((void**)&W3h, g_W3h);
    cudaGetSymbolAddress((void**)&Woh, g_Woh);
    cudaGetSymbolAddress((void**)&W1h, g_W1h);
    cudaGetSymbolAddress((void**)&W2h, g_W2h);
    cudaGetSymbolAddress((void**)&qkvh, g_qkvh);
    cudaGetSymbolAddress((void**)&ah, g_ah);
    cudaGetSymbolAddress((void**)&hh, g_hh);
    cudaGetSymbolAddress((void**)&fh, g_fh);
    cudaGetSymbolAddress((void**)&b3, g_b3);
    cudaGetSymbolAddress((void**)&AW, g_aw);
    cudaGetSymbolAddress((void**)&T0, g_t0);
    cudaGetSymbolAddress((void**)&Hs, g_h);

    cudaFuncSetAttribute(mma_gemm<0, 1>, cudaFuncAttributeMaxDynamicSharedMemorySize, MMA_SMEM);
    cudaFuncSetAttribute(mma_gemm<0, 0>, cudaFuncAttributeMaxDynamicSharedMemorySize, MMA_SMEM);
    cudaFuncSetAttribute(mma_gemm<1, 1>, cudaFuncAttributeMaxDynamicSharedMemorySize, MMA_SMEM);
    cudaFuncSetAttribute(qk_scores, cudaFuncAttributeMaxDynamicSharedMemorySize, QK_SMEM);
    cudaFuncSetAttribute(av_mma, cudaFuncAttributeMaxDynamicSharedMemorySize, AV_SMEM);

    dim3 blk(256);
    dim3 tblk(32, 8);

    // prep
    round_act<<<(Mc * Ec / 2 + 255) / 256, blk>>>(x, xh, Mc * Ec / 2);
    prep_weights<<<12288 + 64, blk>>>(wq_w, wk_w, wv_w, wo_w, ff1_w, ff2_w, pos_emb);
    concat_bias<<<12, blk>>>(wq_b, wk_b, wv_b);

    // fused QKV projection (single-pass) -> fp16
    mma_gemm<0, 1><<<dim3(E3 / 128, Mc / 128), blk, MMA_SMEM>>>(
        xh, W3h, b3, nullptr, qkvh, Ec, E3);

    // per-head V^T (+pe^T) staging
    vt_build<<<dim3(SE / 32, 2, 128), tblk>>>();

    // fused scores (single-pass)
    qk_scores<<<dim3(6, 4, 128), blk, QK_SMEM>>>(AW);

    // softmax, warp-per-row
    softmax_kernel<<<dim3(Sc / 8, Hc, Bc), blk>>>(dist, dt);

    // attn = aw_ext @ vt^T (single-pass)
    av_mma<<<dim3(4, 128), blk, AV_SMEM>>>();

    // output projection (single-pass)
    mma_gemm<0, 0><<<dim3(Ec / 128, Mc / 128), blk, MMA_SMEM>>>(
        ah, Woh, wo_b, T0, nullptr, Ec, Ec);

    // h = LN(x + attn_out), emit fp16 for FF1
    add_ln_kernel<1><<<Mc, blk>>>(x, T0, ln1_g, ln1_b, Hs, hh);

    // FFN (single-pass both)
    mma_gemm<1, 1><<<dim3(FFc / 128, Mc / 128), blk, MMA_SMEM>>>(
        hh, W1h, ff1_b, nullptr, fh, Ec, FFc);
    mma_gemm<0, 0><<<dim3(Ec / 128, Mc / 128), blk, MMA_SMEM>>>(
        fh, W2h, ff2_b, T0, nullptr, FFc, Ec);

    // out = LN(h + ffn)
    add_ln_kernel<0><<<Mc, blk>>>(Hs, T0, ln2_g, ln2_b, out, nullptr);
}